// round 11
// baseline (speedup 1.0000x reference)
#include <cuda_runtime.h>
#include <cuda_fp16.h>

// ---------------- problem constants ----------------
#define Bb   2
#define Ss   2048
#define DMm  256
#define DIi  512
#define NN   16
#define RR   32
#define MM   (Bb*Ss)          // 4096 rows per chain
#define M2   (2*MM)           // 8192 rows: [fwd | reversed]
#define CHUNK 32
#define NCH  (Ss/CHUNK)       // 64 chunks per sequence
#define NSEQ 4                // 4 sequences total (2 fwd + 2 rev)
#define KS   4                // split-K for x-proj

// ---------------- device scratch ----------------
__device__ float  g_res [M2*DMm];
__device__ __half g_xs  [M2*DIi];
__device__ __half g_z   [M2*DIi];
__device__ __half g_xc  [M2*DIi];
__device__ float  g_proj[M2*64];          // [xd(32) | B(16) | C(16)] fp32
__device__ __half g_projh[M2*64];         // half mirror for gemm_dt A-path
__device__ float  g_projp[KS*M2*64];      // split-K partials (fp32)
__device__ __half g_delta[M2*DIi];
__device__ __half g_yg  [M2*DIi];
__device__ float  g_P   [NSEQ*NCH*DIi*NN];
__device__ float  g_Q   [NSEQ*NCH*DIi*NN];
__device__ float  g_Hin [NSEQ*NCH*DIi*NN];

// transposed fp16 weight mirrors  W^T[n][k]
__device__ __half g_winT[4*1024*256];     // in_w:   [blk][n=1024][k=256]
__device__ __half g_xwT [4*64*512];       // xd|xB|xC: [blk][n=64][k=512]
__device__ __half g_dtwT[4*512*32];       // dtp_w:  [blk][n=512][k=32]
__device__ __half g_owT [4*256*512];      // out_w:  [blk][n=256][k=512]
__device__ __half g_mwT [256*512];        // merge_w:[n=256][k=512]

__device__ __forceinline__ float siluf(float x){ return x / (1.f + __expf(-x)); }
__device__ __forceinline__ float spf(float a){ return (a > 20.f) ? a : log1pf(__expf(a)); }

__device__ __forceinline__ unsigned h2pack(float a, float b){
  __half2 h = __floats2half2_rn(a, b);
  return *reinterpret_cast<unsigned*>(&h);
}
__device__ __forceinline__ float4 h4load(const __half* p){
  uint2 u = *(const uint2*)p;
  float2 fa = __half22float2(*(__half2*)&u.x);
  float2 fb = __half22float2(*(__half2*)&u.y);
  return make_float4(fa.x, fa.y, fb.x, fb.y);
}
__device__ __forceinline__ void h4store(__half* p, float4 v){
  uint2 u; u.x = h2pack(v.x, v.y); u.y = h2pack(v.z, v.w);
  *(uint2*)p = u;
}

#define MMA16(c, a, b)                                                       \
  asm volatile("mma.sync.aligned.m16n8k16.row.col.f32.f16.f16.f32 "          \
               "{%0,%1,%2,%3},{%4,%5,%6,%7},{%8,%9},{%0,%1,%2,%3};"          \
               : "+f"((c)[0]), "+f"((c)[1]), "+f"((c)[2]), "+f"((c)[3])      \
               : "r"((a)[0]), "r"((a)[1]), "r"((a)[2]), "r"((a)[3]),         \
                 "r"((b)[0]), "r"((b)[1]))

// ---------------- weight prep: fp32 -> transposed fp16, once per launch ----
__global__ void k_wprep(const float* __restrict__ in_w,
                        const float* __restrict__ xd_w,
                        const float* __restrict__ xB_w,
                        const float* __restrict__ xC_w,
                        const float* __restrict__ dtp_w,
                        const float* __restrict__ out_w,
                        const float* __restrict__ merge_w){
  int i = blockIdx.x*256 + threadIdx.x;       // 1900544 total
  if (i < 1048576){                           // in_w: [blk][k=256][n=1024]
    int blk = i >> 18, r = i & 262143;
    int n = r >> 8, k = r & 255;
    g_winT[i] = __float2half(in_w[(size_t)blk*262144 + k*1024 + n]);
  } else if (i < 1179648){                    // xd|xB|xC
    int j = i - 1048576;
    int blk = j >> 15, r = j & 32767;
    int n = r >> 9, k = r & 511;
    float v;
    if      (n < 32) v = xd_w[(size_t)blk*512*32 + k*32 + n];
    else if (n < 48) v = xB_w[(size_t)blk*512*16 + k*16 + (n-32)];
    else             v = xC_w[(size_t)blk*512*16 + k*16 + (n-48)];
    g_xwT[j] = __float2half(v);
  } else if (i < 1245184){                    // dtp_w: [blk][k=32][n=512]
    int j = i - 1179648;
    int blk = j >> 14, r = j & 16383;
    int n = r >> 5, k = r & 31;
    g_dtwT[j] = __float2half(dtp_w[(size_t)blk*32*512 + k*512 + n]);
  } else if (i < 1769472){                    // out_w: [blk][k=512][n=256]
    int j = i - 1245184;
    int blk = j >> 17, r = j & 131071;
    int n = r >> 9, k = r & 511;
    g_owT[j] = __float2half(out_w[(size_t)blk*512*256 + k*256 + n]);
  } else {                                    // merge_w: [k=512][n=256]
    int j = i - 1769472;
    int n = j >> 9, k = j & 511;
    g_mwT[j] = __float2half(merge_w[k*256 + n]);
  }
}

// ---------------- init: fwd + reversed copies ----------------
__global__ void k_init(const float* __restrict__ x){
  int idx = blockIdx.x*256 + threadIdx.x;       // M2*64 float4s
  int col = idx & 63;
  int m   = idx >> 6;                           // 0..8191
  int half = m >> 12;
  int b = (m >> 11) & 1, s = m & (Ss-1);
  int ms = b*Ss + (half ? (Ss-1-s) : s);
  reinterpret_cast<float4*>(g_res)[m*64+col] =
      reinterpret_cast<const float4*>(x)[ms*64+col];
}

// ======================================================================
// FP16 tensor-core GEMM core, double-buffered, mma.m16n8k16.
// Block tile 128(M) x 64(N), 256 threads = 8 warps (4 M x 2 N),
// warp tile 32x32. K-chunk = 16.  (round-7 proven core)
// B operands now come from pre-transposed fp16 weights: one LDG.64
// yields packed half2 pairs that go straight into fragment smem.
// ======================================================================
#define TC_DECL()                                                     \
  __shared__ __align__(16) unsigned Af[2][1024];                      \
  __shared__ __align__(16) unsigned Bf[2][512];                       \
  const int t = threadIdx.x;                                          \
  const int lane = t & 31, wid = t >> 5;                              \
  const int wm = wid >> 1, wn = wid & 1;                              \
  const int s_r  = t >> 1;          /* A staging row 0..127  */       \
  const int s_kb = (t & 1) * 8;     /* A staging k base 0/8  */       \
  const int s_bq = t >> 6;          /* B staging k-quad 0..3 */       \
  const int s_bn = t & 63;          /* B staging n 0..63     */       \
  float acc[2][4][4] = {};                                            \
  float4 raA0, raA1; uint4 raH; uint2 rbH;                            \
  (void)raA0; (void)raA1; (void)raH;

#define TC_AB(buf) &Af[buf][(((s_r>>4)*32 + ((s_r&7)*4))*4) + ((s_r>>3)&1) + ((s_kb>>2)&2)]

#define TC_STAGE_B(buf) {                                             \
  int ln0 = (s_bn & 7)*4 + ((2*s_bq) & 3);                            \
  int rgB = s_bq >> 1;                                                \
  unsigned* bb = &Bf[buf][((s_bn >> 3)*32 + ln0)*2 + rgB];            \
  bb[0] = rbH.x;                                                      \
  bb[2] = rbH.y; }

#define TC_STAGE_F(buf) {                                             \
  unsigned* ab = TC_AB(buf);                                          \
  ab[0]  = h2pack(raA0.x, raA0.y);                                    \
  ab[4]  = h2pack(raA0.z, raA0.w);                                    \
  ab[8]  = h2pack(raA1.x, raA1.y);                                    \
  ab[12] = h2pack(raA1.z, raA1.w);                                    \
  TC_STAGE_B(buf) }

#define TC_STAGE_H(buf) {                                             \
  unsigned* ab = TC_AB(buf);                                          \
  ab[0]  = raH.x;                                                     \
  ab[4]  = raH.y;                                                     \
  ab[8]  = raH.z;                                                     \
  ab[12] = raH.w;                                                     \
  TC_STAGE_B(buf) }

#define TC_COMP(buf) {                                                \
  unsigned a_[2][4]; unsigned b_[4][2];                               \
  _Pragma("unroll") for (int mt=0;mt<2;mt++)                          \
    *(uint4*)a_[mt] = *(const uint4*)&Af[buf][((wm*2+mt)*32 + lane)*4]; \
  _Pragma("unroll") for (int nt=0;nt<4;nt++)                          \
    *(uint2*)b_[nt] = *(const uint2*)&Bf[buf][((wn*4+nt)*32 + lane)*2]; \
  _Pragma("unroll") for (int mt=0;mt<2;mt++)                          \
    _Pragma("unroll") for (int nt=0;nt<4;nt++)                        \
      MMA16(acc[mt][nt], a_[mt], b_[nt]); }

#define TC_BODY_GEN(KT, STG)                                          \
  LOADA(0); LOADB(0);                                                 \
  STG(0);                                                             \
  if (16 < (KT)) { LOADA(16); LOADB(16); }                            \
  __syncthreads();                                                    \
  { int cur = 0;                                                      \
    _Pragma("unroll 1")                                               \
    for (int k0=0; k0<(KT); k0+=16){                                  \
      if (k0+16 < (KT)) STG(cur^1);                                   \
      if (k0+32 < (KT)) { LOADA(k0+32); LOADB(k0+32); }               \
      TC_COMP(cur);                                                   \
      __syncthreads();                                                \
      cur ^= 1;                                                       \
    } }

#define TC_BODY(KT)   TC_BODY_GEN(KT, TC_STAGE_F)
#define TC_BODY_H(KT) TC_BODY_GEN(KT, TC_STAGE_H)

// in_proj with fused LayerNorm:
//   LN(g_res)[8192,256] @ in_w[256,1024] -> xs | z (half)   per-half weights
__global__ void k_gemm_in(int b0, int b1,
                          const float* __restrict__ g0, const float* __restrict__ bt0,
                          const float* __restrict__ g1, const float* __restrict__ bt1){
  int col0 = blockIdx.x*64, row0 = blockIdx.y*128;
  int half = row0 >> 12;
  const __half* WT = g_winT + (size_t)(half ? b1 : b0)*262144;
  const float* gm = half ? g1  : g0;
  const float* bb = half ? bt1 : bt0;
  __shared__ float sG[DMm], sBt[DMm];
  TC_DECL();
  sG[t] = gm[t]; sBt[t] = bb[t];
  const float* rowp = g_res + (size_t)(row0 + s_r)*DMm;
  float sum = 0.f, sq = 0.f;
  #pragma unroll
  for (int j=0;j<16;j++){
    float4 v0 = *(const float4*)&rowp[j*16 + s_kb];
    float4 v1 = *(const float4*)&rowp[j*16 + s_kb + 4];
    sum += v0.x+v0.y+v0.z+v0.w + v1.x+v1.y+v1.z+v1.w;
    sq  += v0.x*v0.x+v0.y*v0.y+v0.z*v0.z+v0.w*v0.w
         + v1.x*v1.x+v1.y*v1.y+v1.z*v1.z+v1.w*v1.w;
  }
  sum += __shfl_xor_sync(~0u, sum, 1);
  sq  += __shfl_xor_sync(~0u, sq, 1);
  float mean = sum*(1.f/DMm);
  float rstd = rsqrtf(sq*(1.f/DMm) - mean*mean + 1e-5f);
  __syncthreads();   // sG/sBt visible
#define LOADA(k0_) { int kk_=(k0_)+s_kb;                                           \
    raA0 = *(const float4*)&rowp[kk_];                                             \
    raA1 = *(const float4*)&rowp[kk_+4];                                           \
    raA0.x=(raA0.x-mean)*rstd*sG[kk_+0]+sBt[kk_+0];                                \
    raA0.y=(raA0.y-mean)*rstd*sG[kk_+1]+sBt[kk_+1];                                \
    raA0.z=(raA0.z-mean)*rstd*sG[kk_+2]+sBt[kk_+2];                                \
    raA0.w=(raA0.w-mean)*rstd*sG[kk_+3]+sBt[kk_+3];                                \
    raA1.x=(raA1.x-mean)*rstd*sG[kk_+4]+sBt[kk_+4];                                \
    raA1.y=(raA1.y-mean)*rstd*sG[kk_+5]+sBt[kk_+5];                                \
    raA1.z=(raA1.z-mean)*rstd*sG[kk_+6]+sBt[kk_+6];                                \
    raA1.w=(raA1.w-mean)*rstd*sG[kk_+7]+sBt[kk_+7]; }
#define LOADB(k0_) { rbH = *(const uint2*)&WT[(size_t)(col0+s_bn)*DMm + (k0_) + s_bq*4]; }
  TC_BODY(DMm);
#undef LOADA
#undef LOADB
  __half* dst = (col0 < DIi) ? g_xs : g_z;
  int cb = (col0 < DIi) ? col0 : col0 - DIi;
  #pragma unroll
  for (int mt=0;mt<2;mt++)
    #pragma unroll
    for (int nt=0;nt<4;nt++){
      int r = row0 + wm*32 + mt*16 + (lane>>2);
      int c = cb + wn*32 + nt*8 + (lane&3)*2;
      *(unsigned*)&dst[(size_t)r*DIi + c]     = h2pack(acc[mt][nt][0], acc[mt][nt][1]);
      *(unsigned*)&dst[(size_t)(r+8)*DIi + c] = h2pack(acc[mt][nt][2], acc[mt][nt][3]);
    }
}

// x-proj split-K: xc[8192,512](half) @ [xd(32)|xB(16)|xC(16)] -> projp[kz] (fp32)
__global__ void k_gemm_x(int b0, int b1){
  int kz = blockIdx.x, row0 = blockIdx.y*128;
  int half = row0 >> 12;
  int kbase = kz*(DIi/KS);
  const __half* WT = g_xwT + (size_t)(half ? b1 : b0)*32768;
  TC_DECL();
#define LOADA(k0_) { raH = *(const uint4*)&g_xc[(size_t)(row0+s_r)*DIi + kbase+(k0_)+s_kb]; }
#define LOADB(k0_) { rbH = *(const uint2*)&WT[(size_t)s_bn*DIi + kbase + (k0_) + s_bq*4]; }
  TC_BODY_H(DIi/KS);
#undef LOADA
#undef LOADB
  float* dst = g_projp + (size_t)kz*M2*64;
  #pragma unroll
  for (int mt=0;mt<2;mt++)
    #pragma unroll
    for (int nt=0;nt<4;nt++){
      int r = row0 + wm*32 + mt*16 + (lane>>2);
      int c = wn*32 + nt*8 + (lane&3)*2;
      *(float2*)&dst[(size_t)r*64 + c]     = make_float2(acc[mt][nt][0], acc[mt][nt][1]);
      *(float2*)&dst[(size_t)(r+8)*64 + c] = make_float2(acc[mt][nt][2], acc[mt][nt][3]);
    }
}

__global__ void k_xred(){
  int i = blockIdx.x*256 + threadIdx.x;   // M2*16 float4s
  float4 a = reinterpret_cast<const float4*>(g_projp)[i];
  float4 b = reinterpret_cast<const float4*>(g_projp + (size_t)M2*64)[i];
  float4 c = reinterpret_cast<const float4*>(g_projp + (size_t)2*M2*64)[i];
  float4 d = reinterpret_cast<const float4*>(g_projp + (size_t)3*M2*64)[i];
  float4 s = make_float4(a.x+b.x+c.x+d.x, a.y+b.y+c.y+d.y,
                         a.z+b.z+c.z+d.z, a.w+b.w+c.w+d.w);
  reinterpret_cast<float4*>(g_proj)[i] = s;
  h4store(&g_projh[i*4], s);
}

// delta: softplus(projh[:, :32] @ dtp_w[32,512] + dtp_b) -> g_delta (half)
__global__ void k_gemm_dt(int b0, int b1,
                          const float* __restrict__ bd0, const float* __restrict__ bd1){
  int col0 = blockIdx.x*64, row0 = blockIdx.y*128;
  int half = row0 >> 12;
  const __half* WT = g_dtwT + (size_t)(half ? b1 : b0)*16384;
  const float* bd = half ? bd1 : bd0;
  TC_DECL();
#define LOADA(k0_) { raH = *(const uint4*)&g_projh[(size_t)(row0+s_r)*64 + (k0_)+s_kb]; }
#define LOADB(k0_) { rbH = *(const uint2*)&WT[(size_t)(col0+s_bn)*RR + (k0_) + s_bq*4]; }
  TC_BODY_H(RR);
#undef LOADA
#undef LOADB
  #pragma unroll
  for (int mt=0;mt<2;mt++)
    #pragma unroll
    for (int nt=0;nt<4;nt++){
      int r = row0 + wm*32 + mt*16 + (lane>>2);
      int c = col0 + wn*32 + nt*8 + (lane&3)*2;
      float b0v = bd[c], b1v = bd[c+1];
      *(unsigned*)&g_delta[(size_t)r*DIi + c] =
          h2pack(spf(acc[mt][nt][0]+b0v), spf(acc[mt][nt][1]+b1v));
      *(unsigned*)&g_delta[(size_t)(r+8)*DIi + c] =
          h2pack(spf(acc[mt][nt][2]+b0v), spf(acc[mt][nt][3]+b1v));
    }
}

// out_proj: yg[8192,512](half) @ out_w[512,256] + residual (in place on g_res)
__global__ void k_gemm_out(int b0, int b1){
  int col0 = blockIdx.x*64, row0 = blockIdx.y*128;
  int half = row0 >> 12;
  const __half* WT = g_owT + (size_t)(half ? b1 : b0)*131072;
  TC_DECL();
#define LOADA(k0_) { raH = *(const uint4*)&g_yg[(size_t)(row0+s_r)*DIi + (k0_)+s_kb]; }
#define LOADB(k0_) { rbH = *(const uint2*)&WT[(size_t)(col0+s_bn)*DIi + (k0_) + s_bq*4]; }
  TC_BODY_H(DIi);
#undef LOADA
#undef LOADB
  #pragma unroll
  for (int mt=0;mt<2;mt++)
    #pragma unroll
    for (int nt=0;nt<4;nt++){
      int r = row0 + wm*32 + mt*16 + (lane>>2);
      int c = col0 + wn*32 + nt*8 + (lane&3)*2;
      float2 o0 = *(const float2*)&g_res[(size_t)r*DMm + c];
      float2 o1 = *(const float2*)&g_res[(size_t)(r+8)*DMm + c];
      *(float2*)&g_res[(size_t)r*DMm + c] =
          make_float2(acc[mt][nt][0]+o0.x, acc[mt][nt][1]+o0.y);
      *(float2*)&g_res[(size_t)(r+8)*DMm + c] =
          make_float2(acc[mt][nt][2]+o1.x, acc[mt][nt][3]+o1.y);
    }
}

// merge: concat(res_half0, res_half1_reversed)[4096,512] @ merge_w[512,256] -> out
__global__ void k_merge(float* __restrict__ out){
  int col0 = blockIdx.x*64, row0 = blockIdx.y*128;
  TC_DECL();
  int r_ = row0 + s_r;
  int b_ = r_ >> 11, s_ = r_ & (Ss-1);
  int rrev = MM + b_*Ss + (Ss-1-s_);
#define LOADA(k0_) {                                                               \
    int kk0 = (k0_)+s_kb, kk1 = (k0_)+s_kb+4;                                      \
    raA0 = *(const float4*)((kk0 < DMm) ? (g_res + (size_t)r_*DMm + kk0)           \
                                        : (g_res + (size_t)rrev*DMm + kk0-DMm));   \
    raA1 = *(const float4*)((kk1 < DMm) ? (g_res + (size_t)r_*DMm + kk1)           \
                                        : (g_res + (size_t)rrev*DMm + kk1-DMm)); }
#define LOADB(k0_) { rbH = *(const uint2*)&g_mwT[(size_t)(col0+s_bn)*(2*DMm) + (k0_) + s_bq*4]; }
  TC_BODY(2*DMm);
#undef LOADA
#undef LOADB
  #pragma unroll
  for (int mt=0;mt<2;mt++)
    #pragma unroll
    for (int nt=0;nt<4;nt++){
      int r = row0 + wm*32 + mt*16 + (lane>>2);
      int c = col0 + wn*32 + nt*8 + (lane&3)*2;
      *(float2*)&out[(size_t)r*DMm + c]     = make_float2(acc[mt][nt][0], acc[mt][nt][1]);
      *(float2*)&out[(size_t)(r+8)*DMm + c] = make_float2(acc[mt][nt][2], acc[mt][nt][3]);
    }
}

// ---------------- causal depthwise conv (K=4) + silu, half I/O ----------------
__global__ void k_conv(const float* __restrict__ cw0, const float* __restrict__ cb0,
                       const float* __restrict__ cw1, const float* __restrict__ cb1){
  int idx = blockIdx.x*256 + threadIdx.x;   // (M2/4)*128
  int d4 = idx & 127, g = idx >> 7;         // g in [0, M2/4)
  int b2 = g >> 9, sg = g & 511;            // seq 0..3, group within seq
  int half = b2 >> 1;
  const float* cw = half ? cw1 : cw0;
  const float* cb = half ? cb1 : cb0;
  int m0 = b2*Ss + sg*4;
  int d = d4*4;
  float4 w0 = *(const float4*)(cw + (d+0)*4);
  float4 w1 = *(const float4*)(cw + (d+1)*4);
  float4 w2 = *(const float4*)(cw + (d+2)*4);
  float4 w3 = *(const float4*)(cw + (d+3)*4);
  float4 bv = *(const float4*)(cb + d);
  float4 x0, x1, x2;
  if (sg > 0){
    x0 = h4load(&g_xs[(size_t)(m0-3)*DIi + d]);
    x1 = h4load(&g_xs[(size_t)(m0-2)*DIi + d]);
    x2 = h4load(&g_xs[(size_t)(m0-1)*DIi + d]);
  } else {
    x0 = x1 = x2 = make_float4(0.f,0.f,0.f,0.f);
  }
  #pragma unroll
  for (int s=0;s<4;s++){
    float4 x3 = h4load(&g_xs[(size_t)(m0+s)*DIi + d]);
    float4 a;
    a.x = bv.x + w0.x*x0.x + w0.y*x1.x + w0.z*x2.x + w0.w*x3.x;
    a.y = bv.y + w1.x*x0.y + w1.y*x1.y + w1.z*x2.y + w1.w*x3.y;
    a.z = bv.z + w2.x*x0.z + w2.y*x1.z + w2.z*x2.z + w2.w*x3.z;
    a.w = bv.w + w3.x*x0.w + w3.y*x1.w + w3.z*x2.w + w3.w*x3.w;
    a.x = siluf(a.x); a.y = siluf(a.y); a.z = siluf(a.z); a.w = siluf(a.w);
    h4store(&g_xc[(size_t)(m0+s)*DIi + d], a);
    x0 = x1; x1 = x2; x2 = x3;
  }
}

// dA helper: if A[n] == -(n+1) (the actual dataset), dA_n = r^(n+1) with
// r = exp(-delta): 1 MUFU + 15 FMUL instead of 16 MUFU.
__device__ __forceinline__ void dA_compute(float* dAv, const float* A,
                                           float dlt, bool fast){
  if (fast){
    float r = __expf(-dlt);
    dAv[0] = r; dAv[1] = r*r;
    #pragma unroll
    for (int n=2;n<NN;n++) dAv[n] = dAv[n>>1]*dAv[(n-1)>>1];
  } else {
    #pragma unroll
    for (int n=0;n<NN;n++) dAv[n] = __expf(dlt*A[n]);
  }
}

__device__ __forceinline__ bool a_fast(const float* A){
  bool f = true;
  #pragma unroll
  for (int n=0;n<NN;n++) f = f && (fabsf(A[n] + (float)(n+1)) < 1e-5f*(n+1));
  return f;
}

// ---------------- chunked scan phase 1 ----------------
__global__ void k_scan1(const float* __restrict__ Alog0, const float* __restrict__ Alog1){
  __shared__ float sB[CHUNK][NN];
  int blk = blockIdx.x;               // 2 * NSEQ*NCH = 512
  int bc_ = blk >> 1;                 // 0..255
  int seq = bc_ >> 6, c = bc_ & 63;
  int half = seq >> 1;
  const float* Alog = half ? Alog1 : Alog0;
  int d = (blk & 1)*256 + threadIdx.x;
  int m0 = seq*Ss + c*CHUNK;
  { int i0 = threadIdx.x, i1 = threadIdx.x + 256;
    sB[i0>>4][i0&15] = g_proj[(size_t)(m0+(i0>>4))*64 + 32 + (i0&15)];
    sB[i1>>4][i1&15] = g_proj[(size_t)(m0+(i1>>4))*64 + 32 + (i1&15)]; }
  float A[NN];
  #pragma unroll
  for (int n=0;n<NN;n++) A[n] = -__expf(Alog[d*NN + n]);
  bool fast = a_fast(A);
  __syncthreads();
  float h[NN];
  #pragma unroll
  for (int n=0;n<NN;n++) h[n] = 0.f;
  float sd = 0.f;
  #pragma unroll 1
  for (int s=0;s<CHUNK;s++){
    size_t m = m0 + s;
    float dlt = __half2float(g_delta[m*DIi + d]);
    float dx  = dlt * __half2float(g_xc[m*DIi + d]);
    sd += dlt;
    float dAv[NN];
    dA_compute(dAv, A, dlt, fast);
    #pragma unroll
    for (int n=0;n<NN;n++) h[n] = dAv[n]*h[n] + dx*sB[s][n];
  }
  size_t base = ((size_t)bc_*DIi + d)*NN;
  float Pv[NN];
  dA_compute(Pv, A, sd, fast);
  #pragma unroll
  for (int n=0;n<NN;n++){ g_Q[base+n]=h[n]; g_P[base+n]=Pv[n]; }
}

// ---------------- phase 2: combine across chunks ----------------
__global__ void k_comb(){
  int i = blockIdx.x*128 + threadIdx.x;     // NSEQ*DIi*NN = 32768
  int n = i & 15, d = (i >> 4) & (DIi-1), seq = i >> 13;
  float H = 0.f;
  for (int c=0;c<NCH;c++){
    size_t idx = (((size_t)(seq*NCH+c))*DIi + d)*NN + n;
    g_Hin[idx] = H;
    H = g_P[idx]*H + g_Q[idx];
  }
}

// ---------------- phase 3: replay + gated output ----------------
__global__ void k_scan2(const float* __restrict__ Alog0, const float* __restrict__ Alog1,
                        const float* __restrict__ Dp0, const float* __restrict__ Dp1){
  __shared__ float sB[CHUNK][NN];
  __shared__ float sC[CHUNK][NN];
  int blk = blockIdx.x;
  int bc_ = blk >> 1;
  int seq = bc_ >> 6, c = bc_ & 63;
  int half = seq >> 1;
  const float* Alog = half ? Alog1 : Alog0;
  const float* Dp   = half ? Dp1   : Dp0;
  int d = (blk & 1)*256 + threadIdx.x;
  int m0 = seq*Ss + c*CHUNK;
  { int i0 = threadIdx.x, i1 = threadIdx.x + 256;
    sB[i0>>4][i0&15] = g_proj[(size_t)(m0+(i0>>4))*64 + 32 + (i0&15)];
    sB[i1>>4][i1&15] = g_proj[(size_t)(m0+(i1>>4))*64 + 32 + (i1&15)];
    sC[i0>>4][i0&15] = g_proj[(size_t)(m0+(i0>>4))*64 + 48 + (i0&15)];
    sC[i1>>4][i1&15] = g_proj[(size_t)(m0+(i1>>4))*64 + 48 + (i1&15)]; }
  float A[NN];
  #pragma unroll
  for (int n=0;n<NN;n++) A[n] = -__expf(Alog[d*NN + n]);
  bool fast = a_fast(A);
  float h[NN];
  size_t base = ((size_t)bc_*DIi + d)*NN;
  #pragma unroll
  for (int n=0;n<NN;n++) h[n] = g_Hin[base+n];
  float Dv = Dp[d];
  __syncthreads();
  #pragma unroll 1
  for (int s=0;s<CHUNK;s++){
    size_t m = m0 + s;
    float dlt = __half2float(g_delta[m*DIi + d]);
    float x   = __half2float(g_xc[m*DIi + d]);
    float dx  = dlt * x;
    float dAv[NN];
    dA_compute(dAv, A, dlt, fast);
    float y = 0.f;
    #pragma unroll
    for (int n=0;n<NN;n++){
      h[n] = dAv[n]*h[n] + dx*sB[s][n];
      y += h[n]*sC[s][n];
    }
    y += Dv*x;
    float zv = __half2float(g_z[m*DIi + d]);
    g_yg[m*DIi + d] = __float2half(y * siluf(zv));
  }
}

// ---------------- driver ----------------
extern "C" void kernel_launch(void* const* d_in, const int* in_sizes, int n_in,
                              void* d_out, int out_size){
  const float* x      = (const float*)d_in[0];
  const float* in_w   = (const float*)d_in[1];
  const float* conv_w = (const float*)d_in[2];
  const float* conv_b = (const float*)d_in[3];
  const float* A_log  = (const float*)d_in[4];
  const float* xd_w   = (const float*)d_in[5];
  const float* xB_w   = (const float*)d_in[6];
  const float* xC_w   = (const float*)d_in[7];
  const float* dtp_w  = (const float*)d_in[8];
  const float* dtp_b  = (const float*)d_in[9];
  const float* Dp     = (const float*)d_in[10];
  const float* out_w  = (const float*)d_in[11];
  const float* ln_g   = (const float*)d_in[12];
  const float* ln_b   = (const float*)d_in[13];
  const float* merge_w= (const float*)d_in[14];
  float* out = (float*)d_out;

  k_wprep<<<7424, 256>>>(in_w, xd_w, xB_w, xC_w, dtp_w, out_w, merge_w);
  k_init <<<M2*64/256, 256>>>(x);
  for (int bi=0; bi<2; bi++){
    int b0 = bi, b1 = 2 + bi;
    k_gemm_in <<<dim3(16,64), 256>>>(b0, b1,
                                     ln_g + b0*DMm, ln_b + b0*DMm,
                                     ln_g + b1*DMm, ln_b + b1*DMm);
    k_conv    <<<(M2/4)*128/256, 256>>>(conv_w + b0*DIi*4, conv_b + b0*DIi,
                                        conv_w + b1*DIi*4, conv_b + b1*DIi);
    k_gemm_x  <<<dim3(KS,64), 256>>>(b0, b1);
    k_xred    <<<M2*16/256, 256>>>();
    k_gemm_dt <<<dim3(8,64), 256>>>(b0, b1, dtp_b + b0*DIi, dtp_b + b1*DIi);
    k_scan1   <<<2*NSEQ*NCH, 256>>>(A_log + b0*DIi*NN, A_log + b1*DIi*NN);
    k_comb    <<<256, 128>>>();
    k_scan2   <<<2*NSEQ*NCH, 256>>>(A_log + b0*DIi*NN, A_log + b1*DIi*NN,
                                    Dp + b0*DIi, Dp + b1*DIi);
    k_gemm_out<<<dim3(4,64), 256>>>(b0, b1);
  }
  k_merge<<<dim3(4,32), 256>>>(out);
}

// round 12
// speedup vs baseline: 1.1097x; 1.1097x over previous
#include <cuda_runtime.h>
#include <cuda_fp16.h>

// ---------------- problem constants ----------------
#define Bb   2
#define Ss   2048
#define DMm  256
#define DIi  512
#define NN   16
#define RR   32
#define MM   (Bb*Ss)          // 4096 rows per chain
#define M2   (2*MM)           // 8192 rows: [fwd | reversed]
#define CHUNK 32
#define NCH  (Ss/CHUNK)       // 64 chunks per sequence
#define NSEQ 4                // 4 sequences total (2 fwd + 2 rev)
#define KS   4                // split-K for x-proj

// ---------------- device scratch ----------------
__device__ float  g_res [M2*DMm];
__device__ __half g_xs  [M2*DIi];
__device__ __half g_z   [M2*DIi];
__device__ __half g_xc  [M2*DIi];
__device__ float  g_proj[M2*64];          // [xd(32) | B(16) | C(16)] fp32
__device__ __half g_projh[M2*64];         // half mirror for gemm_dt A-path
__device__ float  g_projp[KS*M2*64];      // split-K partials (fp32)
__device__ __half g_delta[M2*DIi];
__device__ __half g_yg  [M2*DIi];
__device__ float  g_P   [NSEQ*NCH*DIi*NN];
__device__ float  g_Q   [NSEQ*NCH*DIi*NN];
__device__ float  g_Hin [NSEQ*NCH*DIi*NN];

// k-pair-packed half2 weight mirrors: W2[k/2][n] = (W[k][n], W[k+1][n])
// stored as u32; n-fastest => B loads stay fully coalesced.
__device__ unsigned g_win2[4*128*1024];   // in_w:   [blk][k2=128][n=1024]
__device__ unsigned g_xw2 [4*256*64];     // xd|xB|xC: [blk][k2=256][n=64]
__device__ unsigned g_dtw2[4*16*512];     // dtp_w:  [blk][k2=16][n=512]
__device__ unsigned g_ow2 [4*256*256];    // out_w:  [blk][k2=256][n=256]
__device__ unsigned g_mw2 [256*256];      // merge_w:[k2=256][n=256]

__device__ __forceinline__ float siluf(float x){ return x / (1.f + __expf(-x)); }
__device__ __forceinline__ float spf(float a){ return (a > 20.f) ? a : log1pf(__expf(a)); }

__device__ __forceinline__ unsigned h2pack(float a, float b){
  __half2 h = __floats2half2_rn(a, b);
  return *reinterpret_cast<unsigned*>(&h);
}
__device__ __forceinline__ float4 h4load(const __half* p){
  uint2 u = *(const uint2*)p;
  float2 fa = __half22float2(*(__half2*)&u.x);
  float2 fb = __half22float2(*(__half2*)&u.y);
  return make_float4(fa.x, fa.y, fb.x, fb.y);
}
__device__ __forceinline__ void h4store(__half* p, float4 v){
  uint2 u; u.x = h2pack(v.x, v.y); u.y = h2pack(v.z, v.w);
  *(uint2*)p = u;
}

#define MMA16(c, a, b)                                                       \
  asm volatile("mma.sync.aligned.m16n8k16.row.col.f32.f16.f16.f32 "          \
               "{%0,%1,%2,%3},{%4,%5,%6,%7},{%8,%9},{%0,%1,%2,%3};"          \
               : "+f"((c)[0]), "+f"((c)[1]), "+f"((c)[2]), "+f"((c)[3])      \
               : "r"((a)[0]), "r"((a)[1]), "r"((a)[2]), "r"((a)[3]),         \
                 "r"((b)[0]), "r"((b)[1]))

// ---------------- weight prep: fp32 -> k-pair half2, once per launch ------
__global__ void k_wprep(const float* __restrict__ in_w,
                        const float* __restrict__ xd_w,
                        const float* __restrict__ xB_w,
                        const float* __restrict__ xC_w,
                        const float* __restrict__ dtp_w,
                        const float* __restrict__ out_w,
                        const float* __restrict__ merge_w){
  int i = blockIdx.x*256 + threadIdx.x;       // 950272 total u32
  if (i < 524288){                            // in_w: [blk][k=256][n=1024]
    int blk = i >> 17, r = i & 131071;
    int k2 = r >> 10, n = r & 1023;
    size_t base = (size_t)blk*262144 + (size_t)(2*k2)*1024 + n;
    g_win2[i] = h2pack(in_w[base], in_w[base + 1024]);
  } else if (i < 589824){                     // xd|xB|xC: [blk][k=512][n=64]
    int j = i - 524288;
    int blk = j >> 14, r = j & 16383;
    int k2 = r >> 6, n = r & 63;
    float v0, v1;
    if (n < 32){
      size_t b = (size_t)blk*16384 + (size_t)(2*k2)*32 + n;
      v0 = xd_w[b]; v1 = xd_w[b + 32];
    } else if (n < 48){
      size_t b = (size_t)blk*8192 + (size_t)(2*k2)*16 + (n-32);
      v0 = xB_w[b]; v1 = xB_w[b + 16];
    } else {
      size_t b = (size_t)blk*8192 + (size_t)(2*k2)*16 + (n-48);
      v0 = xC_w[b]; v1 = xC_w[b + 16];
    }
    g_xw2[j] = h2pack(v0, v1);
  } else if (i < 622592){                     // dtp_w: [blk][k=32][n=512]
    int j = i - 589824;
    int blk = j >> 13, r = j & 8191;
    int k2 = r >> 9, n = r & 511;
    size_t b = (size_t)blk*16384 + (size_t)(2*k2)*512 + n;
    g_dtw2[j] = h2pack(dtp_w[b], dtp_w[b + 512]);
  } else if (i < 884736){                     // out_w: [blk][k=512][n=256]
    int j = i - 622592;
    int blk = j >> 16, r = j & 65535;
    int k2 = r >> 8, n = r & 255;
    size_t b = (size_t)blk*131072 + (size_t)(2*k2)*256 + n;
    g_ow2[j] = h2pack(out_w[b], out_w[b + 256]);
  } else if (i < 950272){                     // merge_w: [k=512][n=256]
    int j = i - 884736;
    int k2 = j >> 8, n = j & 255;
    size_t b = (size_t)(2*k2)*256 + n;
    g_mw2[j] = h2pack(merge_w[b], merge_w[b + 256]);
  }
}

// ---------------- init: fwd + reversed copies ----------------
__global__ void k_init(const float* __restrict__ x){
  int idx = blockIdx.x*256 + threadIdx.x;       // M2*64 float4s
  int col = idx & 63;
  int m   = idx >> 6;                           // 0..8191
  int half = m >> 12;
  int b = (m >> 11) & 1, s = m & (Ss-1);
  int ms = b*Ss + (half ? (Ss-1-s) : s);
  reinterpret_cast<float4*>(g_res)[m*64+col] =
      reinterpret_cast<const float4*>(x)[ms*64+col];
}

// ======================================================================
// FP16 tensor-core GEMM core, double-buffered, mma.m16n8k16.
// Block tile 128(M) x 64(N), 256 threads = 8 warps (4 M x 2 N),
// warp tile 32x32. K-chunk = 16.  (round-7 proven core)
// B operands: 2 coalesced LDG.32 of k-pair half2 mirrors -> direct STS.
// ======================================================================
#define TC_DECL()                                                     \
  __shared__ __align__(16) unsigned Af[2][1024];                      \
  __shared__ __align__(16) unsigned Bf[2][512];                       \
  const int t = threadIdx.x;                                          \
  const int lane = t & 31, wid = t >> 5;                              \
  const int wm = wid >> 1, wn = wid & 1;                              \
  const int s_r  = t >> 1;          /* A staging row 0..127  */       \
  const int s_kb = (t & 1) * 8;     /* A staging k base 0/8  */       \
  const int s_bq = t >> 6;          /* B staging k-quad 0..3 */       \
  const int s_bn = t & 63;          /* B staging n 0..63     */       \
  float acc[2][4][4] = {};                                            \
  float4 raA0, raA1; uint4 raH; unsigned rbx, rby;                    \
  (void)raA0; (void)raA1; (void)raH;

#define TC_AB(buf) &Af[buf][(((s_r>>4)*32 + ((s_r&7)*4))*4) + ((s_r>>3)&1) + ((s_kb>>2)&2)]

#define TC_STAGE_B(buf) {                                             \
  int ln0 = (s_bn & 7)*4 + ((2*s_bq) & 3);                            \
  int rgB = s_bq >> 1;                                                \
  unsigned* bb = &Bf[buf][((s_bn >> 3)*32 + ln0)*2 + rgB];            \
  bb[0] = rbx;                                                        \
  bb[2] = rby; }

#define TC_STAGE_F(buf) {                                             \
  unsigned* ab = TC_AB(buf);                                          \
  ab[0]  = h2pack(raA0.x, raA0.y);                                    \
  ab[4]  = h2pack(raA0.z, raA0.w);                                    \
  ab[8]  = h2pack(raA1.x, raA1.y);                                    \
  ab[12] = h2pack(raA1.z, raA1.w);                                    \
  TC_STAGE_B(buf) }

#define TC_STAGE_H(buf) {                                             \
  unsigned* ab = TC_AB(buf);                                          \
  ab[0]  = raH.x;                                                     \
  ab[4]  = raH.y;                                                     \
  ab[8]  = raH.z;                                                     \
  ab[12] = raH.w;                                                     \
  TC_STAGE_B(buf) }

#define TC_COMP(buf) {                                                \
  unsigned a_[2][4]; unsigned b_[4][2];                               \
  _Pragma("unroll") for (int mt=0;mt<2;mt++)                          \
    *(uint4*)a_[mt] = *(const uint4*)&Af[buf][((wm*2+mt)*32 + lane)*4]; \
  _Pragma("unroll") for (int nt=0;nt<4;nt++)                          \
    *(uint2*)b_[nt] = *(const uint2*)&Bf[buf][((wn*4+nt)*32 + lane)*2]; \
  _Pragma("unroll") for (int mt=0;mt<2;mt++)                          \
    _Pragma("unroll") for (int nt=0;nt<4;nt++)                        \
      MMA16(acc[mt][nt], a_[mt], b_[nt]); }

#define TC_BODY_GEN(KT, STG)                                          \
  LOADA(0); LOADB(0);                                                 \
  STG(0);                                                             \
  if (16 < (KT)) { LOADA(16); LOADB(16); }                            \
  __syncthreads();                                                    \
  { int cur = 0;                                                      \
    _Pragma("unroll 1")                                               \
    for (int k0=0; k0<(KT); k0+=16){                                  \
      if (k0+16 < (KT)) STG(cur^1);                                   \
      if (k0+32 < (KT)) { LOADA(k0+32); LOADB(k0+32); }               \
      TC_COMP(cur);                                                   \
      __syncthreads();                                                \
      cur ^= 1;                                                       \
    } }

#define TC_BODY(KT)   TC_BODY_GEN(KT, TC_STAGE_F)
#define TC_BODY_H(KT) TC_BODY_GEN(KT, TC_STAGE_H)

// in_proj with fused LayerNorm:
//   LN(g_res)[8192,256] @ in_w[256,1024] -> xs | z (half)   per-half weights
__global__ void k_gemm_in(int b0, int b1,
                          const float* __restrict__ g0, const float* __restrict__ bt0,
                          const float* __restrict__ g1, const float* __restrict__ bt1){
  int col0 = blockIdx.x*64, row0 = blockIdx.y*128;
  int half = row0 >> 12;
  const unsigned* W2 = g_win2 + (size_t)(half ? b1 : b0)*131072;
  const float* gm = half ? g1  : g0;
  const float* bb = half ? bt1 : bt0;
  __shared__ float sG[DMm], sBt[DMm];
  TC_DECL();
  sG[t] = gm[t]; sBt[t] = bb[t];
  const float* rowp = g_res + (size_t)(row0 + s_r)*DMm;
  float sum = 0.f, sq = 0.f;
  #pragma unroll
  for (int j=0;j<16;j++){
    float4 v0 = *(const float4*)&rowp[j*16 + s_kb];
    float4 v1 = *(const float4*)&rowp[j*16 + s_kb + 4];
    sum += v0.x+v0.y+v0.z+v0.w + v1.x+v1.y+v1.z+v1.w;
    sq  += v0.x*v0.x+v0.y*v0.y+v0.z*v0.z+v0.w*v0.w
         + v1.x*v1.x+v1.y*v1.y+v1.z*v1.z+v1.w*v1.w;
  }
  sum += __shfl_xor_sync(~0u, sum, 1);
  sq  += __shfl_xor_sync(~0u, sq, 1);
  float mean = sum*(1.f/DMm);
  float rstd = rsqrtf(sq*(1.f/DMm) - mean*mean + 1e-5f);
  __syncthreads();   // sG/sBt visible
#define LOADA(k0_) { int kk_=(k0_)+s_kb;                                           \
    raA0 = *(const float4*)&rowp[kk_];                                             \
    raA1 = *(const float4*)&rowp[kk_+4];                                           \
    raA0.x=(raA0.x-mean)*rstd*sG[kk_+0]+sBt[kk_+0];                                \
    raA0.y=(raA0.y-mean)*rstd*sG[kk_+1]+sBt[kk_+1];                                \
    raA0.z=(raA0.z-mean)*rstd*sG[kk_+2]+sBt[kk_+2];                                \
    raA0.w=(raA0.w-mean)*rstd*sG[kk_+3]+sBt[kk_+3];                                \
    raA1.x=(raA1.x-mean)*rstd*sG[kk_+4]+sBt[kk_+4];                                \
    raA1.y=(raA1.y-mean)*rstd*sG[kk_+5]+sBt[kk_+5];                                \
    raA1.z=(raA1.z-mean)*rstd*sG[kk_+6]+sBt[kk_+6];                                \
    raA1.w=(raA1.w-mean)*rstd*sG[kk_+7]+sBt[kk_+7]; }
#define LOADB(k0_) { int k2_ = ((k0_) >> 1) + s_bq*2;                              \
                     rbx = W2[(size_t)(k2_+0)*1024 + col0 + s_bn];                 \
                     rby = W2[(size_t)(k2_+1)*1024 + col0 + s_bn]; }
  TC_BODY(DMm);
#undef LOADA
#undef LOADB
  __half* dst = (col0 < DIi) ? g_xs : g_z;
  int cb = (col0 < DIi) ? col0 : col0 - DIi;
  #pragma unroll
  for (int mt=0;mt<2;mt++)
    #pragma unroll
    for (int nt=0;nt<4;nt++){
      int r = row0 + wm*32 + mt*16 + (lane>>2);
      int c = cb + wn*32 + nt*8 + (lane&3)*2;
      *(unsigned*)&dst[(size_t)r*DIi + c]     = h2pack(acc[mt][nt][0], acc[mt][nt][1]);
      *(unsigned*)&dst[(size_t)(r+8)*DIi + c] = h2pack(acc[mt][nt][2], acc[mt][nt][3]);
    }
}

// x-proj split-K: xc[8192,512](half) @ [xd(32)|xB(16)|xC(16)] -> projp[kz] (fp32)
__global__ void k_gemm_x(int b0, int b1){
  int kz = blockIdx.x, row0 = blockIdx.y*128;
  int half = row0 >> 12;
  int kbase = kz*(DIi/KS);
  const unsigned* W2 = g_xw2 + (size_t)(half ? b1 : b0)*16384;
  TC_DECL();
#define LOADA(k0_) { raH = *(const uint4*)&g_xc[(size_t)(row0+s_r)*DIi + kbase+(k0_)+s_kb]; }
#define LOADB(k0_) { int k2_ = ((kbase+(k0_)) >> 1) + s_bq*2;                      \
                     rbx = W2[(size_t)(k2_+0)*64 + s_bn];                          \
                     rby = W2[(size_t)(k2_+1)*64 + s_bn]; }
  TC_BODY_H(DIi/KS);
#undef LOADA
#undef LOADB
  float* dst = g_projp + (size_t)kz*M2*64;
  #pragma unroll
  for (int mt=0;mt<2;mt++)
    #pragma unroll
    for (int nt=0;nt<4;nt++){
      int r = row0 + wm*32 + mt*16 + (lane>>2);
      int c = wn*32 + nt*8 + (lane&3)*2;
      *(float2*)&dst[(size_t)r*64 + c]     = make_float2(acc[mt][nt][0], acc[mt][nt][1]);
      *(float2*)&dst[(size_t)(r+8)*64 + c] = make_float2(acc[mt][nt][2], acc[mt][nt][3]);
    }
}

__global__ void k_xred(){
  int i = blockIdx.x*256 + threadIdx.x;   // M2*16 float4s
  float4 a = reinterpret_cast<const float4*>(g_projp)[i];
  float4 b = reinterpret_cast<const float4*>(g_projp + (size_t)M2*64)[i];
  float4 c = reinterpret_cast<const float4*>(g_projp + (size_t)2*M2*64)[i];
  float4 d = reinterpret_cast<const float4*>(g_projp + (size_t)3*M2*64)[i];
  float4 s = make_float4(a.x+b.x+c.x+d.x, a.y+b.y+c.y+d.y,
                         a.z+b.z+c.z+d.z, a.w+b.w+c.w+d.w);
  reinterpret_cast<float4*>(g_proj)[i] = s;
  h4store(&g_projh[i*4], s);
}

// delta: softplus(projh[:, :32] @ dtp_w[32,512] + dtp_b) -> g_delta (half)
__global__ void k_gemm_dt(int b0, int b1,
                          const float* __restrict__ bd0, const float* __restrict__ bd1){
  int col0 = blockIdx.x*64, row0 = blockIdx.y*128;
  int half = row0 >> 12;
  const unsigned* W2 = g_dtw2 + (size_t)(half ? b1 : b0)*8192;
  const float* bd = half ? bd1 : bd0;
  TC_DECL();
#define LOADA(k0_) { raH = *(const uint4*)&g_projh[(size_t)(row0+s_r)*64 + (k0_)+s_kb]; }
#define LOADB(k0_) { int k2_ = ((k0_) >> 1) + s_bq*2;                              \
                     rbx = W2[(size_t)(k2_+0)*512 + col0 + s_bn];                  \
                     rby = W2[(size_t)(k2_+1)*512 + col0 + s_bn]; }
  TC_BODY_H(RR);
#undef LOADA
#undef LOADB
  #pragma unroll
  for (int mt=0;mt<2;mt++)
    #pragma unroll
    for (int nt=0;nt<4;nt++){
      int r = row0 + wm*32 + mt*16 + (lane>>2);
      int c = col0 + wn*32 + nt*8 + (lane&3)*2;
      float b0v = bd[c], b1v = bd[c+1];
      *(unsigned*)&g_delta[(size_t)r*DIi + c] =
          h2pack(spf(acc[mt][nt][0]+b0v), spf(acc[mt][nt][1]+b1v));
      *(unsigned*)&g_delta[(size_t)(r+8)*DIi + c] =
          h2pack(spf(acc[mt][nt][2]+b0v), spf(acc[mt][nt][3]+b1v));
    }
}

// out_proj: yg[8192,512](half) @ out_w[512,256] + residual (in place on g_res)
__global__ void k_gemm_out(int b0, int b1){
  int col0 = blockIdx.x*64, row0 = blockIdx.y*128;
  int half = row0 >> 12;
  const unsigned* W2 = g_ow2 + (size_t)(half ? b1 : b0)*65536;
  TC_DECL();
#define LOADA(k0_) { raH = *(const uint4*)&g_yg[(size_t)(row0+s_r)*DIi + (k0_)+s_kb]; }
#define LOADB(k0_) { int k2_ = ((k0_) >> 1) + s_bq*2;                              \
                     rbx = W2[(size_t)(k2_+0)*256 + col0 + s_bn];                  \
                     rby = W2[(size_t)(k2_+1)*256 + col0 + s_bn]; }
  TC_BODY_H(DIi);
#undef LOADA
#undef LOADB
  #pragma unroll
  for (int mt=0;mt<2;mt++)
    #pragma unroll
    for (int nt=0;nt<4;nt++){
      int r = row0 + wm*32 + mt*16 + (lane>>2);
      int c = col0 + wn*32 + nt*8 + (lane&3)*2;
      float2 o0 = *(const float2*)&g_res[(size_t)r*DMm + c];
      float2 o1 = *(const float2*)&g_res[(size_t)(r+8)*DMm + c];
      *(float2*)&g_res[(size_t)r*DMm + c] =
          make_float2(acc[mt][nt][0]+o0.x, acc[mt][nt][1]+o0.y);
      *(float2*)&g_res[(size_t)(r+8)*DMm + c] =
          make_float2(acc[mt][nt][2]+o1.x, acc[mt][nt][3]+o1.y);
    }
}

// merge: concat(res_half0, res_half1_reversed)[4096,512] @ merge_w[512,256] -> out
__global__ void k_merge(float* __restrict__ out){
  int col0 = blockIdx.x*64, row0 = blockIdx.y*128;
  TC_DECL();
  int r_ = row0 + s_r;
  int b_ = r_ >> 11, s_ = r_ & (Ss-1);
  int rrev = MM + b_*Ss + (Ss-1-s_);
#define LOADA(k0_) {                                                               \
    int kk0 = (k0_)+s_kb, kk1 = (k0_)+s_kb+4;                                      \
    raA0 = *(const float4*)((kk0 < DMm) ? (g_res + (size_t)r_*DMm + kk0)           \
                                        : (g_res + (size_t)rrev*DMm + kk0-DMm));   \
    raA1 = *(const float4*)((kk1 < DMm) ? (g_res + (size_t)r_*DMm + kk1)           \
                                        : (g_res + (size_t)rrev*DMm + kk1-DMm)); }
#define LOADB(k0_) { int k2_ = ((k0_) >> 1) + s_bq*2;                              \
                     rbx = g_mw2[(size_t)(k2_+0)*256 + col0 + s_bn];               \
                     rby = g_mw2[(size_t)(k2_+1)*256 + col0 + s_bn]; }
  TC_BODY(2*DMm);
#undef LOADA
#undef LOADB
  #pragma unroll
  for (int mt=0;mt<2;mt++)
    #pragma unroll
    for (int nt=0;nt<4;nt++){
      int r = row0 + wm*32 + mt*16 + (lane>>2);
      int c = col0 + wn*32 + nt*8 + (lane&3)*2;
      *(float2*)&out[(size_t)r*DMm + c]     = make_float2(acc[mt][nt][0], acc[mt][nt][1]);
      *(float2*)&out[(size_t)(r+8)*DMm + c] = make_float2(acc[mt][nt][2], acc[mt][nt][3]);
    }
}

// ---------------- causal depthwise conv (K=4) + silu, half I/O ----------------
__global__ void k_conv(const float* __restrict__ cw0, const float* __restrict__ cb0,
                       const float* __restrict__ cw1, const float* __restrict__ cb1){
  int idx = blockIdx.x*256 + threadIdx.x;   // (M2/4)*128
  int d4 = idx & 127, g = idx >> 7;         // g in [0, M2/4)
  int b2 = g >> 9, sg = g & 511;            // seq 0..3, group within seq
  int half = b2 >> 1;
  const float* cw = half ? cw1 : cw0;
  const float* cb = half ? cb1 : cb0;
  int m0 = b2*Ss + sg*4;
  int d = d4*4;
  float4 w0 = *(const float4*)(cw + (d+0)*4);
  float4 w1 = *(const float4*)(cw + (d+1)*4);
  float4 w2 = *(const float4*)(cw + (d+2)*4);
  float4 w3 = *(const float4*)(cw + (d+3)*4);
  float4 bv = *(const float4*)(cb + d);
  float4 x0, x1, x2;
  if (sg > 0){
    x0 = h4load(&g_xs[(size_t)(m0-3)*DIi + d]);
    x1 = h4load(&g_xs[(size_t)(m0-2)*DIi + d]);
    x2 = h4load(&g_xs[(size_t)(m0-1)*DIi + d]);
  } else {
    x0 = x1 = x2 = make_float4(0.f,0.f,0.f,0.f);
  }
  #pragma unroll
  for (int s=0;s<4;s++){
    float4 x3 = h4load(&g_xs[(size_t)(m0+s)*DIi + d]);
    float4 a;
    a.x = bv.x + w0.x*x0.x + w0.y*x1.x + w0.z*x2.x + w0.w*x3.x;
    a.y = bv.y + w1.x*x0.y + w1.y*x1.y + w1.z*x2.y + w1.w*x3.y;
    a.z = bv.z + w2.x*x0.z + w2.y*x1.z + w2.z*x2.z + w2.w*x3.z;
    a.w = bv.w + w3.x*x0.w + w3.y*x1.w + w3.z*x2.w + w3.w*x3.w;
    a.x = siluf(a.x); a.y = siluf(a.y); a.z = siluf(a.z); a.w = siluf(a.w);
    h4store(&g_xc[(size_t)(m0+s)*DIi + d], a);
    x0 = x1; x1 = x2; x2 = x3;
  }
}

// dA helper: if A[n] == -(n+1) (the actual dataset), dA_n = r^(n+1) with
// r = exp(-delta): 1 MUFU + 15 FMUL instead of 16 MUFU.
__device__ __forceinline__ void dA_compute(float* dAv, const float* A,
                                           float dlt, bool fast){
  if (fast){
    float r = __expf(-dlt);
    dAv[0] = r; dAv[1] = r*r;
    #pragma unroll
    for (int n=2;n<NN;n++) dAv[n] = dAv[n>>1]*dAv[(n-1)>>1];
  } else {
    #pragma unroll
    for (int n=0;n<NN;n++) dAv[n] = __expf(dlt*A[n]);
  }
}

__device__ __forceinline__ bool a_fast(const float* A){
  bool f = true;
  #pragma unroll
  for (int n=0;n<NN;n++) f = f && (fabsf(A[n] + (float)(n+1)) < 1e-5f*(n+1));
  return f;
}

// ---------------- chunked scan phase 1 ----------------
__global__ void k_scan1(const float* __restrict__ Alog0, const float* __restrict__ Alog1){
  __shared__ float sB[CHUNK][NN];
  int blk = blockIdx.x;               // 2 * NSEQ*NCH = 512
  int bc_ = blk >> 1;                 // 0..255
  int seq = bc_ >> 6, c = bc_ & 63;
  int half = seq >> 1;
  const float* Alog = half ? Alog1 : Alog0;
  int d = (blk & 1)*256 + threadIdx.x;
  int m0 = seq*Ss + c*CHUNK;
  { int i0 = threadIdx.x, i1 = threadIdx.x + 256;
    sB[i0>>4][i0&15] = g_proj[(size_t)(m0+(i0>>4))*64 + 32 + (i0&15)];
    sB[i1>>4][i1&15] = g_proj[(size_t)(m0+(i1>>4))*64 + 32 + (i1&15)]; }
  float A[NN];
  #pragma unroll
  for (int n=0;n<NN;n++) A[n] = -__expf(Alog[d*NN + n]);
  bool fast = a_fast(A);
  __syncthreads();
  float h[NN];
  #pragma unroll
  for (int n=0;n<NN;n++) h[n] = 0.f;
  float sd = 0.f;
  #pragma unroll 1
  for (int s=0;s<CHUNK;s++){
    size_t m = m0 + s;
    float dlt = __half2float(g_delta[m*DIi + d]);
    float dx  = dlt * __half2float(g_xc[m*DIi + d]);
    sd += dlt;
    float dAv[NN];
    dA_compute(dAv, A, dlt, fast);
    #pragma unroll
    for (int n=0;n<NN;n++) h[n] = dAv[n]*h[n] + dx*sB[s][n];
  }
  size_t base = ((size_t)bc_*DIi + d)*NN;
  float Pv[NN];
  dA_compute(Pv, A, sd, fast);
  #pragma unroll
  for (int n=0;n<NN;n++){ g_Q[base+n]=h[n]; g_P[base+n]=Pv[n]; }
}

// ---------------- phase 2: combine across chunks ----------------
__global__ void k_comb(){
  int i = blockIdx.x*128 + threadIdx.x;     // NSEQ*DIi*NN = 32768
  int n = i & 15, d = (i >> 4) & (DIi-1), seq = i >> 13;
  float H = 0.f;
  for (int c=0;c<NCH;c++){
    size_t idx = (((size_t)(seq*NCH+c))*DIi + d)*NN + n;
    g_Hin[idx] = H;
    H = g_P[idx]*H + g_Q[idx];
  }
}

// ---------------- phase 3: replay + gated output ----------------
__global__ void k_scan2(const float* __restrict__ Alog0, const float* __restrict__ Alog1,
                        const float* __restrict__ Dp0, const float* __restrict__ Dp1){
  __shared__ float sB[CHUNK][NN];
  __shared__ float sC[CHUNK][NN];
  int blk = blockIdx.x;
  int bc_ = blk >> 1;
  int seq = bc_ >> 6, c = bc_ & 63;
  int half = seq >> 1;
  const float* Alog = half ? Alog1 : Alog0;
  const float* Dp   = half ? Dp1   : Dp0;
  int d = (blk & 1)*256 + threadIdx.x;
  int m0 = seq*Ss + c*CHUNK;
  { int i0 = threadIdx.x, i1 = threadIdx.x + 256;
    sB[i0>>4][i0&15] = g_proj[(size_t)(m0+(i0>>4))*64 + 32 + (i0&15)];
    sB[i1>>4][i1&15] = g_proj[(size_t)(m0+(i1>>4))*64 + 32 + (i1&15)];
    sC[i0>>4][i0&15] = g_proj[(size_t)(m0+(i0>>4))*64 + 48 + (i0&15)];
    sC[i1>>4][i1&15] = g_proj[(size_t)(m0+(i1>>4))*64 + 48 + (i1&15)]; }
  float A[NN];
  #pragma unroll
  for (int n=0;n<NN;n++) A[n] = -__expf(Alog[d*NN + n]);
  bool fast = a_fast(A);
  float h[NN];
  size_t base = ((size_t)bc_*DIi + d)*NN;
  #pragma unroll
  for (int n=0;n<NN;n++) h[n] = g_Hin[base+n];
  float Dv = Dp[d];
  __syncthreads();
  #pragma unroll 1
  for (int s=0;s<CHUNK;s++){
    size_t m = m0 + s;
    float dlt = __half2float(g_delta[m*DIi + d]);
    float x   = __half2float(g_xc[m*DIi + d]);
    float dx  = dlt * x;
    float dAv[NN];
    dA_compute(dAv, A, dlt, fast);
    float y = 0.f;
    #pragma unroll
    for (int n=0;n<NN;n++){
      h[n] = dAv[n]*h[n] + dx*sB[s][n];
      y += h[n]*sC[s][n];
    }
    y += Dv*x;
    float zv = __half2float(g_z[m*DIi + d]);
    g_yg[m*DIi + d] = __float2half(y * siluf(zv));
  }
}

// ---------------- driver ----------------
extern "C" void kernel_launch(void* const* d_in, const int* in_sizes, int n_in,
                              void* d_out, int out_size){
  const float* x      = (const float*)d_in[0];
  const float* in_w   = (const float*)d_in[1];
  const float* conv_w = (const float*)d_in[2];
  const float* conv_b = (const float*)d_in[3];
  const float* A_log  = (const float*)d_in[4];
  const float* xd_w   = (const float*)d_in[5];
  const float* xB_w   = (const float*)d_in[6];
  const float* xC_w   = (const float*)d_in[7];
  const float* dtp_w  = (const float*)d_in[8];
  const float* dtp_b  = (const float*)d_in[9];
  const float* Dp     = (const float*)d_in[10];
  const float* out_w  = (const float*)d_in[11];
  const float* ln_g   = (const float*)d_in[12];
  const float* ln_b   = (const float*)d_in[13];
  const float* merge_w= (const float*)d_in[14];
  float* out = (float*)d_out;

  k_wprep<<<3712, 256>>>(in_w, xd_w, xB_w, xC_w, dtp_w, out_w, merge_w);
  k_init <<<M2*64/256, 256>>>(x);
  for (int bi=0; bi<2; bi++){
    int b0 = bi, b1 = 2 + bi;
    k_gemm_in <<<dim3(16,64), 256>>>(b0, b1,
                                     ln_g + b0*DMm, ln_b + b0*DMm,
                                     ln_g + b1*DMm, ln_b + b1*DMm);
    k_conv    <<<(M2/4)*128/256, 256>>>(conv_w + b0*DIi*4, conv_b + b0*DIi,
                                        conv_w + b1*DIi*4, conv_b + b1*DIi);
    k_gemm_x  <<<dim3(KS,64), 256>>>(b0, b1);
    k_xred    <<<M2*16/256, 256>>>();
    k_gemm_dt <<<dim3(8,64), 256>>>(b0, b1, dtp_b + b0*DIi, dtp_b + b1*DIi);
    k_scan1   <<<2*NSEQ*NCH, 256>>>(A_log + b0*DIi*NN, A_log + b1*DIi*NN);
    k_comb    <<<256, 128>>>();
    k_scan2   <<<2*NSEQ*NCH, 256>>>(A_log + b0*DIi*NN, A_log + b1*DIi*NN,
                                    Dp + b0*DIi, Dp + b1*DIi);
    k_gemm_out<<<dim3(4,64), 256>>>(b0, b1);
  }
  k_merge<<<dim3(4,32), 256>>>(out);
}

// round 13
// speedup vs baseline: 1.1645x; 1.0494x over previous
#include <cuda_runtime.h>
#include <cuda_fp16.h>

// ---------------- problem constants ----------------
#define Bb   2
#define Ss   2048
#define DMm  256
#define DIi  512
#define NN   16
#define RR   32
#define MM   (Bb*Ss)          // 4096 rows per chain
#define M2   (2*MM)           // 8192 rows: [fwd | reversed]
#define CHUNK 32
#define NCH  (Ss/CHUNK)       // 64 chunks per sequence
#define NSEQ 4                // 4 sequences total (2 fwd + 2 rev)
#define KS   4                // split-K for x-proj

// ---------------- device scratch ----------------
__device__ float  g_res [M2*DMm];
__device__ __half g_xs  [M2*DIi];
__device__ __half g_z   [M2*DIi];
__device__ __half g_xc  [M2*DIi];
__device__ float  g_proj[M2*64];          // [xd(32) | B(16) | C(16)] fp32
__device__ __half g_projh[M2*64];         // half mirror for gemm_dt A-path
__device__ float  g_projp[KS*M2*64];      // split-K partials (fp32)
__device__ __half g_delta[M2*DIi];
__device__ __half g_yg  [M2*DIi];
__device__ float  g_P   [NSEQ*NCH*DIi*NN];
__device__ float  g_Q   [NSEQ*NCH*DIi*NN];
__device__ float  g_Hin [NSEQ*NCH*DIi*NN];

// k-pair-packed half2 weight mirrors: W2[k/2][n] = (W[k][n], W[k+1][n])
__device__ unsigned g_win2[4*128*1024];   // in_w:   [blk][k2=128][n=1024]
__device__ unsigned g_xw2 [4*256*64];     // xd|xB|xC: [blk][k2=256][n=64]
__device__ unsigned g_dtw2[4*16*512];     // dtp_w:  [blk][k2=16][n=512]
__device__ unsigned g_ow2 [4*256*256];    // out_w:  [blk][k2=256][n=256]
__device__ unsigned g_mw2 [256*256];      // merge_w:[k2=256][n=256]

__device__ __forceinline__ float siluf(float x){ return x / (1.f + __expf(-x)); }
__device__ __forceinline__ float spf(float a){ return (a > 20.f) ? a : log1pf(__expf(a)); }

__device__ __forceinline__ unsigned h2pack(float a, float b){
  __half2 h = __floats2half2_rn(a, b);
  return *reinterpret_cast<unsigned*>(&h);
}
__device__ __forceinline__ float4 h4load(const __half* p){
  uint2 u = *(const uint2*)p;
  float2 fa = __half22float2(*(__half2*)&u.x);
  float2 fb = __half22float2(*(__half2*)&u.y);
  return make_float4(fa.x, fa.y, fb.x, fb.y);
}
__device__ __forceinline__ void h4store(__half* p, float4 v){
  uint2 u; u.x = h2pack(v.x, v.y); u.y = h2pack(v.z, v.w);
  *(uint2*)p = u;
}

#define MMA16(c, a, b)                                                       \
  asm volatile("mma.sync.aligned.m16n8k16.row.col.f32.f16.f16.f32 "          \
               "{%0,%1,%2,%3},{%4,%5,%6,%7},{%8,%9},{%0,%1,%2,%3};"          \
               : "+f"((c)[0]), "+f"((c)[1]), "+f"((c)[2]), "+f"((c)[3])      \
               : "r"((a)[0]), "r"((a)[1]), "r"((a)[2]), "r"((a)[3]),         \
                 "r"((b)[0]), "r"((b)[1]))

// ---------------- merged prep: weight pack + input init, one launch -------
__global__ void k_prep(const float* __restrict__ x,
                       const float* __restrict__ in_w,
                       const float* __restrict__ xd_w,
                       const float* __restrict__ xB_w,
                       const float* __restrict__ xC_w,
                       const float* __restrict__ dtp_w,
                       const float* __restrict__ out_w,
                       const float* __restrict__ merge_w){
  int i = blockIdx.x*256 + threadIdx.x;       // 950272 wprep + 524288 init
  if (i < 524288){                            // in_w: [blk][k=256][n=1024]
    int blk = i >> 17, r = i & 131071;
    int k2 = r >> 10, n = r & 1023;
    size_t base = (size_t)blk*262144 + (size_t)(2*k2)*1024 + n;
    g_win2[i] = h2pack(in_w[base], in_w[base + 1024]);
  } else if (i < 589824){                     // xd|xB|xC: [blk][k=512][n=64]
    int j = i - 524288;
    int blk = j >> 14, r = j & 16383;
    int k2 = r >> 6, n = r & 63;
    float v0, v1;
    if (n < 32){
      size_t b = (size_t)blk*16384 + (size_t)(2*k2)*32 + n;
      v0 = xd_w[b]; v1 = xd_w[b + 32];
    } else if (n < 48){
      size_t b = (size_t)blk*8192 + (size_t)(2*k2)*16 + (n-32);
      v0 = xB_w[b]; v1 = xB_w[b + 16];
    } else {
      size_t b = (size_t)blk*8192 + (size_t)(2*k2)*16 + (n-48);
      v0 = xC_w[b]; v1 = xC_w[b + 16];
    }
    g_xw2[j] = h2pack(v0, v1);
  } else if (i < 622592){                     // dtp_w: [blk][k=32][n=512]
    int j = i - 589824;
    int blk = j >> 13, r = j & 8191;
    int k2 = r >> 9, n = r & 511;
    size_t b = (size_t)blk*16384 + (size_t)(2*k2)*512 + n;
    g_dtw2[j] = h2pack(dtp_w[b], dtp_w[b + 512]);
  } else if (i < 884736){                     // out_w: [blk][k=512][n=256]
    int j = i - 622592;
    int blk = j >> 16, r = j & 65535;
    int k2 = r >> 8, n = r & 255;
    size_t b = (size_t)blk*131072 + (size_t)(2*k2)*256 + n;
    g_ow2[j] = h2pack(out_w[b], out_w[b + 256]);
  } else if (i < 950272){                     // merge_w: [k=512][n=256]
    int j = i - 884736;
    int k2 = j >> 8, n = j & 255;
    size_t b = (size_t)(2*k2)*256 + n;
    g_mw2[j] = h2pack(merge_w[b], merge_w[b + 256]);
  } else {                                    // init: fwd + reversed copies
    int idx = i - 950272;                     // M2*64 = 524288 float4s
    int col = idx & 63;
    int m   = idx >> 6;
    int half = m >> 12;
    int b = (m >> 11) & 1, s = m & (Ss-1);
    int ms = b*Ss + (half ? (Ss-1-s) : s);
    reinterpret_cast<float4*>(g_res)[m*64+col] =
        reinterpret_cast<const float4*>(x)[ms*64+col];
  }
}

// ======================================================================
// TC: 128x64 FP16 mma core (round-7 proven). 256 thr = 8 warps (4Mx2N).
// ======================================================================
#define TC_DECL()                                                     \
  __shared__ __align__(16) unsigned Af[2][1024];                      \
  __shared__ __align__(16) unsigned Bf[2][512];                       \
  const int t = threadIdx.x;                                          \
  const int lane = t & 31, wid = t >> 5;                              \
  const int wm = wid >> 1, wn = wid & 1;                              \
  const int s_r  = t >> 1;                                            \
  const int s_kb = (t & 1) * 8;                                       \
  const int s_bq = t >> 6;                                            \
  const int s_bn = t & 63;                                            \
  float acc[2][4][4] = {};                                            \
  float4 raA0, raA1; uint4 raH; unsigned rbx, rby;                    \
  (void)raA0; (void)raA1; (void)raH;

#define TC_AB(buf) &Af[buf][(((s_r>>4)*32 + ((s_r&7)*4))*4) + ((s_r>>3)&1) + ((s_kb>>2)&2)]

#define TC_STAGE_B(buf) {                                             \
  int ln0 = (s_bn & 7)*4 + ((2*s_bq) & 3);                            \
  int rgB = s_bq >> 1;                                                \
  unsigned* bb = &Bf[buf][((s_bn >> 3)*32 + ln0)*2 + rgB];            \
  bb[0] = rbx;                                                        \
  bb[2] = rby; }

#define TC_STAGE_F(buf) {                                             \
  unsigned* ab = TC_AB(buf);                                          \
  ab[0]  = h2pack(raA0.x, raA0.y);                                    \
  ab[4]  = h2pack(raA0.z, raA0.w);                                    \
  ab[8]  = h2pack(raA1.x, raA1.y);                                    \
  ab[12] = h2pack(raA1.z, raA1.w);                                    \
  TC_STAGE_B(buf) }

#define TC_STAGE_H(buf) {                                             \
  unsigned* ab = TC_AB(buf);                                          \
  ab[0]  = raH.x;                                                     \
  ab[4]  = raH.y;                                                     \
  ab[8]  = raH.z;                                                     \
  ab[12] = raH.w;                                                     \
  TC_STAGE_B(buf) }

#define TC_COMP(buf) {                                                \
  unsigned a_[2][4]; unsigned b_[4][2];                               \
  _Pragma("unroll") for (int mt=0;mt<2;mt++)                          \
    *(uint4*)a_[mt] = *(const uint4*)&Af[buf][((wm*2+mt)*32 + lane)*4]; \
  _Pragma("unroll") for (int nt=0;nt<4;nt++)                          \
    *(uint2*)b_[nt] = *(const uint2*)&Bf[buf][((wn*4+nt)*32 + lane)*2]; \
  _Pragma("unroll") for (int mt=0;mt<2;mt++)                          \
    _Pragma("unroll") for (int nt=0;nt<4;nt++)                        \
      MMA16(acc[mt][nt], a_[mt], b_[nt]); }

#define TC_BODY_GEN(KT, STG, CMP)                                     \
  LOADA(0); LOADB(0);                                                 \
  STG(0);                                                             \
  if (16 < (KT)) { LOADA(16); LOADB(16); }                            \
  __syncthreads();                                                    \
  { int cur = 0;                                                      \
    _Pragma("unroll 1")                                               \
    for (int k0=0; k0<(KT); k0+=16){                                  \
      if (k0+16 < (KT)) STG(cur^1);                                   \
      if (k0+32 < (KT)) { LOADA(k0+32); LOADB(k0+32); }               \
      CMP(cur);                                                       \
      __syncthreads();                                                \
      cur ^= 1;                                                       \
    } }

#define TC_BODY(KT)   TC_BODY_GEN(KT, TC_STAGE_F, TC_COMP)
#define TC_BODY_H(KT) TC_BODY_GEN(KT, TC_STAGE_H, TC_COMP)

// ======================================================================
// TC2: 128x128 FP16 mma core. Same 256 threads, warp tile 32x64:
// 16 mma per chunk per warp — 2x mma per barrier, B smem bytes/mma halved.
// B staging: thread t covers (n = t&127, k2-quad = (t>>7)*4) -> 4 LDG.32.
// ======================================================================
#define TC2_DECL()                                                    \
  __shared__ __align__(16) unsigned Af[2][1024];                      \
  __shared__ __align__(16) unsigned Bf[2][1024];                      \
  const int t = threadIdx.x;                                          \
  const int lane = t & 31, wid = t >> 5;                              \
  const int wm = wid >> 1, wn = wid & 1;                              \
  const int s_r  = t >> 1;                                            \
  const int s_kb = (t & 1) * 8;                                       \
  const int s_bn = t & 127;         /* B n 0..127        */           \
  const int s_bq = (t >> 7) * 4;    /* B k2 base 0 or 4  */           \
  const int b_base = (((s_bn>>3)*32 + (s_bn&7)*4))*2 + (s_bq>>2);     \
  float acc[2][8][4] = {};                                            \
  float4 raA0, raA1; uint4 raH;                                       \
  unsigned rb0, rb1, rb2, rb3;                                        \
  (void)raA0; (void)raA1; (void)raH;

#define TC2_STAGE_B(buf) {                                            \
  Bf[buf][b_base+0] = rb0;                                            \
  Bf[buf][b_base+2] = rb1;                                            \
  Bf[buf][b_base+4] = rb2;                                            \
  Bf[buf][b_base+6] = rb3; }

#define TC2_STAGE_F(buf) {                                            \
  unsigned* ab = TC_AB(buf);                                          \
  ab[0]  = h2pack(raA0.x, raA0.y);                                    \
  ab[4]  = h2pack(raA0.z, raA0.w);                                    \
  ab[8]  = h2pack(raA1.x, raA1.y);                                    \
  ab[12] = h2pack(raA1.z, raA1.w);                                    \
  TC2_STAGE_B(buf) }

#define TC2_STAGE_H(buf) {                                            \
  unsigned* ab = TC_AB(buf);                                          \
  ab[0]  = raH.x;                                                     \
  ab[4]  = raH.y;                                                     \
  ab[8]  = raH.z;                                                     \
  ab[12] = raH.w;                                                     \
  TC2_STAGE_B(buf) }

#define TC2_COMP(buf) {                                               \
  unsigned a_[2][4];                                                  \
  _Pragma("unroll") for (int mt=0;mt<2;mt++)                          \
    *(uint4*)a_[mt] = *(const uint4*)&Af[buf][((wm*2+mt)*32 + lane)*4]; \
  _Pragma("unroll") for (int j=0;j<8;j++){                            \
    unsigned b_[2];                                                   \
    *(uint2*)b_ = *(const uint2*)&Bf[buf][((wn*8+j)*32 + lane)*2];    \
    MMA16(acc[0][j], a_[0], b_);                                      \
    MMA16(acc[1][j], a_[1], b_);                                      \
  } }

#define TC2_BODY(KT)   TC_BODY_GEN(KT, TC2_STAGE_F, TC2_COMP)
#define TC2_BODY_H(KT) TC_BODY_GEN(KT, TC2_STAGE_H, TC2_COMP)

// in_proj with fused LayerNorm, 128-wide N tiles:
//   LN(g_res)[8192,256] @ in_w[256,1024] -> xs | z (half)
__global__ void k_gemm_in(int b0, int b1,
                          const float* __restrict__ g0, const float* __restrict__ bt0,
                          const float* __restrict__ g1, const float* __restrict__ bt1){
  int col0 = blockIdx.x*128, row0 = blockIdx.y*128;
  int half = row0 >> 12;
  const unsigned* W2 = g_win2 + (size_t)(half ? b1 : b0)*131072;
  const float* gm = half ? g1  : g0;
  const float* bb = half ? bt1 : bt0;
  __shared__ float sG[DMm], sBt[DMm];
  TC2_DECL();
  sG[t] = gm[t]; sBt[t] = bb[t];
  const float* rowp = g_res + (size_t)(row0 + s_r)*DMm;
  float sum = 0.f, sq = 0.f;
  #pragma unroll
  for (int j=0;j<16;j++){
    float4 v0 = *(const float4*)&rowp[j*16 + s_kb];
    float4 v1 = *(const float4*)&rowp[j*16 + s_kb + 4];
    sum += v0.x+v0.y+v0.z+v0.w + v1.x+v1.y+v1.z+v1.w;
    sq  += v0.x*v0.x+v0.y*v0.y+v0.z*v0.z+v0.w*v0.w
         + v1.x*v1.x+v1.y*v1.y+v1.z*v1.z+v1.w*v1.w;
  }
  sum += __shfl_xor_sync(~0u, sum, 1);
  sq  += __shfl_xor_sync(~0u, sq, 1);
  float mean = sum*(1.f/DMm);
  float rstd = rsqrtf(sq*(1.f/DMm) - mean*mean + 1e-5f);
  __syncthreads();   // sG/sBt visible
#define LOADA(k0_) { int kk_=(k0_)+s_kb;                                           \
    raA0 = *(const float4*)&rowp[kk_];                                             \
    raA1 = *(const float4*)&rowp[kk_+4];                                           \
    raA0.x=(raA0.x-mean)*rstd*sG[kk_+0]+sBt[kk_+0];                                \
    raA0.y=(raA0.y-mean)*rstd*sG[kk_+1]+sBt[kk_+1];                                \
    raA0.z=(raA0.z-mean)*rstd*sG[kk_+2]+sBt[kk_+2];                                \
    raA0.w=(raA0.w-mean)*rstd*sG[kk_+3]+sBt[kk_+3];                                \
    raA1.x=(raA1.x-mean)*rstd*sG[kk_+4]+sBt[kk_+4];                                \
    raA1.y=(raA1.y-mean)*rstd*sG[kk_+5]+sBt[kk_+5];                                \
    raA1.z=(raA1.z-mean)*rstd*sG[kk_+6]+sBt[kk_+6];                                \
    raA1.w=(raA1.w-mean)*rstd*sG[kk_+7]+sBt[kk_+7]; }
#define LOADB(k0_) { int k2_ = ((k0_) >> 1) + s_bq;                                \
                     rb0 = W2[(size_t)(k2_+0)*1024 + col0 + s_bn];                 \
                     rb1 = W2[(size_t)(k2_+1)*1024 + col0 + s_bn];                 \
                     rb2 = W2[(size_t)(k2_+2)*1024 + col0 + s_bn];                 \
                     rb3 = W2[(size_t)(k2_+3)*1024 + col0 + s_bn]; }
  TC2_BODY(DMm);
#undef LOADA
#undef LOADB
  __half* dst = (col0 < DIi) ? g_xs : g_z;
  int cb = (col0 < DIi) ? col0 : col0 - DIi;
  #pragma unroll
  for (int mt=0;mt<2;mt++)
    #pragma unroll
    for (int j=0;j<8;j++){
      int r = row0 + wm*32 + mt*16 + (lane>>2);
      int c = cb + wn*64 + j*8 + (lane&3)*2;
      *(unsigned*)&dst[(size_t)r*DIi + c]     = h2pack(acc[mt][j][0], acc[mt][j][1]);
      *(unsigned*)&dst[(size_t)(r+8)*DIi + c] = h2pack(acc[mt][j][2], acc[mt][j][3]);
    }
}

// x-proj split-K (64-wide core): xc @ [xd|xB|xC] -> projp[kz]
__global__ void k_gemm_x(int b0, int b1){
  int kz = blockIdx.x, row0 = blockIdx.y*128;
  int half = row0 >> 12;
  int kbase = kz*(DIi/KS);
  const unsigned* W2 = g_xw2 + (size_t)(half ? b1 : b0)*16384;
  TC_DECL();
#define LOADA(k0_) { raH = *(const uint4*)&g_xc[(size_t)(row0+s_r)*DIi + kbase+(k0_)+s_kb]; }
#define LOADB(k0_) { int k2_ = ((kbase+(k0_)) >> 1) + s_bq*2;                      \
                     rbx = W2[(size_t)(k2_+0)*64 + s_bn];                          \
                     rby = W2[(size_t)(k2_+1)*64 + s_bn]; }
  TC_BODY_H(DIi/KS);
#undef LOADA
#undef LOADB
  float* dst = g_projp + (size_t)kz*M2*64;
  #pragma unroll
  for (int mt=0;mt<2;mt++)
    #pragma unroll
    for (int nt=0;nt<4;nt++){
      int r = row0 + wm*32 + mt*16 + (lane>>2);
      int c = wn*32 + nt*8 + (lane&3)*2;
      *(float2*)&dst[(size_t)r*64 + c]     = make_float2(acc[mt][nt][0], acc[mt][nt][1]);
      *(float2*)&dst[(size_t)(r+8)*64 + c] = make_float2(acc[mt][nt][2], acc[mt][nt][3]);
    }
}

__global__ void k_xred(){
  int i = blockIdx.x*256 + threadIdx.x;   // M2*16 float4s
  float4 a = reinterpret_cast<const float4*>(g_projp)[i];
  float4 b = reinterpret_cast<const float4*>(g_projp + (size_t)M2*64)[i];
  float4 c = reinterpret_cast<const float4*>(g_projp + (size_t)2*M2*64)[i];
  float4 d = reinterpret_cast<const float4*>(g_projp + (size_t)3*M2*64)[i];
  float4 s = make_float4(a.x+b.x+c.x+d.x, a.y+b.y+c.y+d.y,
                         a.z+b.z+c.z+d.z, a.w+b.w+c.w+d.w);
  reinterpret_cast<float4*>(g_proj)[i] = s;
  h4store(&g_projh[i*4], s);
}

// delta: softplus(projh[:, :32] @ dtp_w[32,512] + dtp_b), 128-wide N tiles
__global__ void k_gemm_dt(int b0, int b1,
                          const float* __restrict__ bd0, const float* __restrict__ bd1){
  int col0 = blockIdx.x*128, row0 = blockIdx.y*128;
  int half = row0 >> 12;
  const unsigned* W2 = g_dtw2 + (size_t)(half ? b1 : b0)*8192;
  const float* bd = half ? bd1 : bd0;
  TC2_DECL();
#define LOADA(k0_) { raH = *(const uint4*)&g_projh[(size_t)(row0+s_r)*64 + (k0_)+s_kb]; }
#define LOADB(k0_) { int k2_ = ((k0_) >> 1) + s_bq;                                \
                     rb0 = W2[(size_t)(k2_+0)*512 + col0 + s_bn];                  \
                     rb1 = W2[(size_t)(k2_+1)*512 + col0 + s_bn];                  \
                     rb2 = W2[(size_t)(k2_+2)*512 + col0 + s_bn];                  \
                     rb3 = W2[(size_t)(k2_+3)*512 + col0 + s_bn]; }
  TC2_BODY_H(RR);
#undef LOADA
#undef LOADB
  #pragma unroll
  for (int mt=0;mt<2;mt++)
    #pragma unroll
    for (int j=0;j<8;j++){
      int r = row0 + wm*32 + mt*16 + (lane>>2);
      int c = col0 + wn*64 + j*8 + (lane&3)*2;
      float b0v = bd[c], b1v = bd[c+1];
      *(unsigned*)&g_delta[(size_t)r*DIi + c] =
          h2pack(spf(acc[mt][j][0]+b0v), spf(acc[mt][j][1]+b1v));
      *(unsigned*)&g_delta[(size_t)(r+8)*DIi + c] =
          h2pack(spf(acc[mt][j][2]+b0v), spf(acc[mt][j][3]+b1v));
    }
}

// out_proj (64-wide core): yg @ out_w + residual
__global__ void k_gemm_out(int b0, int b1){
  int col0 = blockIdx.x*64, row0 = blockIdx.y*128;
  int half = row0 >> 12;
  const unsigned* W2 = g_ow2 + (size_t)(half ? b1 : b0)*65536;
  TC_DECL();
#define LOADA(k0_) { raH = *(const uint4*)&g_yg[(size_t)(row0+s_r)*DIi + (k0_)+s_kb]; }
#define LOADB(k0_) { int k2_ = ((k0_) >> 1) + s_bq*2;                              \
                     rbx = W2[(size_t)(k2_+0)*256 + col0 + s_bn];                  \
                     rby = W2[(size_t)(k2_+1)*256 + col0 + s_bn]; }
  TC_BODY_H(DIi);
#undef LOADA
#undef LOADB
  #pragma unroll
  for (int mt=0;mt<2;mt++)
    #pragma unroll
    for (int nt=0;nt<4;nt++){
      int r = row0 + wm*32 + mt*16 + (lane>>2);
      int c = col0 + wn*32 + nt*8 + (lane&3)*2;
      float2 o0 = *(const float2*)&g_res[(size_t)r*DMm + c];
      float2 o1 = *(const float2*)&g_res[(size_t)(r+8)*DMm + c];
      *(float2*)&g_res[(size_t)r*DMm + c] =
          make_float2(acc[mt][nt][0]+o0.x, acc[mt][nt][1]+o0.y);
      *(float2*)&g_res[(size_t)(r+8)*DMm + c] =
          make_float2(acc[mt][nt][2]+o1.x, acc[mt][nt][3]+o1.y);
    }
}

// merge (64-wide core): concat(res0, res1_rev) @ merge_w -> out
__global__ void k_merge(float* __restrict__ out){
  int col0 = blockIdx.x*64, row0 = blockIdx.y*128;
  TC_DECL();
  int r_ = row0 + s_r;
  int b_ = r_ >> 11, s_ = r_ & (Ss-1);
  int rrev = MM + b_*Ss + (Ss-1-s_);
#define LOADA(k0_) {                                                               \
    int kk0 = (k0_)+s_kb, kk1 = (k0_)+s_kb+4;                                      \
    raA0 = *(const float4*)((kk0 < DMm) ? (g_res + (size_t)r_*DMm + kk0)           \
                                        : (g_res + (size_t)rrev*DMm + kk0-DMm));   \
    raA1 = *(const float4*)((kk1 < DMm) ? (g_res + (size_t)r_*DMm + kk1)           \
                                        : (g_res + (size_t)rrev*DMm + kk1-DMm)); }
#define LOADB(k0_) { int k2_ = ((k0_) >> 1) + s_bq*2;                              \
                     rbx = g_mw2[(size_t)(k2_+0)*256 + col0 + s_bn];               \
                     rby = g_mw2[(size_t)(k2_+1)*256 + col0 + s_bn]; }
  TC_BODY(2*DMm);
#undef LOADA
#undef LOADB
  #pragma unroll
  for (int mt=0;mt<2;mt++)
    #pragma unroll
    for (int nt=0;nt<4;nt++){
      int r = row0 + wm*32 + mt*16 + (lane>>2);
      int c = col0 + wn*32 + nt*8 + (lane&3)*2;
      *(float2*)&out[(size_t)r*DMm + c]     = make_float2(acc[mt][nt][0], acc[mt][nt][1]);
      *(float2*)&out[(size_t)(r+8)*DMm + c] = make_float2(acc[mt][nt][2], acc[mt][nt][3]);
    }
}

// ---------------- causal depthwise conv (K=4) + silu, half I/O ----------------
__global__ void k_conv(const float* __restrict__ cw0, const float* __restrict__ cb0,
                       const float* __restrict__ cw1, const float* __restrict__ cb1){
  int idx = blockIdx.x*256 + threadIdx.x;   // (M2/4)*128
  int d4 = idx & 127, g = idx >> 7;         // g in [0, M2/4)
  int b2 = g >> 9, sg = g & 511;            // seq 0..3, group within seq
  int half = b2 >> 1;
  const float* cw = half ? cw1 : cw0;
  const float* cb = half ? cb1 : cb0;
  int m0 = b2*Ss + sg*4;
  int d = d4*4;
  float4 w0 = *(const float4*)(cw + (d+0)*4);
  float4 w1 = *(const float4*)(cw + (d+1)*4);
  float4 w2 = *(const float4*)(cw + (d+2)*4);
  float4 w3 = *(const float4*)(cw + (d+3)*4);
  float4 bv = *(const float4*)(cb + d);
  float4 x0, x1, x2;
  if (sg > 0){
    x0 = h4load(&g_xs[(size_t)(m0-3)*DIi + d]);
    x1 = h4load(&g_xs[(size_t)(m0-2)*DIi + d]);
    x2 = h4load(&g_xs[(size_t)(m0-1)*DIi + d]);
  } else {
    x0 = x1 = x2 = make_float4(0.f,0.f,0.f,0.f);
  }
  #pragma unroll
  for (int s=0;s<4;s++){
    float4 x3 = h4load(&g_xs[(size_t)(m0+s)*DIi + d]);
    float4 a;
    a.x = bv.x + w0.x*x0.x + w0.y*x1.x + w0.z*x2.x + w0.w*x3.x;
    a.y = bv.y + w1.x*x0.y + w1.y*x1.y + w1.z*x2.y + w1.w*x3.y;
    a.z = bv.z + w2.x*x0.z + w2.y*x1.z + w2.z*x2.z + w2.w*x3.z;
    a.w = bv.w + w3.x*x0.w + w3.y*x1.w + w3.z*x2.w + w3.w*x3.w;
    a.x = siluf(a.x); a.y = siluf(a.y); a.z = siluf(a.z); a.w = siluf(a.w);
    h4store(&g_xc[(size_t)(m0+s)*DIi + d], a);
    x0 = x1; x1 = x2; x2 = x3;
  }
}

// dA helper: if A[n] == -(n+1) (the actual dataset), dA_n = r^(n+1) with
// r = exp(-delta): 1 MUFU + 15 FMUL instead of 16 MUFU.
__device__ __forceinline__ void dA_compute(float* dAv, const float* A,
                                           float dlt, bool fast){
  if (fast){
    float r = __expf(-dlt);
    dAv[0] = r; dAv[1] = r*r;
    #pragma unroll
    for (int n=2;n<NN;n++) dAv[n] = dAv[n>>1]*dAv[(n-1)>>1];
  } else {
    #pragma unroll
    for (int n=0;n<NN;n++) dAv[n] = __expf(dlt*A[n]);
  }
}

__device__ __forceinline__ bool a_fast(const float* A){
  bool f = true;
  #pragma unroll
  for (int n=0;n<NN;n++) f = f && (fabsf(A[n] + (float)(n+1)) < 1e-5f*(n+1));
  return f;
}

// ---------------- chunked scan phase 1 ----------------
__global__ void k_scan1(const float* __restrict__ Alog0, const float* __restrict__ Alog1){
  __shared__ float sB[CHUNK][NN];
  int blk = blockIdx.x;               // 2 * NSEQ*NCH = 512
  int bc_ = blk >> 1;                 // 0..255
  int seq = bc_ >> 6, c = bc_ & 63;
  int half = seq >> 1;
  const float* Alog = half ? Alog1 : Alog0;
  int d = (blk & 1)*256 + threadIdx.x;
  int m0 = seq*Ss + c*CHUNK;
  { int i0 = threadIdx.x, i1 = threadIdx.x + 256;
    sB[i0>>4][i0&15] = g_proj[(size_t)(m0+(i0>>4))*64 + 32 + (i0&15)];
    sB[i1>>4][i1&15] = g_proj[(size_t)(m0+(i1>>4))*64 + 32 + (i1&15)]; }
  float A[NN];
  #pragma unroll
  for (int n=0;n<NN;n++) A[n] = -__expf(Alog[d*NN + n]);
  bool fast = a_fast(A);
  __syncthreads();
  float h[NN];
  #pragma unroll
  for (int n=0;n<NN;n++) h[n] = 0.f;
  float sd = 0.f;
  #pragma unroll 1
  for (int s=0;s<CHUNK;s++){
    size_t m = m0 + s;
    float dlt = __half2float(g_delta[m*DIi + d]);
    float dx  = dlt * __half2float(g_xc[m*DIi + d]);
    sd += dlt;
    float dAv[NN];
    dA_compute(dAv, A, dlt, fast);
    #pragma unroll
    for (int n=0;n<NN;n++) h[n] = dAv[n]*h[n] + dx*sB[s][n];
  }
  size_t base = ((size_t)bc_*DIi + d)*NN;
  float Pv[NN];
  dA_compute(Pv, A, sd, fast);
  #pragma unroll
  for (int n=0;n<NN;n++){ g_Q[base+n]=h[n]; g_P[base+n]=Pv[n]; }
}

// ---------------- phase 2: combine across chunks ----------------
__global__ void k_comb(){
  int i = blockIdx.x*128 + threadIdx.x;     // NSEQ*DIi*NN = 32768
  int n = i & 15, d = (i >> 4) & (DIi-1), seq = i >> 13;
  float H = 0.f;
  for (int c=0;c<NCH;c++){
    size_t idx = (((size_t)(seq*NCH+c))*DIi + d)*NN + n;
    g_Hin[idx] = H;
    H = g_P[idx]*H + g_Q[idx];
  }
}

// ---------------- phase 3: replay + gated output ----------------
__global__ void k_scan2(const float* __restrict__ Alog0, const float* __restrict__ Alog1,
                        const float* __restrict__ Dp0, const float* __restrict__ Dp1){
  __shared__ float sB[CHUNK][NN];
  __shared__ float sC[CHUNK][NN];
  int blk = blockIdx.x;
  int bc_ = blk >> 1;
  int seq = bc_ >> 6, c = bc_ & 63;
  int half = seq >> 1;
  const float* Alog = half ? Alog1 : Alog0;
  const float* Dp   = half ? Dp1   : Dp0;
  int d = (blk & 1)*256 + threadIdx.x;
  int m0 = seq*Ss + c*CHUNK;
  { int i0 = threadIdx.x, i1 = threadIdx.x + 256;
    sB[i0>>4][i0&15] = g_proj[(size_t)(m0+(i0>>4))*64 + 32 + (i0&15)];
    sB[i1>>4][i1&15] = g_proj[(size_t)(m0+(i1>>4))*64 + 32 + (i1&15)];
    sC[i0>>4][i0&15] = g_proj[(size_t)(m0+(i0>>4))*64 + 48 + (i0&15)];
    sC[i1>>4][i1&15] = g_proj[(size_t)(m0+(i1>>4))*64 + 48 + (i1&15)]; }
  float A[NN];
  #pragma unroll
  for (int n=0;n<NN;n++) A[n] = -__expf(Alog[d*NN + n]);
  bool fast = a_fast(A);
  float h[NN];
  size_t base = ((size_t)bc_*DIi + d)*NN;
  #pragma unroll
  for (int n=0;n<NN;n++) h[n] = g_Hin[base+n];
  float Dv = Dp[d];
  __syncthreads();
  #pragma unroll 1
  for (int s=0;s<CHUNK;s++){
    size_t m = m0 + s;
    float dlt = __half2float(g_delta[m*DIi + d]);
    float x   = __half2float(g_xc[m*DIi + d]);
    float dx  = dlt * x;
    float dAv[NN];
    dA_compute(dAv, A, dlt, fast);
    float y = 0.f;
    #pragma unroll
    for (int n=0;n<NN;n++){
      h[n] = dAv[n]*h[n] + dx*sB[s][n];
      y += h[n]*sC[s][n];
    }
    y += Dv*x;
    float zv = __half2float(g_z[m*DIi + d]);
    g_yg[m*DIi + d] = __float2half(y * siluf(zv));
  }
}

// ---------------- driver ----------------
extern "C" void kernel_launch(void* const* d_in, const int* in_sizes, int n_in,
                              void* d_out, int out_size){
  const float* x      = (const float*)d_in[0];
  const float* in_w   = (const float*)d_in[1];
  const float* conv_w = (const float*)d_in[2];
  const float* conv_b = (const float*)d_in[3];
  const float* A_log  = (const float*)d_in[4];
  const float* xd_w   = (const float*)d_in[5];
  const float* xB_w   = (const float*)d_in[6];
  const float* xC_w   = (const float*)d_in[7];
  const float* dtp_w  = (const float*)d_in[8];
  const float* dtp_b  = (const float*)d_in[9];
  const float* Dp     = (const float*)d_in[10];
  const float* out_w  = (const float*)d_in[11];
  const float* ln_g   = (const float*)d_in[12];
  const float* ln_b   = (const float*)d_in[13];
  const float* merge_w= (const float*)d_in[14];
  float* out = (float*)d_out;

  k_prep<<<5760, 256>>>(x, in_w, xd_w, xB_w, xC_w, dtp_w, out_w, merge_w);
  for (int bi=0; bi<2; bi++){
    int b0 = bi, b1 = 2 + bi;
    k_gemm_in <<<dim3(8,64), 256>>>(b0, b1,
                                    ln_g + b0*DMm, ln_b + b0*DMm,
                                    ln_g + b1*DMm, ln_b + b1*DMm);
    k_conv    <<<(M2/4)*128/256, 256>>>(conv_w + b0*DIi*4, conv_b + b0*DIi,
                                        conv_w + b1*DIi*4, conv_b + b1*DIi);
    k_gemm_x  <<<dim3(KS,64), 256>>>(b0, b1);
    k_xred    <<<M2*16/256, 256>>>();
    k_gemm_dt <<<dim3(4,64), 256>>>(b0, b1, dtp_b + b0*DIi, dtp_b + b1*DIi);
    k_scan1   <<<2*NSEQ*NCH, 256>>>(A_log + b0*DIi*NN, A_log + b1*DIi*NN);
    k_comb    <<<256, 128>>>();
    k_scan2   <<<2*NSEQ*NCH, 256>>>(A_log + b0*DIi*NN, A_log + b1*DIi*NN,
                                    Dp + b0*DIi, Dp + b1*DIi);
    k_gemm_out<<<dim3(4,64), 256>>>(b0, b1);
  }
  k_merge<<<dim3(4,32), 256>>>(out);
}

// round 14
// speedup vs baseline: 1.1887x; 1.0208x over previous
#include <cuda_runtime.h>
#include <cuda_fp16.h>

// ---------------- problem constants ----------------
#define Bb   2
#define Ss   2048
#define DMm  256
#define DIi  512
#define NN   16
#define RR   32
#define MM   (Bb*Ss)          // 4096 rows per chain
#define M2   (2*MM)           // 8192 rows: [fwd | reversed]
#define CHUNK 32
#define NCH  (Ss/CHUNK)       // 64 chunks per sequence
#define NSEQ 4                // 4 sequences total (2 fwd + 2 rev)
#define KS   4                // split-K for x-proj

// ---------------- device scratch ----------------
__device__ float  g_res [M2*DMm];
__device__ __half g_xs  [M2*DIi];
__device__ __half g_z   [M2*DIi];
__device__ __half g_xc  [M2*DIi];
__device__ float  g_proj[M2*64];          // [xd(32) | B(16) | C(16)] fp32
__device__ __half g_projh[M2*64];         // half mirror for gemm_dt A-path
__device__ float  g_projp[KS*M2*64];      // split-K partials (fp32)
__device__ __half g_delta[M2*DIi];
__device__ __half g_yg  [M2*DIi];
__device__ float  g_P   [NSEQ*NCH*DIi*NN];
__device__ float  g_Q   [NSEQ*NCH*DIi*NN];
__device__ float  g_Hin [NSEQ*NCH*DIi*NN];

// k-pair-packed half2 weight mirrors: W2[k/2][n] = (W[k][n], W[k+1][n])
__device__ unsigned g_win2[4*128*1024];   // in_w:   [blk][k2=128][n=1024]
__device__ unsigned g_xw2 [4*256*64];     // xd|xB|xC: [blk][k2=256][n=64]
__device__ unsigned g_dtw2[4*16*512];     // dtp_w:  [blk][k2=16][n=512]
__device__ unsigned g_ow2 [4*256*256];    // out_w:  [blk][k2=256][n=256]
__device__ unsigned g_mw2 [256*256];      // merge_w:[k2=256][n=256]

__device__ __forceinline__ float siluf(float x){ return x / (1.f + __expf(-x)); }
__device__ __forceinline__ float spf(float a){ return (a > 20.f) ? a : log1pf(__expf(a)); }

__device__ __forceinline__ unsigned h2pack(float a, float b){
  __half2 h = __floats2half2_rn(a, b);
  return *reinterpret_cast<unsigned*>(&h);
}
__device__ __forceinline__ float4 h4load(const __half* p){
  uint2 u = *(const uint2*)p;
  float2 fa = __half22float2(*(__half2*)&u.x);
  float2 fb = __half22float2(*(__half2*)&u.y);
  return make_float4(fa.x, fa.y, fb.x, fb.y);
}
__device__ __forceinline__ void h4store(__half* p, float4 v){
  uint2 u; u.x = h2pack(v.x, v.y); u.y = h2pack(v.z, v.w);
  *(uint2*)p = u;
}

#define MMA16(c, a, b)                                                       \
  asm volatile("mma.sync.aligned.m16n8k16.row.col.f32.f16.f16.f32 "          \
               "{%0,%1,%2,%3},{%4,%5,%6,%7},{%8,%9},{%0,%1,%2,%3};"          \
               : "+f"((c)[0]), "+f"((c)[1]), "+f"((c)[2]), "+f"((c)[3])      \
               : "r"((a)[0]), "r"((a)[1]), "r"((a)[2]), "r"((a)[3]),         \
                 "r"((b)[0]), "r"((b)[1]))

// ---------------- merged prep: weight pack + input init, one launch -------
__global__ void k_prep(const float* __restrict__ x,
                       const float* __restrict__ in_w,
                       const float* __restrict__ xd_w,
                       const float* __restrict__ xB_w,
                       const float* __restrict__ xC_w,
                       const float* __restrict__ dtp_w,
                       const float* __restrict__ out_w,
                       const float* __restrict__ merge_w){
  int i = blockIdx.x*256 + threadIdx.x;       // 950272 wprep + 524288 init
  if (i < 524288){                            // in_w: [blk][k=256][n=1024]
    int blk = i >> 17, r = i & 131071;
    int k2 = r >> 10, n = r & 1023;
    size_t base = (size_t)blk*262144 + (size_t)(2*k2)*1024 + n;
    g_win2[i] = h2pack(in_w[base], in_w[base + 1024]);
  } else if (i < 589824){                     // xd|xB|xC: [blk][k=512][n=64]
    int j = i - 524288;
    int blk = j >> 14, r = j & 16383;
    int k2 = r >> 6, n = r & 63;
    float v0, v1;
    if (n < 32){
      size_t b = (size_t)blk*16384 + (size_t)(2*k2)*32 + n;
      v0 = xd_w[b]; v1 = xd_w[b + 32];
    } else if (n < 48){
      size_t b = (size_t)blk*8192 + (size_t)(2*k2)*16 + (n-32);
      v0 = xB_w[b]; v1 = xB_w[b + 16];
    } else {
      size_t b = (size_t)blk*8192 + (size_t)(2*k2)*16 + (n-48);
      v0 = xC_w[b]; v1 = xC_w[b + 16];
    }
    g_xw2[j] = h2pack(v0, v1);
  } else if (i < 622592){                     // dtp_w: [blk][k=32][n=512]
    int j = i - 589824;
    int blk = j >> 13, r = j & 8191;
    int k2 = r >> 9, n = r & 511;
    size_t b = (size_t)blk*16384 + (size_t)(2*k2)*512 + n;
    g_dtw2[j] = h2pack(dtp_w[b], dtp_w[b + 512]);
  } else if (i < 884736){                     // out_w: [blk][k=512][n=256]
    int j = i - 622592;
    int blk = j >> 16, r = j & 65535;
    int k2 = r >> 8, n = r & 255;
    size_t b = (size_t)blk*131072 + (size_t)(2*k2)*256 + n;
    g_ow2[j] = h2pack(out_w[b], out_w[b + 256]);
  } else if (i < 950272){                     // merge_w: [k=512][n=256]
    int j = i - 884736;
    int k2 = j >> 8, n = j & 255;
    size_t b = (size_t)(2*k2)*256 + n;
    g_mw2[j] = h2pack(merge_w[b], merge_w[b + 256]);
  } else {                                    // init: fwd + reversed copies
    int idx = i - 950272;                     // M2*64 = 524288 float4s
    int col = idx & 63;
    int m   = idx >> 6;
    int half = m >> 12;
    int b = (m >> 11) & 1, s = m & (Ss-1);
    int ms = b*Ss + (half ? (Ss-1-s) : s);
    reinterpret_cast<float4*>(g_res)[m*64+col] =
        reinterpret_cast<const float4*>(x)[ms*64+col];
  }
}

// ======================================================================
// TC: 128x64 FP16 mma core (round-7 proven). 256 thr = 8 warps (4Mx2N).
// ======================================================================
#define TC_DECL()                                                     \
  __shared__ __align__(16) unsigned Af[2][1024];                      \
  __shared__ __align__(16) unsigned Bf[2][512];                       \
  const int t = threadIdx.x;                                          \
  const int lane = t & 31, wid = t >> 5;                              \
  const int wm = wid >> 1, wn = wid & 1;                              \
  const int s_r  = t >> 1;                                            \
  const int s_kb = (t & 1) * 8;                                       \
  const int s_bq = t >> 6;                                            \
  const int s_bn = t & 63;                                            \
  float acc[2][4][4] = {};                                            \
  float4 raA0, raA1; uint4 raH; unsigned rbx, rby;                    \
  (void)raA0; (void)raA1; (void)raH;

#define TC_AB(buf) &Af[buf][(((s_r>>4)*32 + ((s_r&7)*4))*4) + ((s_r>>3)&1) + ((s_kb>>2)&2)]

#define TC_STAGE_B(buf) {                                             \
  int ln0 = (s_bn & 7)*4 + ((2*s_bq) & 3);                            \
  int rgB = s_bq >> 1;                                                \
  unsigned* bb = &Bf[buf][((s_bn >> 3)*32 + ln0)*2 + rgB];            \
  bb[0] = rbx;                                                        \
  bb[2] = rby; }

#define TC_STAGE_F(buf) {                                             \
  unsigned* ab = TC_AB(buf);                                          \
  ab[0]  = h2pack(raA0.x, raA0.y);                                    \
  ab[4]  = h2pack(raA0.z, raA0.w);                                    \
  ab[8]  = h2pack(raA1.x, raA1.y);                                    \
  ab[12] = h2pack(raA1.z, raA1.w);                                    \
  TC_STAGE_B(buf) }

#define TC_STAGE_H(buf) {                                             \
  unsigned* ab = TC_AB(buf);                                          \
  ab[0]  = raH.x;                                                     \
  ab[4]  = raH.y;                                                     \
  ab[8]  = raH.z;                                                     \
  ab[12] = raH.w;                                                     \
  TC_STAGE_B(buf) }

#define TC_COMP(buf) {                                                \
  unsigned a_[2][4]; unsigned b_[4][2];                               \
  _Pragma("unroll") for (int mt=0;mt<2;mt++)                          \
    *(uint4*)a_[mt] = *(const uint4*)&Af[buf][((wm*2+mt)*32 + lane)*4]; \
  _Pragma("unroll") for (int nt=0;nt<4;nt++)                          \
    *(uint2*)b_[nt] = *(const uint2*)&Bf[buf][((wn*4+nt)*32 + lane)*2]; \
  _Pragma("unroll") for (int mt=0;mt<2;mt++)                          \
    _Pragma("unroll") for (int nt=0;nt<4;nt++)                        \
      MMA16(acc[mt][nt], a_[mt], b_[nt]); }

#define TC_BODY_GEN(KT, STG, CMP)                                     \
  LOADA(0); LOADB(0);                                                 \
  STG(0);                                                             \
  if (16 < (KT)) { LOADA(16); LOADB(16); }                            \
  __syncthreads();                                                    \
  { int cur = 0;                                                      \
    _Pragma("unroll 1")                                               \
    for (int k0=0; k0<(KT); k0+=16){                                  \
      if (k0+16 < (KT)) STG(cur^1);                                   \
      if (k0+32 < (KT)) { LOADA(k0+32); LOADB(k0+32); }               \
      CMP(cur);                                                       \
      __syncthreads();                                                \
      cur ^= 1;                                                       \
    } }

#define TC_BODY(KT)   TC_BODY_GEN(KT, TC_STAGE_F, TC_COMP)
#define TC_BODY_H(KT) TC_BODY_GEN(KT, TC_STAGE_H, TC_COMP)

// ======================================================================
// TC2: 128x128 FP16 mma core. 256 threads, warp tile 32x64 (16 mma/chunk).
// ======================================================================
#define TC2_DECL()                                                    \
  __shared__ __align__(16) unsigned Af[2][1024];                      \
  __shared__ __align__(16) unsigned Bf[2][1024];                      \
  const int t = threadIdx.x;                                          \
  const int lane = t & 31, wid = t >> 5;                              \
  const int wm = wid >> 1, wn = wid & 1;                              \
  const int s_r  = t >> 1;                                            \
  const int s_kb = (t & 1) * 8;                                       \
  const int s_bn = t & 127;         /* B n 0..127        */           \
  const int s_bq = (t >> 7) * 4;    /* B k2 base 0 or 4  */           \
  const int b_base = (((s_bn>>3)*32 + (s_bn&7)*4))*2 + (s_bq>>2);     \
  float acc[2][8][4] = {};                                            \
  float4 raA0, raA1; uint4 raH;                                       \
  unsigned rb0, rb1, rb2, rb3;                                        \
  (void)raA0; (void)raA1; (void)raH;

#define TC2_STAGE_B(buf) {                                            \
  Bf[buf][b_base+0] = rb0;                                            \
  Bf[buf][b_base+2] = rb1;                                            \
  Bf[buf][b_base+4] = rb2;                                            \
  Bf[buf][b_base+6] = rb3; }

#define TC2_STAGE_F(buf) {                                            \
  unsigned* ab = TC_AB(buf);                                          \
  ab[0]  = h2pack(raA0.x, raA0.y);                                    \
  ab[4]  = h2pack(raA0.z, raA0.w);                                    \
  ab[8]  = h2pack(raA1.x, raA1.y);                                    \
  ab[12] = h2pack(raA1.z, raA1.w);                                    \
  TC2_STAGE_B(buf) }

#define TC2_STAGE_H(buf) {                                            \
  unsigned* ab = TC_AB(buf);                                          \
  ab[0]  = raH.x;                                                     \
  ab[4]  = raH.y;                                                     \
  ab[8]  = raH.z;                                                     \
  ab[12] = raH.w;                                                     \
  TC2_STAGE_B(buf) }

#define TC2_COMP(buf) {                                               \
  unsigned a_[2][4];                                                  \
  _Pragma("unroll") for (int mt=0;mt<2;mt++)                          \
    *(uint4*)a_[mt] = *(const uint4*)&Af[buf][((wm*2+mt)*32 + lane)*4]; \
  _Pragma("unroll") for (int j=0;j<8;j++){                            \
    unsigned b_[2];                                                   \
    *(uint2*)b_ = *(const uint2*)&Bf[buf][((wn*8+j)*32 + lane)*2];    \
    MMA16(acc[0][j], a_[0], b_);                                      \
    MMA16(acc[1][j], a_[1], b_);                                      \
  } }

#define TC2_BODY(KT)   TC_BODY_GEN(KT, TC2_STAGE_F, TC2_COMP)
#define TC2_BODY_H(KT) TC_BODY_GEN(KT, TC2_STAGE_H, TC2_COMP)

// ======================================================================
// TC3: 256x64 "tall" FP16 mma core. 256 threads, warp tile 64x32
// (16 mma/chunk). One thread stages one full A row (2 LDG.128 of halves).
// A smem padded to 33-lane stride per m-tile to cap STS conflicts at 4-way.
// ======================================================================
#define TC3_DECL()                                                    \
  __shared__ __align__(16) unsigned Af[2][2112];                      \
  __shared__ __align__(16) unsigned Bf[2][512];                       \
  const int t = threadIdx.x;                                          \
  const int lane = t & 31, wid = t >> 5;                              \
  const int wm = wid >> 1, wn = wid & 1;                              \
  const int s_bq = t >> 6;                                            \
  const int s_bn = t & 63;                                            \
  const int aoff3 = ((t>>4)*33 + (t&7)*4)*4 + ((t>>3)&1);             \
  float acc[4][4][4] = {};                                            \
  uint4 raH0, raH1; unsigned rbx, rby;

#define TC3_STAGE_H(buf) {                                            \
  unsigned* ab = &Af[buf][aoff3];                                     \
  ab[0]  = raH0.x;                                                    \
  ab[4]  = raH0.y;                                                    \
  ab[8]  = raH0.z;                                                    \
  ab[12] = raH0.w;                                                    \
  ab[2]  = raH1.x;                                                    \
  ab[6]  = raH1.y;                                                    \
  ab[10] = raH1.z;                                                    \
  ab[14] = raH1.w;                                                    \
  TC_STAGE_B(buf) }

#define TC3_COMP(buf) {                                               \
  unsigned a_[4][4]; unsigned b_[4][2];                               \
  _Pragma("unroll") for (int mt=0;mt<4;mt++)                          \
    *(uint4*)a_[mt] = *(const uint4*)&Af[buf][((wm*4+mt)*33 + lane)*4]; \
  _Pragma("unroll") for (int nt=0;nt<4;nt++)                          \
    *(uint2*)b_[nt] = *(const uint2*)&Bf[buf][((wn*4+nt)*32 + lane)*2]; \
  _Pragma("unroll") for (int mt=0;mt<4;mt++)                          \
    _Pragma("unroll") for (int nt=0;nt<4;nt++)                        \
      MMA16(acc[mt][nt], a_[mt], b_[nt]); }

#define TC3_BODY_H(KT) TC_BODY_GEN(KT, TC3_STAGE_H, TC3_COMP)

// in_proj with fused LayerNorm, 128-wide N tiles (TC2)
__global__ void k_gemm_in(int b0, int b1,
                          const float* __restrict__ g0, const float* __restrict__ bt0,
                          const float* __restrict__ g1, const float* __restrict__ bt1){
  int col0 = blockIdx.x*128, row0 = blockIdx.y*128;
  int half = row0 >> 12;
  const unsigned* W2 = g_win2 + (size_t)(half ? b1 : b0)*131072;
  const float* gm = half ? g1  : g0;
  const float* bb = half ? bt1 : bt0;
  __shared__ float sG[DMm], sBt[DMm];
  TC2_DECL();
  sG[t] = gm[t]; sBt[t] = bb[t];
  const float* rowp = g_res + (size_t)(row0 + s_r)*DMm;
  float sum = 0.f, sq = 0.f;
  #pragma unroll
  for (int j=0;j<16;j++){
    float4 v0 = *(const float4*)&rowp[j*16 + s_kb];
    float4 v1 = *(const float4*)&rowp[j*16 + s_kb + 4];
    sum += v0.x+v0.y+v0.z+v0.w + v1.x+v1.y+v1.z+v1.w;
    sq  += v0.x*v0.x+v0.y*v0.y+v0.z*v0.z+v0.w*v0.w
         + v1.x*v1.x+v1.y*v1.y+v1.z*v1.z+v1.w*v1.w;
  }
  sum += __shfl_xor_sync(~0u, sum, 1);
  sq  += __shfl_xor_sync(~0u, sq, 1);
  float mean = sum*(1.f/DMm);
  float rstd = rsqrtf(sq*(1.f/DMm) - mean*mean + 1e-5f);
  __syncthreads();   // sG/sBt visible
#define LOADA(k0_) { int kk_=(k0_)+s_kb;                                           \
    raA0 = *(const float4*)&rowp[kk_];                                             \
    raA1 = *(const float4*)&rowp[kk_+4];                                           \
    raA0.x=(raA0.x-mean)*rstd*sG[kk_+0]+sBt[kk_+0];                                \
    raA0.y=(raA0.y-mean)*rstd*sG[kk_+1]+sBt[kk_+1];                                \
    raA0.z=(raA0.z-mean)*rstd*sG[kk_+2]+sBt[kk_+2];                                \
    raA0.w=(raA0.w-mean)*rstd*sG[kk_+3]+sBt[kk_+3];                                \
    raA1.x=(raA1.x-mean)*rstd*sG[kk_+4]+sBt[kk_+4];                                \
    raA1.y=(raA1.y-mean)*rstd*sG[kk_+5]+sBt[kk_+5];                                \
    raA1.z=(raA1.z-mean)*rstd*sG[kk_+6]+sBt[kk_+6];                                \
    raA1.w=(raA1.w-mean)*rstd*sG[kk_+7]+sBt[kk_+7]; }
#define LOADB(k0_) { int k2_ = ((k0_) >> 1) + s_bq;                                \
                     rb0 = W2[(size_t)(k2_+0)*1024 + col0 + s_bn];                 \
                     rb1 = W2[(size_t)(k2_+1)*1024 + col0 + s_bn];                 \
                     rb2 = W2[(size_t)(k2_+2)*1024 + col0 + s_bn];                 \
                     rb3 = W2[(size_t)(k2_+3)*1024 + col0 + s_bn]; }
  TC2_BODY(DMm);
#undef LOADA
#undef LOADB
  __half* dst = (col0 < DIi) ? g_xs : g_z;
  int cb = (col0 < DIi) ? col0 : col0 - DIi;
  #pragma unroll
  for (int mt=0;mt<2;mt++)
    #pragma unroll
    for (int j=0;j<8;j++){
      int r = row0 + wm*32 + mt*16 + (lane>>2);
      int c = cb + wn*64 + j*8 + (lane&3)*2;
      *(unsigned*)&dst[(size_t)r*DIi + c]     = h2pack(acc[mt][j][0], acc[mt][j][1]);
      *(unsigned*)&dst[(size_t)(r+8)*DIi + c] = h2pack(acc[mt][j][2], acc[mt][j][3]);
    }
}

// x-proj split-K, tall 256x64 tiles (TC3): xc @ [xd|xB|xC] -> projp[kz]
__global__ void k_gemm_x(int b0, int b1){
  int kz = blockIdx.x, row0 = blockIdx.y*256;
  int half = row0 >> 12;
  int kbase = kz*(DIi/KS);
  const unsigned* W2 = g_xw2 + (size_t)(half ? b1 : b0)*16384;
  TC3_DECL();
#define LOADA(k0_) { const __half* ap = &g_xc[(size_t)(row0+t)*DIi + kbase+(k0_)];  \
                     raH0 = *(const uint4*)ap; raH1 = *(const uint4*)(ap+8); }
#define LOADB(k0_) { int k2_ = ((kbase+(k0_)) >> 1) + s_bq*2;                      \
                     rbx = W2[(size_t)(k2_+0)*64 + s_bn];                          \
                     rby = W2[(size_t)(k2_+1)*64 + s_bn]; }
  TC3_BODY_H(DIi/KS);
#undef LOADA
#undef LOADB
  float* dst = g_projp + (size_t)kz*M2*64;
  #pragma unroll
  for (int mt=0;mt<4;mt++)
    #pragma unroll
    for (int nt=0;nt<4;nt++){
      int r = row0 + wm*64 + mt*16 + (lane>>2);
      int c = wn*32 + nt*8 + (lane&3)*2;
      *(float2*)&dst[(size_t)r*64 + c]     = make_float2(acc[mt][nt][0], acc[mt][nt][1]);
      *(float2*)&dst[(size_t)(r+8)*64 + c] = make_float2(acc[mt][nt][2], acc[mt][nt][3]);
    }
}

__global__ void k_xred(){
  int i = blockIdx.x*256 + threadIdx.x;   // M2*16 float4s
  float4 a = reinterpret_cast<const float4*>(g_projp)[i];
  float4 b = reinterpret_cast<const float4*>(g_projp + (size_t)M2*64)[i];
  float4 c = reinterpret_cast<const float4*>(g_projp + (size_t)2*M2*64)[i];
  float4 d = reinterpret_cast<const float4*>(g_projp + (size_t)3*M2*64)[i];
  float4 s = make_float4(a.x+b.x+c.x+d.x, a.y+b.y+c.y+d.y,
                         a.z+b.z+c.z+d.z, a.w+b.w+c.w+d.w);
  reinterpret_cast<float4*>(g_proj)[i] = s;
  h4store(&g_projh[i*4], s);
}

// delta: softplus(projh[:, :32] @ dtp_w[32,512] + dtp_b), 128-wide N (TC2)
__global__ void k_gemm_dt(int b0, int b1,
                          const float* __restrict__ bd0, const float* __restrict__ bd1){
  int col0 = blockIdx.x*128, row0 = blockIdx.y*128;
  int half = row0 >> 12;
  const unsigned* W2 = g_dtw2 + (size_t)(half ? b1 : b0)*8192;
  const float* bd = half ? bd1 : bd0;
  TC2_DECL();
#define LOADA(k0_) { raH = *(const uint4*)&g_projh[(size_t)(row0+s_r)*64 + (k0_)+s_kb]; }
#define LOADB(k0_) { int k2_ = ((k0_) >> 1) + s_bq;                                \
                     rb0 = W2[(size_t)(k2_+0)*512 + col0 + s_bn];                  \
                     rb1 = W2[(size_t)(k2_+1)*512 + col0 + s_bn];                  \
                     rb2 = W2[(size_t)(k2_+2)*512 + col0 + s_bn];                  \
                     rb3 = W2[(size_t)(k2_+3)*512 + col0 + s_bn]; }
  TC2_BODY_H(RR);
#undef LOADA
#undef LOADB
  #pragma unroll
  for (int mt=0;mt<2;mt++)
    #pragma unroll
    for (int j=0;j<8;j++){
      int r = row0 + wm*32 + mt*16 + (lane>>2);
      int c = col0 + wn*64 + j*8 + (lane&3)*2;
      float b0v = bd[c], b1v = bd[c+1];
      *(unsigned*)&g_delta[(size_t)r*DIi + c] =
          h2pack(spf(acc[mt][j][0]+b0v), spf(acc[mt][j][1]+b1v));
      *(unsigned*)&g_delta[(size_t)(r+8)*DIi + c] =
          h2pack(spf(acc[mt][j][2]+b0v), spf(acc[mt][j][3]+b1v));
    }
}

// out_proj, 128-wide N tiles (TC2): yg @ out_w + residual (in place on g_res)
__global__ void k_gemm_out(int b0, int b1){
  int col0 = blockIdx.x*128, row0 = blockIdx.y*128;
  int half = row0 >> 12;
  const unsigned* W2 = g_ow2 + (size_t)(half ? b1 : b0)*65536;
  TC2_DECL();
#define LOADA(k0_) { raH = *(const uint4*)&g_yg[(size_t)(row0+s_r)*DIi + (k0_)+s_kb]; }
#define LOADB(k0_) { int k2_ = ((k0_) >> 1) + s_bq;                                \
                     rb0 = W2[(size_t)(k2_+0)*256 + col0 + s_bn];                  \
                     rb1 = W2[(size_t)(k2_+1)*256 + col0 + s_bn];                  \
                     rb2 = W2[(size_t)(k2_+2)*256 + col0 + s_bn];                  \
                     rb3 = W2[(size_t)(k2_+3)*256 + col0 + s_bn]; }
  TC2_BODY_H(DIi);
#undef LOADA
#undef LOADB
  #pragma unroll
  for (int mt=0;mt<2;mt++)
    #pragma unroll
    for (int j=0;j<8;j++){
      int r = row0 + wm*32 + mt*16 + (lane>>2);
      int c = col0 + wn*64 + j*8 + (lane&3)*2;
      float2 o0 = *(const float2*)&g_res[(size_t)r*DMm + c];
      float2 o1 = *(const float2*)&g_res[(size_t)(r+8)*DMm + c];
      *(float2*)&g_res[(size_t)r*DMm + c] =
          make_float2(acc[mt][j][0]+o0.x, acc[mt][j][1]+o0.y);
      *(float2*)&g_res[(size_t)(r+8)*DMm + c] =
          make_float2(acc[mt][j][2]+o1.x, acc[mt][j][3]+o1.y);
    }
}

// merge (64-wide core): concat(res0, res1_rev) @ merge_w -> out
__global__ void k_merge(float* __restrict__ out){
  int col0 = blockIdx.x*64, row0 = blockIdx.y*128;
  TC_DECL();
  int r_ = row0 + s_r;
  int b_ = r_ >> 11, s_ = r_ & (Ss-1);
  int rrev = MM + b_*Ss + (Ss-1-s_);
#define LOADA(k0_) {                                                               \
    int kk0 = (k0_)+s_kb, kk1 = (k0_)+s_kb+4;                                      \
    raA0 = *(const float4*)((kk0 < DMm) ? (g_res + (size_t)r_*DMm + kk0)           \
                                        : (g_res + (size_t)rrev*DMm + kk0-DMm));   \
    raA1 = *(const float4*)((kk1 < DMm) ? (g_res + (size_t)r_*DMm + kk1)           \
                                        : (g_res + (size_t)rrev*DMm + kk1-DMm)); }
#define LOADB(k0_) { int k2_ = ((k0_) >> 1) + s_bq*2;                              \
                     rbx = g_mw2[(size_t)(k2_+0)*256 + col0 + s_bn];               \
                     rby = g_mw2[(size_t)(k2_+1)*256 + col0 + s_bn]; }
  TC_BODY(2*DMm);
#undef LOADA
#undef LOADB
  #pragma unroll
  for (int mt=0;mt<2;mt++)
    #pragma unroll
    for (int nt=0;nt<4;nt++){
      int r = row0 + wm*32 + mt*16 + (lane>>2);
      int c = col0 + wn*32 + nt*8 + (lane&3)*2;
      *(float2*)&out[(size_t)r*DMm + c]     = make_float2(acc[mt][nt][0], acc[mt][nt][1]);
      *(float2*)&out[(size_t)(r+8)*DMm + c] = make_float2(acc[mt][nt][2], acc[mt][nt][3]);
    }
}

// ---------------- causal depthwise conv (K=4) + silu, half I/O ----------------
__global__ void k_conv(const float* __restrict__ cw0, const float* __restrict__ cb0,
                       const float* __restrict__ cw1, const float* __restrict__ cb1){
  int idx = blockIdx.x*256 + threadIdx.x;   // (M2/4)*128
  int d4 = idx & 127, g = idx >> 7;         // g in [0, M2/4)
  int b2 = g >> 9, sg = g & 511;            // seq 0..3, group within seq
  int half = b2 >> 1;
  const float* cw = half ? cw1 : cw0;
  const float* cb = half ? cb1 : cb0;
  int m0 = b2*Ss + sg*4;
  int d = d4*4;
  float4 w0 = *(const float4*)(cw + (d+0)*4);
  float4 w1 = *(const float4*)(cw + (d+1)*4);
  float4 w2 = *(const float4*)(cw + (d+2)*4);
  float4 w3 = *(const float4*)(cw + (d+3)*4);
  float4 bv = *(const float4*)(cb + d);
  float4 x0, x1, x2;
  if (sg > 0){
    x0 = h4load(&g_xs[(size_t)(m0-3)*DIi + d]);
    x1 = h4load(&g_xs[(size_t)(m0-2)*DIi + d]);
    x2 = h4load(&g_xs[(size_t)(m0-1)*DIi + d]);
  } else {
    x0 = x1 = x2 = make_float4(0.f,0.f,0.f,0.f);
  }
  #pragma unroll
  for (int s=0;s<4;s++){
    float4 x3 = h4load(&g_xs[(size_t)(m0+s)*DIi + d]);
    float4 a;
    a.x = bv.x + w0.x*x0.x + w0.y*x1.x + w0.z*x2.x + w0.w*x3.x;
    a.y = bv.y + w1.x*x0.y + w1.y*x1.y + w1.z*x2.y + w1.w*x3.y;
    a.z = bv.z + w2.x*x0.z + w2.y*x1.z + w2.z*x2.z + w2.w*x3.z;
    a.w = bv.w + w3.x*x0.w + w3.y*x1.w + w3.z*x2.w + w3.w*x3.w;
    a.x = siluf(a.x); a.y = siluf(a.y); a.z = siluf(a.z); a.w = siluf(a.w);
    h4store(&g_xc[(size_t)(m0+s)*DIi + d], a);
    x0 = x1; x1 = x2; x2 = x3;
  }
}

// dA helper: if A[n] == -(n+1) (the actual dataset), dA_n = r^(n+1) with
// r = exp(-delta): 1 MUFU + 15 FMUL instead of 16 MUFU.
__device__ __forceinline__ void dA_compute(float* dAv, const float* A,
                                           float dlt, bool fast){
  if (fast){
    float r = __expf(-dlt);
    dAv[0] = r; dAv[1] = r*r;
    #pragma unroll
    for (int n=2;n<NN;n++) dAv[n] = dAv[n>>1]*dAv[(n-1)>>1];
  } else {
    #pragma unroll
    for (int n=0;n<NN;n++) dAv[n] = __expf(dlt*A[n]);
  }
}

__device__ __forceinline__ bool a_fast(const float* A){
  bool f = true;
  #pragma unroll
  for (int n=0;n<NN;n++) f = f && (fabsf(A[n] + (float)(n+1)) < 1e-5f*(n+1));
  return f;
}

// ---------------- chunked scan phase 1 ----------------
__global__ void k_scan1(const float* __restrict__ Alog0, const float* __restrict__ Alog1){
  __shared__ float sB[CHUNK][NN];
  int blk = blockIdx.x;               // 2 * NSEQ*NCH = 512
  int bc_ = blk >> 1;                 // 0..255
  int seq = bc_ >> 6, c = bc_ & 63;
  int half = seq >> 1;
  const float* Alog = half ? Alog1 : Alog0;
  int d = (blk & 1)*256 + threadIdx.x;
  int m0 = seq*Ss + c*CHUNK;
  { int i0 = threadIdx.x, i1 = threadIdx.x + 256;
    sB[i0>>4][i0&15] = g_proj[(size_t)(m0+(i0>>4))*64 + 32 + (i0&15)];
    sB[i1>>4][i1&15] = g_proj[(size_t)(m0+(i1>>4))*64 + 32 + (i1&15)]; }
  float A[NN];
  #pragma unroll
  for (int n=0;n<NN;n++) A[n] = -__expf(Alog[d*NN + n]);
  bool fast = a_fast(A);
  __syncthreads();
  float h[NN];
  #pragma unroll
  for (int n=0;n<NN;n++) h[n] = 0.f;
  float sd = 0.f;
  #pragma unroll 1
  for (int s=0;s<CHUNK;s++){
    size_t m = m0 + s;
    float dlt = __half2float(g_delta[m*DIi + d]);
    float dx  = dlt * __half2float(g_xc[m*DIi + d]);
    sd += dlt;
    float dAv[NN];
    dA_compute(dAv, A, dlt, fast);
    #pragma unroll
    for (int n=0;n<NN;n++) h[n] = dAv[n]*h[n] + dx*sB[s][n];
  }
  size_t base = ((size_t)bc_*DIi + d)*NN;
  float Pv[NN];
  dA_compute(Pv, A, sd, fast);
  #pragma unroll
  for (int n=0;n<NN;n++){ g_Q[base+n]=h[n]; g_P[base+n]=Pv[n]; }
}

// ---------------- phase 2: combine across chunks ----------------
__global__ void k_comb(){
  int i = blockIdx.x*128 + threadIdx.x;     // NSEQ*DIi*NN = 32768
  int n = i & 15, d = (i >> 4) & (DIi-1), seq = i >> 13;
  float H = 0.f;
  for (int c=0;c<NCH;c++){
    size_t idx = (((size_t)(seq*NCH+c))*DIi + d)*NN + n;
    g_Hin[idx] = H;
    H = g_P[idx]*H + g_Q[idx];
  }
}

// ---------------- phase 3: replay + gated output ----------------
__global__ void k_scan2(const float* __restrict__ Alog0, const float* __restrict__ Alog1,
                        const float* __restrict__ Dp0, const float* __restrict__ Dp1){
  __shared__ float sB[CHUNK][NN];
  __shared__ float sC[CHUNK][NN];
  int blk = blockIdx.x;
  int bc_ = blk >> 1;
  int seq = bc_ >> 6, c = bc_ & 63;
  int half = seq >> 1;
  const float* Alog = half ? Alog1 : Alog0;
  const float* Dp   = half ? Dp1   : Dp0;
  int d = (blk & 1)*256 + threadIdx.x;
  int m0 = seq*Ss + c*CHUNK;
  { int i0 = threadIdx.x, i1 = threadIdx.x + 256;
    sB[i0>>4][i0&15] = g_proj[(size_t)(m0+(i0>>4))*64 + 32 + (i0&15)];
    sB[i1>>4][i1&15] = g_proj[(size_t)(m0+(i1>>4))*64 + 32 + (i1&15)];
    sC[i0>>4][i0&15] = g_proj[(size_t)(m0+(i0>>4))*64 + 48 + (i0&15)];
    sC[i1>>4][i1&15] = g_proj[(size_t)(m0+(i1>>4))*64 + 48 + (i1&15)]; }
  float A[NN];
  #pragma unroll
  for (int n=0;n<NN;n++) A[n] = -__expf(Alog[d*NN + n]);
  bool fast = a_fast(A);
  float h[NN];
  size_t base = ((size_t)bc_*DIi + d)*NN;
  #pragma unroll
  for (int n=0;n<NN;n++) h[n] = g_Hin[base+n];
  float Dv = Dp[d];
  __syncthreads();
  #pragma unroll 1
  for (int s=0;s<CHUNK;s++){
    size_t m = m0 + s;
    float dlt = __half2float(g_delta[m*DIi + d]);
    float x   = __half2float(g_xc[m*DIi + d]);
    float dx  = dlt * x;
    float dAv[NN];
    dA_compute(dAv, A, dlt, fast);
    float y = 0.f;
    #pragma unroll
    for (int n=0;n<NN;n++){
      h[n] = dAv[n]*h[n] + dx*sB[s][n];
      y += h[n]*sC[s][n];
    }
    y += Dv*x;
    float zv = __half2float(g_z[m*DIi + d]);
    g_yg[m*DIi + d] = __float2half(y * siluf(zv));
  }
}

// ---------------- driver ----------------
extern "C" void kernel_launch(void* const* d_in, const int* in_sizes, int n_in,
                              void* d_out, int out_size){
  const float* x      = (const float*)d_in[0];
  const float* in_w   = (const float*)d_in[1];
  const float* conv_w = (const float*)d_in[2];
  const float* conv_b = (const float*)d_in[3];
  const float* A_log  = (const float*)d_in[4];
  const float* xd_w   = (const float*)d_in[5];
  const float* xB_w   = (const float*)d_in[6];
  const float* xC_w   = (const float*)d_in[7];
  const float* dtp_w  = (const float*)d_in[8];
  const float* dtp_b  = (const float*)d_in[9];
  const float* Dp     = (const float*)d_in[10];
  const float* out_w  = (const float*)d_in[11];
  const float* ln_g   = (const float*)d_in[12];
  const float* ln_b   = (const float*)d_in[13];
  const float* merge_w= (const float*)d_in[14];
  float* out = (float*)d_out;

  k_prep<<<5760, 256>>>(x, in_w, xd_w, xB_w, xC_w, dtp_w, out_w, merge_w);
  for (int bi=0; bi<2; bi++){
    int b0 = bi, b1 = 2 + bi;
    k_gemm_in <<<dim3(8,64), 256>>>(b0, b1,
                                    ln_g + b0*DMm, ln_b + b0*DMm,
                                    ln_g + b1*DMm, ln_b + b1*DMm);
    k_conv    <<<(M2/4)*128/256, 256>>>(conv_w + b0*DIi*4, conv_b + b0*DIi,
                                        conv_w + b1*DIi*4, conv_b + b1*DIi);
    k_gemm_x  <<<dim3(KS,32), 256>>>(b0, b1);
    k_xred    <<<M2*16/256, 256>>>();
    k_gemm_dt <<<dim3(4,64), 256>>>(b0, b1, dtp_b + b0*DIi, dtp_b + b1*DIi);
    k_scan1   <<<2*NSEQ*NCH, 256>>>(A_log + b0*DIi*NN, A_log + b1*DIi*NN);
    k_comb    <<<256, 128>>>();
    k_scan2   <<<2*NSEQ*NCH, 256>>>(A_log + b0*DIi*NN, A_log + b1*DIi*NN,
                                    Dp + b0*DIi, Dp + b1*DIi);
    k_gemm_out<<<dim3(2,64), 256>>>(b0, b1);
  }
  k_merge<<<dim3(4,32), 256>>>(out);
}

// round 15
// speedup vs baseline: 1.3692x; 1.1518x over previous
#include <cuda_runtime.h>
#include <cuda_fp16.h>

// ---------------- problem constants ----------------
#define Bb   2
#define Ss   2048
#define DMm  256
#define DIi  512
#define NN   16
#define RR   32
#define MM   (Bb*Ss)          // 4096 rows per chain
#define M2   (2*MM)           // 8192 rows: [fwd | reversed]
#define CHUNK 32
#define NCH  (Ss/CHUNK)       // 64 chunks per sequence
#define NSEQ 4                // 4 sequences total (2 fwd + 2 rev)
#define KS   4                // split-K for x-proj

// ---------------- device scratch ----------------
__device__ float  g_res [M2*DMm];
__device__ __half g_xs  [M2*DIi];
__device__ __half g_z   [M2*DIi];
__device__ __half g_xc  [M2*DIi];
__device__ float  g_proj[M2*64];          // [xd(32) | B(16) | C(16)] fp32
__device__ __half g_projh[M2*64];         // half mirror for gemm_dt A-path
__device__ float  g_projp[KS*M2*64];      // split-K partials (fp32)
__device__ __half g_delta[M2*DIi];
__device__ __half g_yg  [M2*DIi];
__device__ float  g_P   [NSEQ*NCH*DIi*NN];
__device__ float  g_Q   [NSEQ*NCH*DIi*NN];
__device__ float  g_Hin [NSEQ*NCH*DIi*NN];

// k-pair-packed half2 weight mirrors: W2[k/2][n] = (W[k][n], W[k+1][n])
__device__ unsigned g_win2[4*128*1024];   // in_w:   [blk][k2=128][n=1024]
__device__ unsigned g_xw2 [4*256*64];     // xd|xB|xC: [blk][k2=256][n=64]
__device__ unsigned g_dtw2[4*16*512];     // dtp_w:  [blk][k2=16][n=512]
__device__ unsigned g_ow2 [4*256*256];    // out_w:  [blk][k2=256][n=256]
__device__ unsigned g_mw2 [256*256];      // merge_w:[k2=256][n=256]

__device__ __forceinline__ float siluf(float x){ return x / (1.f + __expf(-x)); }
__device__ __forceinline__ float spf(float a){ return (a > 20.f) ? a : log1pf(__expf(a)); }

__device__ __forceinline__ unsigned h2pack(float a, float b){
  __half2 h = __floats2half2_rn(a, b);
  return *reinterpret_cast<unsigned*>(&h);
}
__device__ __forceinline__ float4 h4load(const __half* p){
  uint2 u = *(const uint2*)p;
  float2 fa = __half22float2(*(__half2*)&u.x);
  float2 fb = __half22float2(*(__half2*)&u.y);
  return make_float4(fa.x, fa.y, fb.x, fb.y);
}
__device__ __forceinline__ void h4store(__half* p, float4 v){
  uint2 u; u.x = h2pack(v.x, v.y); u.y = h2pack(v.z, v.w);
  *(uint2*)p = u;
}

#define MMA16(c, a, b)                                                       \
  asm volatile("mma.sync.aligned.m16n8k16.row.col.f32.f16.f16.f32 "          \
               "{%0,%1,%2,%3},{%4,%5,%6,%7},{%8,%9},{%0,%1,%2,%3};"          \
               : "+f"((c)[0]), "+f"((c)[1]), "+f"((c)[2]), "+f"((c)[3])      \
               : "r"((a)[0]), "r"((a)[1]), "r"((a)[2]), "r"((a)[3]),         \
                 "r"((b)[0]), "r"((b)[1]))

// ---------------- merged prep: weight pack + input init, one launch -------
__global__ void k_prep(const float* __restrict__ x,
                       const float* __restrict__ in_w,
                       const float* __restrict__ xd_w,
                       const float* __restrict__ xB_w,
                       const float* __restrict__ xC_w,
                       const float* __restrict__ dtp_w,
                       const float* __restrict__ out_w,
                       const float* __restrict__ merge_w){
  int i = blockIdx.x*256 + threadIdx.x;       // 950272 wprep + 524288 init
  if (i < 524288){                            // in_w: [blk][k=256][n=1024]
    int blk = i >> 17, r = i & 131071;
    int k2 = r >> 10, n = r & 1023;
    size_t base = (size_t)blk*262144 + (size_t)(2*k2)*1024 + n;
    g_win2[i] = h2pack(in_w[base], in_w[base + 1024]);
  } else if (i < 589824){                     // xd|xB|xC: [blk][k=512][n=64]
    int j = i - 524288;
    int blk = j >> 14, r = j & 16383;
    int k2 = r >> 6, n = r & 63;
    float v0, v1;
    if (n < 32){
      size_t b = (size_t)blk*16384 + (size_t)(2*k2)*32 + n;
      v0 = xd_w[b]; v1 = xd_w[b + 32];
    } else if (n < 48){
      size_t b = (size_t)blk*8192 + (size_t)(2*k2)*16 + (n-32);
      v0 = xB_w[b]; v1 = xB_w[b + 16];
    } else {
      size_t b = (size_t)blk*8192 + (size_t)(2*k2)*16 + (n-48);
      v0 = xC_w[b]; v1 = xC_w[b + 16];
    }
    g_xw2[j] = h2pack(v0, v1);
  } else if (i < 622592){                     // dtp_w: [blk][k=32][n=512]
    int j = i - 589824;
    int blk = j >> 13, r = j & 8191;
    int k2 = r >> 9, n = r & 511;
    size_t b = (size_t)blk*16384 + (size_t)(2*k2)*512 + n;
    g_dtw2[j] = h2pack(dtp_w[b], dtp_w[b + 512]);
  } else if (i < 884736){                     // out_w: [blk][k=512][n=256]
    int j = i - 622592;
    int blk = j >> 16, r = j & 65535;
    int k2 = r >> 8, n = r & 255;
    size_t b = (size_t)blk*131072 + (size_t)(2*k2)*256 + n;
    g_ow2[j] = h2pack(out_w[b], out_w[b + 256]);
  } else if (i < 950272){                     // merge_w: [k=512][n=256]
    int j = i - 884736;
    int k2 = j >> 8, n = j & 255;
    size_t b = (size_t)(2*k2)*256 + n;
    g_mw2[j] = h2pack(merge_w[b], merge_w[b + 256]);
  } else {                                    // init: fwd + reversed copies
    int idx = i - 950272;                     // M2*64 = 524288 float4s
    int col = idx & 63;
    int m   = idx >> 6;
    int half = m >> 12;
    int b = (m >> 11) & 1, s = m & (Ss-1);
    int ms = b*Ss + (half ? (Ss-1-s) : s);
    reinterpret_cast<float4*>(g_res)[m*64+col] =
        reinterpret_cast<const float4*>(x)[ms*64+col];
  }
}

// ======================================================================
// TC: 128x64 FP16 mma core (round-7 proven). 256 thr = 8 warps (4Mx2N).
// ======================================================================
#define TC_DECL()                                                     \
  __shared__ __align__(16) unsigned Af[2][1024];                      \
  __shared__ __align__(16) unsigned Bf[2][512];                       \
  const int t = threadIdx.x;                                          \
  const int lane = t & 31, wid = t >> 5;                              \
  const int wm = wid >> 1, wn = wid & 1;                              \
  const int s_r  = t >> 1;                                            \
  const int s_kb = (t & 1) * 8;                                       \
  const int s_bq = t >> 6;                                            \
  const int s_bn = t & 63;                                            \
  float acc[2][4][4] = {};                                            \
  float4 raA0, raA1; uint4 raH; unsigned rbx, rby;                    \
  (void)raA0; (void)raA1; (void)raH;

#define TC_AB(buf) &Af[buf][(((s_r>>4)*32 + ((s_r&7)*4))*4) + ((s_r>>3)&1) + ((s_kb>>2)&2)]

#define TC_STAGE_B(buf) {                                             \
  int ln0 = (s_bn & 7)*4 + ((2*s_bq) & 3);                            \
  int rgB = s_bq >> 1;                                                \
  unsigned* bb = &Bf[buf][((s_bn >> 3)*32 + ln0)*2 + rgB];            \
  bb[0] = rbx;                                                        \
  bb[2] = rby; }

#define TC_STAGE_F(buf) {                                             \
  unsigned* ab = TC_AB(buf);                                          \
  ab[0]  = h2pack(raA0.x, raA0.y);                                    \
  ab[4]  = h2pack(raA0.z, raA0.w);                                    \
  ab[8]  = h2pack(raA1.x, raA1.y);                                    \
  ab[12] = h2pack(raA1.z, raA1.w);                                    \
  TC_STAGE_B(buf) }

#define TC_STAGE_H(buf) {                                             \
  unsigned* ab = TC_AB(buf);                                          \
  ab[0]  = raH.x;                                                     \
  ab[4]  = raH.y;                                                     \
  ab[8]  = raH.z;                                                     \
  ab[12] = raH.w;                                                     \
  TC_STAGE_B(buf) }

#define TC_COMP(buf) {                                                \
  unsigned a_[2][4]; unsigned b_[4][2];                               \
  _Pragma("unroll") for (int mt=0;mt<2;mt++)                          \
    *(uint4*)a_[mt] = *(const uint4*)&Af[buf][((wm*2+mt)*32 + lane)*4]; \
  _Pragma("unroll") for (int nt=0;nt<4;nt++)                          \
    *(uint2*)b_[nt] = *(const uint2*)&Bf[buf][((wn*4+nt)*32 + lane)*2]; \
  _Pragma("unroll") for (int mt=0;mt<2;mt++)                          \
    _Pragma("unroll") for (int nt=0;nt<4;nt++)                        \
      MMA16(acc[mt][nt], a_[mt], b_[nt]); }

#define TC_BODY_GEN(KT, STG, CMP)                                     \
  LOADA(0); LOADB(0);                                                 \
  STG(0);                                                             \
  if (16 < (KT)) { LOADA(16); LOADB(16); }                            \
  __syncthreads();                                                    \
  { int cur = 0;                                                      \
    _Pragma("unroll 1")                                               \
    for (int k0=0; k0<(KT); k0+=16){                                  \
      if (k0+16 < (KT)) STG(cur^1);                                   \
      if (k0+32 < (KT)) { LOADA(k0+32); LOADB(k0+32); }               \
      CMP(cur);                                                       \
      __syncthreads();                                                \
      cur ^= 1;                                                       \
    } }

#define TC_BODY(KT)   TC_BODY_GEN(KT, TC_STAGE_F, TC_COMP)
#define TC_BODY_H(KT) TC_BODY_GEN(KT, TC_STAGE_H, TC_COMP)

// ======================================================================
// TC2: 128x128 FP16 mma core. 256 threads, warp tile 32x64 (16 mma/chunk).
// ======================================================================
#define TC2_DECL()                                                    \
  __shared__ __align__(16) unsigned Af[2][1024];                      \
  __shared__ __align__(16) unsigned Bf[2][1024];                      \
  const int t = threadIdx.x;                                          \
  const int lane = t & 31, wid = t >> 5;                              \
  const int wm = wid >> 1, wn = wid & 1;                              \
  const int s_r  = t >> 1;                                            \
  const int s_kb = (t & 1) * 8;                                       \
  const int s_bn = t & 127;         /* B n 0..127        */           \
  const int s_bq = (t >> 7) * 4;    /* B k2 base 0 or 4  */           \
  const int b_base = (((s_bn>>3)*32 + (s_bn&7)*4))*2 + (s_bq>>2);     \
  float acc[2][8][4] = {};                                            \
  float4 raA0, raA1; uint4 raH;                                       \
  unsigned rb0, rb1, rb2, rb3;                                        \
  (void)raA0; (void)raA1; (void)raH;

#define TC2_STAGE_B(buf) {                                            \
  Bf[buf][b_base+0] = rb0;                                            \
  Bf[buf][b_base+2] = rb1;                                            \
  Bf[buf][b_base+4] = rb2;                                            \
  Bf[buf][b_base+6] = rb3; }

#define TC2_STAGE_F(buf) {                                            \
  unsigned* ab = TC_AB(buf);                                          \
  ab[0]  = h2pack(raA0.x, raA0.y);                                    \
  ab[4]  = h2pack(raA0.z, raA0.w);                                    \
  ab[8]  = h2pack(raA1.x, raA1.y);                                    \
  ab[12] = h2pack(raA1.z, raA1.w);                                    \
  TC2_STAGE_B(buf) }

#define TC2_STAGE_H(buf) {                                            \
  unsigned* ab = TC_AB(buf);                                          \
  ab[0]  = raH.x;                                                     \
  ab[4]  = raH.y;                                                     \
  ab[8]  = raH.z;                                                     \
  ab[12] = raH.w;                                                     \
  TC2_STAGE_B(buf) }

#define TC2_COMP(buf) {                                               \
  unsigned a_[2][4];                                                  \
  _Pragma("unroll") for (int mt=0;mt<2;mt++)                          \
    *(uint4*)a_[mt] = *(const uint4*)&Af[buf][((wm*2+mt)*32 + lane)*4]; \
  _Pragma("unroll") for (int j=0;j<8;j++){                            \
    unsigned b_[2];                                                   \
    *(uint2*)b_ = *(const uint2*)&Bf[buf][((wn*8+j)*32 + lane)*2];    \
    MMA16(acc[0][j], a_[0], b_);                                      \
    MMA16(acc[1][j], a_[1], b_);                                      \
  } }

#define TC2_BODY(KT)   TC_BODY_GEN(KT, TC2_STAGE_F, TC2_COMP)
#define TC2_BODY_H(KT) TC_BODY_GEN(KT, TC2_STAGE_H, TC2_COMP)

// in_proj with fused LayerNorm, 128-wide N tiles (TC2)
__global__ void k_gemm_in(int b0, int b1,
                          const float* __restrict__ g0, const float* __restrict__ bt0,
                          const float* __restrict__ g1, const float* __restrict__ bt1){
  int col0 = blockIdx.x*128, row0 = blockIdx.y*128;
  int half = row0 >> 12;
  const unsigned* W2 = g_win2 + (size_t)(half ? b1 : b0)*131072;
  const float* gm = half ? g1  : g0;
  const float* bb = half ? bt1 : bt0;
  __shared__ float sG[DMm], sBt[DMm];
  TC2_DECL();
  sG[t] = gm[t]; sBt[t] = bb[t];
  const float* rowp = g_res + (size_t)(row0 + s_r)*DMm;
  float sum = 0.f, sq = 0.f;
  #pragma unroll
  for (int j=0;j<16;j++){
    float4 v0 = *(const float4*)&rowp[j*16 + s_kb];
    float4 v1 = *(const float4*)&rowp[j*16 + s_kb + 4];
    sum += v0.x+v0.y+v0.z+v0.w + v1.x+v1.y+v1.z+v1.w;
    sq  += v0.x*v0.x+v0.y*v0.y+v0.z*v0.z+v0.w*v0.w
         + v1.x*v1.x+v1.y*v1.y+v1.z*v1.z+v1.w*v1.w;
  }
  sum += __shfl_xor_sync(~0u, sum, 1);
  sq  += __shfl_xor_sync(~0u, sq, 1);
  float mean = sum*(1.f/DMm);
  float rstd = rsqrtf(sq*(1.f/DMm) - mean*mean + 1e-5f);
  __syncthreads();   // sG/sBt visible
#define LOADA(k0_) { int kk_=(k0_)+s_kb;                                           \
    raA0 = *(const float4*)&rowp[kk_];                                             \
    raA1 = *(const float4*)&rowp[kk_+4];                                           \
    raA0.x=(raA0.x-mean)*rstd*sG[kk_+0]+sBt[kk_+0];                                \
    raA0.y=(raA0.y-mean)*rstd*sG[kk_+1]+sBt[kk_+1];                                \
    raA0.z=(raA0.z-mean)*rstd*sG[kk_+2]+sBt[kk_+2];                                \
    raA0.w=(raA0.w-mean)*rstd*sG[kk_+3]+sBt[kk_+3];                                \
    raA1.x=(raA1.x-mean)*rstd*sG[kk_+4]+sBt[kk_+4];                                \
    raA1.y=(raA1.y-mean)*rstd*sG[kk_+5]+sBt[kk_+5];                                \
    raA1.z=(raA1.z-mean)*rstd*sG[kk_+6]+sBt[kk_+6];                                \
    raA1.w=(raA1.w-mean)*rstd*sG[kk_+7]+sBt[kk_+7]; }
#define LOADB(k0_) { int k2_ = ((k0_) >> 1) + s_bq;                                \
                     rb0 = W2[(size_t)(k2_+0)*1024 + col0 + s_bn];                 \
                     rb1 = W2[(size_t)(k2_+1)*1024 + col0 + s_bn];                 \
                     rb2 = W2[(size_t)(k2_+2)*1024 + col0 + s_bn];                 \
                     rb3 = W2[(size_t)(k2_+3)*1024 + col0 + s_bn]; }
  TC2_BODY(DMm);
#undef LOADA
#undef LOADB
  __half* dst = (col0 < DIi) ? g_xs : g_z;
  int cb = (col0 < DIi) ? col0 : col0 - DIi;
  #pragma unroll
  for (int mt=0;mt<2;mt++)
    #pragma unroll
    for (int j=0;j<8;j++){
      int r = row0 + wm*32 + mt*16 + (lane>>2);
      int c = cb + wn*64 + j*8 + (lane&3)*2;
      *(unsigned*)&dst[(size_t)r*DIi + c]     = h2pack(acc[mt][j][0], acc[mt][j][1]);
      *(unsigned*)&dst[(size_t)(r+8)*DIi + c] = h2pack(acc[mt][j][2], acc[mt][j][3]);
    }
}

// x-proj split-K (proven TC core): xc @ [xd|xB|xC] -> projp[kz]
__global__ void k_gemm_x(int b0, int b1){
  int kz = blockIdx.x, row0 = blockIdx.y*128;
  int half = row0 >> 12;
  int kbase = kz*(DIi/KS);
  const unsigned* W2 = g_xw2 + (size_t)(half ? b1 : b0)*16384;
  TC_DECL();
#define LOADA(k0_) { raH = *(const uint4*)&g_xc[(size_t)(row0+s_r)*DIi + kbase+(k0_)+s_kb]; }
#define LOADB(k0_) { int k2_ = ((kbase+(k0_)) >> 1) + s_bq*2;                      \
                     rbx = W2[(size_t)(k2_+0)*64 + s_bn];                          \
                     rby = W2[(size_t)(k2_+1)*64 + s_bn]; }
  TC_BODY_H(DIi/KS);
#undef LOADA
#undef LOADB
  float* dst = g_projp + (size_t)kz*M2*64;
  #pragma unroll
  for (int mt=0;mt<2;mt++)
    #pragma unroll
    for (int nt=0;nt<4;nt++){
      int r = row0 + wm*32 + mt*16 + (lane>>2);
      int c = wn*32 + nt*8 + (lane&3)*2;
      *(float2*)&dst[(size_t)r*64 + c]     = make_float2(acc[mt][nt][0], acc[mt][nt][1]);
      *(float2*)&dst[(size_t)(r+8)*64 + c] = make_float2(acc[mt][nt][2], acc[mt][nt][3]);
    }
}

__global__ void k_xred(){
  int i = blockIdx.x*256 + threadIdx.x;   // M2*16 float4s
  float4 a = reinterpret_cast<const float4*>(g_projp)[i];
  float4 b = reinterpret_cast<const float4*>(g_projp + (size_t)M2*64)[i];
  float4 c = reinterpret_cast<const float4*>(g_projp + (size_t)2*M2*64)[i];
  float4 d = reinterpret_cast<const float4*>(g_projp + (size_t)3*M2*64)[i];
  float4 s = make_float4(a.x+b.x+c.x+d.x, a.y+b.y+c.y+d.y,
                         a.z+b.z+c.z+d.z, a.w+b.w+c.w+d.w);
  reinterpret_cast<float4*>(g_proj)[i] = s;
  h4store(&g_projh[i*4], s);
}

// delta: softplus(projh[:, :32] @ dtp_w[32,512] + dtp_b), 128-wide N (TC2)
__global__ void k_gemm_dt(int b0, int b1,
                          const float* __restrict__ bd0, const float* __restrict__ bd1){
  int col0 = blockIdx.x*128, row0 = blockIdx.y*128;
  int half = row0 >> 12;
  const unsigned* W2 = g_dtw2 + (size_t)(half ? b1 : b0)*8192;
  const float* bd = half ? bd1 : bd0;
  TC2_DECL();
#define LOADA(k0_) { raH = *(const uint4*)&g_projh[(size_t)(row0+s_r)*64 + (k0_)+s_kb]; }
#define LOADB(k0_) { int k2_ = ((k0_) >> 1) + s_bq;                                \
                     rb0 = W2[(size_t)(k2_+0)*512 + col0 + s_bn];                  \
                     rb1 = W2[(size_t)(k2_+1)*512 + col0 + s_bn];                  \
                     rb2 = W2[(size_t)(k2_+2)*512 + col0 + s_bn];                  \
                     rb3 = W2[(size_t)(k2_+3)*512 + col0 + s_bn]; }
  TC2_BODY_H(RR);
#undef LOADA
#undef LOADB
  #pragma unroll
  for (int mt=0;mt<2;mt++)
    #pragma unroll
    for (int j=0;j<8;j++){
      int r = row0 + wm*32 + mt*16 + (lane>>2);
      int c = col0 + wn*64 + j*8 + (lane&3)*2;
      float b0v = bd[c], b1v = bd[c+1];
      *(unsigned*)&g_delta[(size_t)r*DIi + c] =
          h2pack(spf(acc[mt][j][0]+b0v), spf(acc[mt][j][1]+b1v));
      *(unsigned*)&g_delta[(size_t)(r+8)*DIi + c] =
          h2pack(spf(acc[mt][j][2]+b0v), spf(acc[mt][j][3]+b1v));
    }
}

// out_proj, 128-wide N tiles (TC2): yg @ out_w + residual (in place on g_res)
__global__ void k_gemm_out(int b0, int b1){
  int col0 = blockIdx.x*128, row0 = blockIdx.y*128;
  int half = row0 >> 12;
  const unsigned* W2 = g_ow2 + (size_t)(half ? b1 : b0)*65536;
  TC2_DECL();
#define LOADA(k0_) { raH = *(const uint4*)&g_yg[(size_t)(row0+s_r)*DIi + (k0_)+s_kb]; }
#define LOADB(k0_) { int k2_ = ((k0_) >> 1) + s_bq;                                \
                     rb0 = W2[(size_t)(k2_+0)*256 + col0 + s_bn];                  \
                     rb1 = W2[(size_t)(k2_+1)*256 + col0 + s_bn];                  \
                     rb2 = W2[(size_t)(k2_+2)*256 + col0 + s_bn];                  \
                     rb3 = W2[(size_t)(k2_+3)*256 + col0 + s_bn]; }
  TC2_BODY_H(DIi);
#undef LOADA
#undef LOADB
  #pragma unroll
  for (int mt=0;mt<2;mt++)
    #pragma unroll
    for (int j=0;j<8;j++){
      int r = row0 + wm*32 + mt*16 + (lane>>2);
      int c = col0 + wn*64 + j*8 + (lane&3)*2;
      float2 o0 = *(const float2*)&g_res[(size_t)r*DMm + c];
      float2 o1 = *(const float2*)&g_res[(size_t)(r+8)*DMm + c];
      *(float2*)&g_res[(size_t)r*DMm + c] =
          make_float2(acc[mt][j][0]+o0.x, acc[mt][j][1]+o0.y);
      *(float2*)&g_res[(size_t)(r+8)*DMm + c] =
          make_float2(acc[mt][j][2]+o1.x, acc[mt][j][3]+o1.y);
    }
}

// merge (64-wide core): concat(res0, res1_rev) @ merge_w -> out
__global__ void k_merge(float* __restrict__ out){
  int col0 = blockIdx.x*64, row0 = blockIdx.y*128;
  TC_DECL();
  int r_ = row0 + s_r;
  int b_ = r_ >> 11, s_ = r_ & (Ss-1);
  int rrev = MM + b_*Ss + (Ss-1-s_);
#define LOADA(k0_) {                                                               \
    int kk0 = (k0_)+s_kb, kk1 = (k0_)+s_kb+4;                                      \
    raA0 = *(const float4*)((kk0 < DMm) ? (g_res + (size_t)r_*DMm + kk0)           \
                                        : (g_res + (size_t)rrev*DMm + kk0-DMm));   \
    raA1 = *(const float4*)((kk1 < DMm) ? (g_res + (size_t)r_*DMm + kk1)           \
                                        : (g_res + (size_t)rrev*DMm + kk1-DMm)); }
#define LOADB(k0_) { int k2_ = ((k0_) >> 1) + s_bq*2;                              \
                     rbx = g_mw2[(size_t)(k2_+0)*256 + col0 + s_bn];               \
                     rby = g_mw2[(size_t)(k2_+1)*256 + col0 + s_bn]; }
  TC_BODY(2*DMm);
#undef LOADA
#undef LOADB
  #pragma unroll
  for (int mt=0;mt<2;mt++)
    #pragma unroll
    for (int nt=0;nt<4;nt++){
      int r = row0 + wm*32 + mt*16 + (lane>>2);
      int c = col0 + wn*32 + nt*8 + (lane&3)*2;
      *(float2*)&out[(size_t)r*DMm + c]     = make_float2(acc[mt][nt][0], acc[mt][nt][1]);
      *(float2*)&out[(size_t)(r+8)*DMm + c] = make_float2(acc[mt][nt][2], acc[mt][nt][3]);
    }
}

// ---------------- causal depthwise conv (K=4) + silu, 8 s-positions/thread ----
__global__ void k_conv(const float* __restrict__ cw0, const float* __restrict__ cb0,
                       const float* __restrict__ cw1, const float* __restrict__ cb1){
  int idx = blockIdx.x*256 + threadIdx.x;   // (M2/8)*128
  int d4 = idx & 127, g = idx >> 7;         // g in [0, M2/8)
  int b2 = g >> 8, sg = g & 255;            // seq 0..3, group within seq
  int half = b2 >> 1;
  const float* cw = half ? cw1 : cw0;
  const float* cb = half ? cb1 : cb0;
  int m0 = b2*Ss + sg*8;
  int d = d4*4;
  float4 w0 = *(const float4*)(cw + (d+0)*4);
  float4 w1 = *(const float4*)(cw + (d+1)*4);
  float4 w2 = *(const float4*)(cw + (d+2)*4);
  float4 w3 = *(const float4*)(cw + (d+3)*4);
  float4 bv = *(const float4*)(cb + d);
  float4 x0, x1, x2;
  if (sg > 0){
    x0 = h4load(&g_xs[(size_t)(m0-3)*DIi + d]);
    x1 = h4load(&g_xs[(size_t)(m0-2)*DIi + d]);
    x2 = h4load(&g_xs[(size_t)(m0-1)*DIi + d]);
  } else {
    x0 = x1 = x2 = make_float4(0.f,0.f,0.f,0.f);
  }
  #pragma unroll
  for (int s=0;s<8;s++){
    float4 x3 = h4load(&g_xs[(size_t)(m0+s)*DIi + d]);
    float4 a;
    a.x = bv.x + w0.x*x0.x + w0.y*x1.x + w0.z*x2.x + w0.w*x3.x;
    a.y = bv.y + w1.x*x0.y + w1.y*x1.y + w1.z*x2.y + w1.w*x3.y;
    a.z = bv.z + w2.x*x0.z + w2.y*x1.z + w2.z*x2.z + w2.w*x3.z;
    a.w = bv.w + w3.x*x0.w + w3.y*x1.w + w3.z*x2.w + w3.w*x3.w;
    a.x = siluf(a.x); a.y = siluf(a.y); a.z = siluf(a.z); a.w = siluf(a.w);
    h4store(&g_xc[(size_t)(m0+s)*DIi + d], a);
    x0 = x1; x1 = x2; x2 = x3;
  }
}

// dA helper: if A[n] == -(n+1) (the actual dataset), dA_n = r^(n+1) with
// r = exp(-delta): 1 MUFU + 15 FMUL instead of 16 MUFU.
__device__ __forceinline__ void dA_compute(float* dAv, const float* A,
                                           float dlt, bool fast){
  if (fast){
    float r = __expf(-dlt);
    dAv[0] = r; dAv[1] = r*r;
    #pragma unroll
    for (int n=2;n<NN;n++) dAv[n] = dAv[n>>1]*dAv[(n-1)>>1];
  } else {
    #pragma unroll
    for (int n=0;n<NN;n++) dAv[n] = __expf(dlt*A[n]);
  }
}

__device__ __forceinline__ bool a_fast(const float* A){
  bool f = true;
  #pragma unroll
  for (int n=0;n<NN;n++) f = f && (fabsf(A[n] + (float)(n+1)) < 1e-5f*(n+1));
  return f;
}

// ---------------- chunked scan phase 1 ----------------
__global__ void k_scan1(const float* __restrict__ Alog0, const float* __restrict__ Alog1){
  __shared__ float sB[CHUNK][NN];
  int blk = blockIdx.x;               // 2 * NSEQ*NCH = 512
  int bc_ = blk >> 1;                 // 0..255
  int seq = bc_ >> 6, c = bc_ & 63;
  int half = seq >> 1;
  const float* Alog = half ? Alog1 : Alog0;
  int d = (blk & 1)*256 + threadIdx.x;
  int m0 = seq*Ss + c*CHUNK;
  { int i0 = threadIdx.x, i1 = threadIdx.x + 256;
    sB[i0>>4][i0&15] = g_proj[(size_t)(m0+(i0>>4))*64 + 32 + (i0&15)];
    sB[i1>>4][i1&15] = g_proj[(size_t)(m0+(i1>>4))*64 + 32 + (i1&15)]; }
  float A[NN];
  #pragma unroll
  for (int n=0;n<NN;n++) A[n] = -__expf(Alog[d*NN + n]);
  bool fast = a_fast(A);
  __syncthreads();
  float h[NN];
  #pragma unroll
  for (int n=0;n<NN;n++) h[n] = 0.f;
  float sd = 0.f;
  #pragma unroll 2
  for (int s=0;s<CHUNK;s++){
    size_t m = m0 + s;
    float dlt = __half2float(g_delta[m*DIi + d]);
    float dx  = dlt * __half2float(g_xc[m*DIi + d]);
    sd += dlt;
    float dAv[NN];
    dA_compute(dAv, A, dlt, fast);
    float4 b0 = *(const float4*)&sB[s][0];
    float4 b1 = *(const float4*)&sB[s][4];
    float4 b2 = *(const float4*)&sB[s][8];
    float4 b3 = *(const float4*)&sB[s][12];
    h[0]  = dAv[0] *h[0]  + dx*b0.x;  h[1]  = dAv[1] *h[1]  + dx*b0.y;
    h[2]  = dAv[2] *h[2]  + dx*b0.z;  h[3]  = dAv[3] *h[3]  + dx*b0.w;
    h[4]  = dAv[4] *h[4]  + dx*b1.x;  h[5]  = dAv[5] *h[5]  + dx*b1.y;
    h[6]  = dAv[6] *h[6]  + dx*b1.z;  h[7]  = dAv[7] *h[7]  + dx*b1.w;
    h[8]  = dAv[8] *h[8]  + dx*b2.x;  h[9]  = dAv[9] *h[9]  + dx*b2.y;
    h[10] = dAv[10]*h[10] + dx*b2.z;  h[11] = dAv[11]*h[11] + dx*b2.w;
    h[12] = dAv[12]*h[12] + dx*b3.x;  h[13] = dAv[13]*h[13] + dx*b3.y;
    h[14] = dAv[14]*h[14] + dx*b3.z;  h[15] = dAv[15]*h[15] + dx*b3.w;
  }
  size_t base = ((size_t)bc_*DIi + d)*NN;
  float Pv[NN];
  dA_compute(Pv, A, sd, fast);
  #pragma unroll
  for (int n=0;n<NN;n++){ g_Q[base+n]=h[n]; g_P[base+n]=Pv[n]; }
}

// ---------------- phase 2: combine across chunks ----------------
__global__ void k_comb(){
  int i = blockIdx.x*128 + threadIdx.x;     // NSEQ*DIi*NN = 32768
  int n = i & 15, d = (i >> 4) & (DIi-1), seq = i >> 13;
  float H = 0.f;
  for (int c=0;c<NCH;c++){
    size_t idx = (((size_t)(seq*NCH+c))*DIi + d)*NN + n;
    g_Hin[idx] = H;
    H = g_P[idx]*H + g_Q[idx];
  }
}

// ---------------- phase 3: replay + gated output ----------------
__global__ void k_scan2(const float* __restrict__ Alog0, const float* __restrict__ Alog1,
                        const float* __restrict__ Dp0, const float* __restrict__ Dp1){
  __shared__ float sB[CHUNK][NN];
  __shared__ float sC[CHUNK][NN];
  int blk = blockIdx.x;
  int bc_ = blk >> 1;
  int seq = bc_ >> 6, c = bc_ & 63;
  int half = seq >> 1;
  const float* Alog = half ? Alog1 : Alog0;
  const float* Dp   = half ? Dp1   : Dp0;
  int d = (blk & 1)*256 + threadIdx.x;
  int m0 = seq*Ss + c*CHUNK;
  { int i0 = threadIdx.x, i1 = threadIdx.x + 256;
    sB[i0>>4][i0&15] = g_proj[(size_t)(m0+(i0>>4))*64 + 32 + (i0&15)];
    sB[i1>>4][i1&15] = g_proj[(size_t)(m0+(i1>>4))*64 + 32 + (i1&15)];
    sC[i0>>4][i0&15] = g_proj[(size_t)(m0+(i0>>4))*64 + 48 + (i0&15)];
    sC[i1>>4][i1&15] = g_proj[(size_t)(m0+(i1>>4))*64 + 48 + (i1&15)]; }
  float A[NN];
  #pragma unroll
  for (int n=0;n<NN;n++) A[n] = -__expf(Alog[d*NN + n]);
  bool fast = a_fast(A);
  float h[NN];
  size_t base = ((size_t)bc_*DIi + d)*NN;
  #pragma unroll
  for (int n=0;n<NN;n++) h[n] = g_Hin[base+n];
  float Dv = Dp[d];
  __syncthreads();
  #pragma unroll 2
  for (int s=0;s<CHUNK;s++){
    size_t m = m0 + s;
    float dlt = __half2float(g_delta[m*DIi + d]);
    float x   = __half2float(g_xc[m*DIi + d]);
    float dx  = dlt * x;
    float dAv[NN];
    dA_compute(dAv, A, dlt, fast);
    float4 b0 = *(const float4*)&sB[s][0];
    float4 b1 = *(const float4*)&sB[s][4];
    float4 b2 = *(const float4*)&sB[s][8];
    float4 b3 = *(const float4*)&sB[s][12];
    float4 c0 = *(const float4*)&sC[s][0];
    float4 c1 = *(const float4*)&sC[s][4];
    float4 c2 = *(const float4*)&sC[s][8];
    float4 c3 = *(const float4*)&sC[s][12];
    float y = 0.f;
    h[0]  = dAv[0] *h[0]  + dx*b0.x;  y += h[0] *c0.x;
    h[1]  = dAv[1] *h[1]  + dx*b0.y;  y += h[1] *c0.y;
    h[2]  = dAv[2] *h[2]  + dx*b0.z;  y += h[2] *c0.z;
    h[3]  = dAv[3] *h[3]  + dx*b0.w;  y += h[3] *c0.w;
    h[4]  = dAv[4] *h[4]  + dx*b1.x;  y += h[4] *c1.x;
    h[5]  = dAv[5] *h[5]  + dx*b1.y;  y += h[5] *c1.y;
    h[6]  = dAv[6] *h[6]  + dx*b1.z;  y += h[6] *c1.z;
    h[7]  = dAv[7] *h[7]  + dx*b1.w;  y += h[7] *c1.w;
    h[8]  = dAv[8] *h[8]  + dx*b2.x;  y += h[8] *c2.x;
    h[9]  = dAv[9] *h[9]  + dx*b2.y;  y += h[9] *c2.y;
    h[10] = dAv[10]*h[10] + dx*b2.z;  y += h[10]*c2.z;
    h[11] = dAv[11]*h[11] + dx*b2.w;  y += h[11]*c2.w;
    h[12] = dAv[12]*h[12] + dx*b3.x;  y += h[12]*c3.x;
    h[13] = dAv[13]*h[13] + dx*b3.y;  y += h[13]*c3.y;
    h[14] = dAv[14]*h[14] + dx*b3.z;  y += h[14]*c3.z;
    h[15] = dAv[15]*h[15] + dx*b3.w;  y += h[15]*c3.w;
    y += Dv*x;
    float zv = __half2float(g_z[m*DIi + d]);
    g_yg[m*DIi + d] = __float2half(y * siluf(zv));
  }
}

// ---------------- driver ----------------
extern "C" void kernel_launch(void* const* d_in, const int* in_sizes, int n_in,
                              void* d_out, int out_size){
  const float* x      = (const float*)d_in[0];
  const float* in_w   = (const float*)d_in[1];
  const float* conv_w = (const float*)d_in[2];
  const float* conv_b = (const float*)d_in[3];
  const float* A_log  = (const float*)d_in[4];
  const float* xd_w   = (const float*)d_in[5];
  const float* xB_w   = (const float*)d_in[6];
  const float* xC_w   = (const float*)d_in[7];
  const float* dtp_w  = (const float*)d_in[8];
  const float* dtp_b  = (const float*)d_in[9];
  const float* Dp     = (const float*)d_in[10];
  const float* out_w  = (const float*)d_in[11];
  const float* ln_g   = (const float*)d_in[12];
  const float* ln_b   = (const float*)d_in[13];
  const float* merge_w= (const float*)d_in[14];
  float* out = (float*)d_out;

  k_prep<<<5760, 256>>>(x, in_w, xd_w, xB_w, xC_w, dtp_w, out_w, merge_w);
  for (int bi=0; bi<2; bi++){
    int b0 = bi, b1 = 2 + bi;
    k_gemm_in <<<dim3(8,64), 256>>>(b0, b1,
                                    ln_g + b0*DMm, ln_b + b0*DMm,
                                    ln_g + b1*DMm, ln_b + b1*DMm);
    k_conv    <<<(M2/8)*128/256, 256>>>(conv_w + b0*DIi*4, conv_b + b0*DIi,
                                        conv_w + b1*DIi*4, conv_b + b1*DIi);
    k_gemm_x  <<<dim3(KS,64), 256>>>(b0, b1);
    k_xred    <<<M2*16/256, 256>>>();
    k_gemm_dt <<<dim3(4,64), 256>>>(b0, b1, dtp_b + b0*DIi, dtp_b + b1*DIi);
    k_scan1   <<<2*NSEQ*NCH, 256>>>(A_log + b0*DIi*NN, A_log + b1*DIi*NN);
    k_comb    <<<256, 128>>>();
    k_scan2   <<<2*NSEQ*NCH, 256>>>(A_log + b0*DIi*NN, A_log + b1*DIi*NN,
                                    Dp + b0*DIi, Dp + b1*DIi);
    k_gemm_out<<<dim3(2,64), 256>>>(b0, b1);
  }
  k_merge<<<dim3(4,32), 256>>>(out);
}

// round 16
// speedup vs baseline: 1.4419x; 1.0531x over previous
#include <cuda_runtime.h>
#include <cuda_fp16.h>

// ---------------- problem constants ----------------
#define Bb   2
#define Ss   2048
#define DMm  256
#define DIi  512
#define NN   16
#define RR   32
#define MM   (Bb*Ss)          // 4096 rows per chain
#define M2   (2*MM)           // 8192 rows: [fwd | reversed]
#define CHUNK 32
#define NCH  (Ss/CHUNK)       // 64 chunks per sequence
#define NSEQ 4                // 4 sequences total (2 fwd + 2 rev)
#define KS   4                // split-K for x-proj

// ---------------- device scratch ----------------
__device__ float  g_res [M2*DMm];
__device__ __half g_xs  [M2*DIi];
__device__ __half g_z   [M2*DIi];
__device__ __half g_xc  [M2*DIi];
__device__ float  g_proj[M2*64];          // [xd(32) | B(16) | C(16)] fp32
__device__ __half g_projh[M2*64];         // half mirror for gemm_dt A-path
__device__ float  g_projp[KS*M2*64];      // split-K partials (fp32)
__device__ __half g_delta[M2*DIi];
__device__ __half g_yg  [M2*DIi];
__device__ float  g_P   [NSEQ*NCH*DIi*NN];
__device__ float  g_Q   [NSEQ*NCH*DIi*NN];
__device__ float  g_Hin [NSEQ*NCH*DIi*NN];

// k-grouped packed half2 weight mirrors (n-fastest => coalesced):
//  uint2: (k,k+1),(k+2,k+3)   uint4: pairs covering 8 consecutive k
__device__ uint4 g_win4[4*32*1024];   // in_w:   [blk][k8=32][n=1024]
__device__ uint2 g_xw4 [4*128*64];    // xd|xB|xC: [blk][k4=128][n=64]
__device__ uint4 g_dtw8[4*4*512];     // dtp_w:  [blk][k8=4][n=512]
__device__ uint4 g_ow8 [4*64*256];    // out_w:  [blk][k8=64][n=256]
__device__ uint2 g_mw4 [128*256];     // merge_w:[k4=128][n=256]

__device__ __forceinline__ float siluf(float x){ return x / (1.f + __expf(-x)); }
__device__ __forceinline__ float spf(float a){ return (a > 20.f) ? a : log1pf(__expf(a)); }

__device__ __forceinline__ unsigned h2pack(float a, float b){
  __half2 h = __floats2half2_rn(a, b);
  return *reinterpret_cast<unsigned*>(&h);
}
__device__ __forceinline__ float4 h4load(const __half* p){
  uint2 u = *(const uint2*)p;
  float2 fa = __half22float2(*(__half2*)&u.x);
  float2 fb = __half22float2(*(__half2*)&u.y);
  return make_float4(fa.x, fa.y, fb.x, fb.y);
}
__device__ __forceinline__ void h4store(__half* p, float4 v){
  uint2 u; u.x = h2pack(v.x, v.y); u.y = h2pack(v.z, v.w);
  *(uint2*)p = u;
}

#define MMA16(c, a, b)                                                       \
  asm volatile("mma.sync.aligned.m16n8k16.row.col.f32.f16.f16.f32 "          \
               "{%0,%1,%2,%3},{%4,%5,%6,%7},{%8,%9},{%0,%1,%2,%3};"          \
               : "+f"((c)[0]), "+f"((c)[1]), "+f"((c)[2]), "+f"((c)[3])      \
               : "r"((a)[0]), "r"((a)[1]), "r"((a)[2]), "r"((a)[3]),         \
                 "r"((b)[0]), "r"((b)[1]))

// ---------------- merged prep: weight pack + input init, one launch -------
__global__ void k_prep(const float* __restrict__ x,
                       const float* __restrict__ in_w,
                       const float* __restrict__ xd_w,
                       const float* __restrict__ xB_w,
                       const float* __restrict__ xC_w,
                       const float* __restrict__ dtp_w,
                       const float* __restrict__ out_w,
                       const float* __restrict__ merge_w){
  int i = blockIdx.x*256 + threadIdx.x;       // 794624 total
  if (i < 131072){                            // win4: [blk][k8=32][n=1024]
    int blk = i >> 15, r = i & 32767;
    int k8 = r >> 10, n = r & 1023;
    size_t b = (size_t)blk*262144 + (size_t)(8*k8)*1024 + n;
    g_win4[i] = make_uint4(h2pack(in_w[b], in_w[b+1024]),
                           h2pack(in_w[b+2048], in_w[b+3072]),
                           h2pack(in_w[b+4096], in_w[b+5120]),
                           h2pack(in_w[b+6144], in_w[b+7168]));
  } else if (i < 163840){                     // xw4: [blk][k4=128][n=64]
    int j = i - 131072;
    int blk = j >> 13, r = j & 8191;
    int k4 = r >> 6, n = r & 63;
    int k = 4*k4;
    float v0,v1,v2,v3;
    if (n < 32){
      size_t b = (size_t)blk*16384 + (size_t)k*32 + n;
      v0=xd_w[b]; v1=xd_w[b+32]; v2=xd_w[b+64]; v3=xd_w[b+96];
    } else if (n < 48){
      size_t b = (size_t)blk*8192 + (size_t)k*16 + (n-32);
      v0=xB_w[b]; v1=xB_w[b+16]; v2=xB_w[b+32]; v3=xB_w[b+48];
    } else {
      size_t b = (size_t)blk*8192 + (size_t)k*16 + (n-48);
      v0=xC_w[b]; v1=xC_w[b+16]; v2=xC_w[b+32]; v3=xC_w[b+48];
    }
    g_xw4[j] = make_uint2(h2pack(v0,v1), h2pack(v2,v3));
  } else if (i < 172032){                     // dtw8: [blk][k8=4][n=512]
    int j = i - 163840;
    int blk = j >> 11, r = j & 2047;
    int k8 = r >> 9, n = r & 511;
    size_t b = (size_t)blk*16384 + (size_t)(8*k8)*512 + n;
    g_dtw8[j] = make_uint4(h2pack(dtp_w[b], dtp_w[b+512]),
                           h2pack(dtp_w[b+1024], dtp_w[b+1536]),
                           h2pack(dtp_w[b+2048], dtp_w[b+2560]),
                           h2pack(dtp_w[b+3072], dtp_w[b+3584]));
  } else if (i < 237568){                     // ow8: [blk][k8=64][n=256]
    int j = i - 172032;
    int blk = j >> 14, r = j & 16383;
    int k8 = r >> 8, n = r & 255;
    size_t b = (size_t)blk*131072 + (size_t)(8*k8)*256 + n;
    g_ow8[j] = make_uint4(h2pack(out_w[b], out_w[b+256]),
                          h2pack(out_w[b+512], out_w[b+768]),
                          h2pack(out_w[b+1024], out_w[b+1280]),
                          h2pack(out_w[b+1536], out_w[b+1792]));
  } else if (i < 270336){                     // mw4: [k4=128][n=256]
    int j = i - 237568;
    int k4 = j >> 8, n = j & 255;
    size_t b = (size_t)(4*k4)*256 + n;
    g_mw4[j] = make_uint2(h2pack(merge_w[b], merge_w[b+256]),
                          h2pack(merge_w[b+512], merge_w[b+768]));
  } else {                                    // init: fwd + reversed copies
    int idx = i - 270336;                     // M2*64 = 524288 float4s
    int col = idx & 63;
    int m   = idx >> 6;
    int half = m >> 12;
    int b = (m >> 11) & 1, s = m & (Ss-1);
    int ms = b*Ss + (half ? (Ss-1-s) : s);
    reinterpret_cast<float4*>(g_res)[m*64+col] =
        reinterpret_cast<const float4*>(x)[ms*64+col];
  }
}

// ======================================================================
// TC: 128x64 FP16 mma core. 256 thr = 8 warps (4Mx2N).
// B stage: one LDG.64 of k-quad mirror.
// ======================================================================
#define TC_DECL()                                                     \
  __shared__ __align__(16) unsigned Af[2][1024];                      \
  __shared__ __align__(16) unsigned Bf[2][512];                       \
  const int t = threadIdx.x;                                          \
  const int lane = t & 31, wid = t >> 5;                              \
  const int wm = wid >> 1, wn = wid & 1;                              \
  const int s_r  = t >> 1;                                            \
  const int s_kb = (t & 1) * 8;                                       \
  const int s_bq = t >> 6;                                            \
  const int s_bn = t & 63;                                            \
  float acc[2][4][4] = {};                                            \
  float4 raA0, raA1; uint4 raH; unsigned rbx, rby;                    \
  (void)raA0; (void)raA1; (void)raH;

#define TC_AB(buf) &Af[buf][(((s_r>>4)*32 + ((s_r&7)*4))*4) + ((s_r>>3)&1) + ((s_kb>>2)&2)]

#define TC_STAGE_B(buf) {                                             \
  int ln0 = (s_bn & 7)*4 + ((2*s_bq) & 3);                            \
  int rgB = s_bq >> 1;                                                \
  unsigned* bb = &Bf[buf][((s_bn >> 3)*32 + ln0)*2 + rgB];            \
  bb[0] = rbx;                                                        \
  bb[2] = rby; }

#define TC_STAGE_F(buf) {                                             \
  unsigned* ab = TC_AB(buf);                                          \
  ab[0]  = h2pack(raA0.x, raA0.y);                                    \
  ab[4]  = h2pack(raA0.z, raA0.w);                                    \
  ab[8]  = h2pack(raA1.x, raA1.y);                                    \
  ab[12] = h2pack(raA1.z, raA1.w);                                    \
  TC_STAGE_B(buf) }

#define TC_STAGE_H(buf) {                                             \
  unsigned* ab = TC_AB(buf);                                          \
  ab[0]  = raH.x;                                                     \
  ab[4]  = raH.y;                                                     \
  ab[8]  = raH.z;                                                     \
  ab[12] = raH.w;                                                     \
  TC_STAGE_B(buf) }

#define TC_COMP(buf) {                                                \
  unsigned a_[2][4]; unsigned b_[4][2];                               \
  _Pragma("unroll") for (int mt=0;mt<2;mt++)                          \
    *(uint4*)a_[mt] = *(const uint4*)&Af[buf][((wm*2+mt)*32 + lane)*4]; \
  _Pragma("unroll") for (int nt=0;nt<4;nt++)                          \
    *(uint2*)b_[nt] = *(const uint2*)&Bf[buf][((wn*4+nt)*32 + lane)*2]; \
  _Pragma("unroll") for (int mt=0;mt<2;mt++)                          \
    _Pragma("unroll") for (int nt=0;nt<4;nt++)                        \
      MMA16(acc[mt][nt], a_[mt], b_[nt]); }

#define TC_BODY_GEN(KT, STG, CMP)                                     \
  LOADA(0); LOADB(0);                                                 \
  STG(0);                                                             \
  if (16 < (KT)) { LOADA(16); LOADB(16); }                            \
  __syncthreads();                                                    \
  { int cur = 0;                                                      \
    _Pragma("unroll 1")                                               \
    for (int k0=0; k0<(KT); k0+=16){                                  \
      if (k0+16 < (KT)) STG(cur^1);                                   \
      if (k0+32 < (KT)) { LOADA(k0+32); LOADB(k0+32); }               \
      CMP(cur);                                                       \
      __syncthreads();                                                \
      cur ^= 1;                                                       \
    } }

#define TC_BODY(KT)   TC_BODY_GEN(KT, TC_STAGE_F, TC_COMP)
#define TC_BODY_H(KT) TC_BODY_GEN(KT, TC_STAGE_H, TC_COMP)

// ======================================================================
// TC2: 128x128 FP16 mma core. 256 threads, warp tile 32x64 (16 mma/chunk).
// B stage: one LDG.128 of k-octet mirror.
// ======================================================================
#define TC2_DECL()                                                    \
  __shared__ __align__(16) unsigned Af[2][1024];                      \
  __shared__ __align__(16) unsigned Bf[2][1024];                      \
  const int t = threadIdx.x;                                          \
  const int lane = t & 31, wid = t >> 5;                              \
  const int wm = wid >> 1, wn = wid & 1;                              \
  const int s_r  = t >> 1;                                            \
  const int s_kb = (t & 1) * 8;                                       \
  const int s_bn = t & 127;         /* B n 0..127        */           \
  const int s_bq = (t >> 7) * 4;    /* B k2 base 0 or 4  */           \
  const int b_base = (((s_bn>>3)*32 + (s_bn&7)*4))*2 + (s_bq>>2);     \
  float acc[2][8][4] = {};                                            \
  float4 raA0, raA1; uint4 raH;                                       \
  unsigned rb0, rb1, rb2, rb3;                                        \
  (void)raA0; (void)raA1; (void)raH;

#define TC2_STAGE_B(buf) {                                            \
  Bf[buf][b_base+0] = rb0;                                            \
  Bf[buf][b_base+2] = rb1;                                            \
  Bf[buf][b_base+4] = rb2;                                            \
  Bf[buf][b_base+6] = rb3; }

#define TC2_STAGE_F(buf) {                                            \
  unsigned* ab = TC_AB(buf);                                          \
  ab[0]  = h2pack(raA0.x, raA0.y);                                    \
  ab[4]  = h2pack(raA0.z, raA0.w);                                    \
  ab[8]  = h2pack(raA1.x, raA1.y);                                    \
  ab[12] = h2pack(raA1.z, raA1.w);                                    \
  TC2_STAGE_B(buf) }

#define TC2_STAGE_H(buf) {                                            \
  unsigned* ab = TC_AB(buf);                                          \
  ab[0]  = raH.x;                                                     \
  ab[4]  = raH.y;                                                     \
  ab[8]  = raH.z;                                                     \
  ab[12] = raH.w;                                                     \
  TC2_STAGE_B(buf) }

#define TC2_COMP(buf) {                                               \
  unsigned a_[2][4];                                                  \
  _Pragma("unroll") for (int mt=0;mt<2;mt++)                          \
    *(uint4*)a_[mt] = *(const uint4*)&Af[buf][((wm*2+mt)*32 + lane)*4]; \
  _Pragma("unroll") for (int j=0;j<8;j++){                            \
    unsigned b_[2];                                                   \
    *(uint2*)b_ = *(const uint2*)&Bf[buf][((wn*8+j)*32 + lane)*2];    \
    MMA16(acc[0][j], a_[0], b_);                                      \
    MMA16(acc[1][j], a_[1], b_);                                      \
  } }

#define TC2_BODY(KT)   TC_BODY_GEN(KT, TC2_STAGE_F, TC2_COMP)
#define TC2_BODY_H(KT) TC_BODY_GEN(KT, TC2_STAGE_H, TC2_COMP)

// in_proj with fused LayerNorm, 128-wide N tiles (TC2)
__global__ void k_gemm_in(int b0, int b1,
                          const float* __restrict__ g0, const float* __restrict__ bt0,
                          const float* __restrict__ g1, const float* __restrict__ bt1){
  int col0 = blockIdx.x*128, row0 = blockIdx.y*128;
  int half = row0 >> 12;
  const uint4* W4 = g_win4 + (size_t)(half ? b1 : b0)*32768;
  const float* gm = half ? g1  : g0;
  const float* bb = half ? bt1 : bt0;
  __shared__ float sG[DMm], sBt[DMm];
  TC2_DECL();
  sG[t] = gm[t]; sBt[t] = bb[t];
  const float* rowp = g_res + (size_t)(row0 + s_r)*DMm;
  float sum = 0.f, sq = 0.f;
  #pragma unroll
  for (int j=0;j<16;j++){
    float4 v0 = *(const float4*)&rowp[j*16 + s_kb];
    float4 v1 = *(const float4*)&rowp[j*16 + s_kb + 4];
    sum += v0.x+v0.y+v0.z+v0.w + v1.x+v1.y+v1.z+v1.w;
    sq  += v0.x*v0.x+v0.y*v0.y+v0.z*v0.z+v0.w*v0.w
         + v1.x*v1.x+v1.y*v1.y+v1.z*v1.z+v1.w*v1.w;
  }
  sum += __shfl_xor_sync(~0u, sum, 1);
  sq  += __shfl_xor_sync(~0u, sq, 1);
  float mean = sum*(1.f/DMm);
  float rstd = rsqrtf(sq*(1.f/DMm) - mean*mean + 1e-5f);
  __syncthreads();   // sG/sBt visible
#define LOADA(k0_) { int kk_=(k0_)+s_kb;                                           \
    raA0 = *(const float4*)&rowp[kk_];                                             \
    raA1 = *(const float4*)&rowp[kk_+4];                                           \
    raA0.x=(raA0.x-mean)*rstd*sG[kk_+0]+sBt[kk_+0];                                \
    raA0.y=(raA0.y-mean)*rstd*sG[kk_+1]+sBt[kk_+1];                                \
    raA0.z=(raA0.z-mean)*rstd*sG[kk_+2]+sBt[kk_+2];                                \
    raA0.w=(raA0.w-mean)*rstd*sG[kk_+3]+sBt[kk_+3];                                \
    raA1.x=(raA1.x-mean)*rstd*sG[kk_+4]+sBt[kk_+4];                                \
    raA1.y=(raA1.y-mean)*rstd*sG[kk_+5]+sBt[kk_+5];                                \
    raA1.z=(raA1.z-mean)*rstd*sG[kk_+6]+sBt[kk_+6];                                \
    raA1.w=(raA1.w-mean)*rstd*sG[kk_+7]+sBt[kk_+7]; }
#define LOADB(k0_) { uint4 v = W4[(size_t)(((k0_)>>3)+(s_bq>>2))*1024 + col0 + s_bn]; \
                     rb0 = v.x; rb1 = v.y; rb2 = v.z; rb3 = v.w; }
  TC2_BODY(DMm);
#undef LOADA
#undef LOADB
  __half* dst = (col0 < DIi) ? g_xs : g_z;
  int cb = (col0 < DIi) ? col0 : col0 - DIi;
  #pragma unroll
  for (int mt=0;mt<2;mt++)
    #pragma unroll
    for (int j=0;j<8;j++){
      int r = row0 + wm*32 + mt*16 + (lane>>2);
      int c = cb + wn*64 + j*8 + (lane&3)*2;
      *(unsigned*)&dst[(size_t)r*DIi + c]     = h2pack(acc[mt][j][0], acc[mt][j][1]);
      *(unsigned*)&dst[(size_t)(r+8)*DIi + c] = h2pack(acc[mt][j][2], acc[mt][j][3]);
    }
}

// x-proj split-K (TC core): xc @ [xd|xB|xC] -> projp[kz]
__global__ void k_gemm_x(int b0, int b1){
  int kz = blockIdx.x, row0 = blockIdx.y*128;
  int half = row0 >> 12;
  int kbase = kz*(DIi/KS);
  const uint2* W4 = g_xw4 + (size_t)(half ? b1 : b0)*8192;
  TC_DECL();
#define LOADA(k0_) { raH = *(const uint4*)&g_xc[(size_t)(row0+s_r)*DIi + kbase+(k0_)+s_kb]; }
#define LOADB(k0_) { uint2 v = W4[(size_t)(((kbase+(k0_))>>2)+s_bq)*64 + s_bn];    \
                     rbx = v.x; rby = v.y; }
  TC_BODY_H(DIi/KS);
#undef LOADA
#undef LOADB
  float* dst = g_projp + (size_t)kz*M2*64;
  #pragma unroll
  for (int mt=0;mt<2;mt++)
    #pragma unroll
    for (int nt=0;nt<4;nt++){
      int r = row0 + wm*32 + mt*16 + (lane>>2);
      int c = wn*32 + nt*8 + (lane&3)*2;
      *(float2*)&dst[(size_t)r*64 + c]     = make_float2(acc[mt][nt][0], acc[mt][nt][1]);
      *(float2*)&dst[(size_t)(r+8)*64 + c] = make_float2(acc[mt][nt][2], acc[mt][nt][3]);
    }
}

__global__ void k_xred(){
  int i = blockIdx.x*256 + threadIdx.x;   // M2*16 float4s
  float4 a = reinterpret_cast<const float4*>(g_projp)[i];
  float4 b = reinterpret_cast<const float4*>(g_projp + (size_t)M2*64)[i];
  float4 c = reinterpret_cast<const float4*>(g_projp + (size_t)2*M2*64)[i];
  float4 d = reinterpret_cast<const float4*>(g_projp + (size_t)3*M2*64)[i];
  float4 s = make_float4(a.x+b.x+c.x+d.x, a.y+b.y+c.y+d.y,
                         a.z+b.z+c.z+d.z, a.w+b.w+c.w+d.w);
  reinterpret_cast<float4*>(g_proj)[i] = s;
  h4store(&g_projh[i*4], s);
}

// delta: softplus(projh[:, :32] @ dtp_w[32,512] + dtp_b), 128-wide N (TC2)
__global__ void k_gemm_dt(int b0, int b1,
                          const float* __restrict__ bd0, const float* __restrict__ bd1){
  int col0 = blockIdx.x*128, row0 = blockIdx.y*128;
  int half = row0 >> 12;
  const uint4* W8 = g_dtw8 + (size_t)(half ? b1 : b0)*2048;
  const float* bd = half ? bd1 : bd0;
  TC2_DECL();
#define LOADA(k0_) { raH = *(const uint4*)&g_projh[(size_t)(row0+s_r)*64 + (k0_)+s_kb]; }
#define LOADB(k0_) { uint4 v = W8[(size_t)(((k0_)>>3)+(s_bq>>2))*512 + col0 + s_bn]; \
                     rb0 = v.x; rb1 = v.y; rb2 = v.z; rb3 = v.w; }
  TC2_BODY_H(RR);
#undef LOADA
#undef LOADB
  #pragma unroll
  for (int mt=0;mt<2;mt++)
    #pragma unroll
    for (int j=0;j<8;j++){
      int r = row0 + wm*32 + mt*16 + (lane>>2);
      int c = col0 + wn*64 + j*8 + (lane&3)*2;
      float b0v = bd[c], b1v = bd[c+1];
      *(unsigned*)&g_delta[(size_t)r*DIi + c] =
          h2pack(spf(acc[mt][j][0]+b0v), spf(acc[mt][j][1]+b1v));
      *(unsigned*)&g_delta[(size_t)(r+8)*DIi + c] =
          h2pack(spf(acc[mt][j][2]+b0v), spf(acc[mt][j][3]+b1v));
    }
}

// out_proj, 128-wide N tiles (TC2): yg @ out_w + residual (in place on g_res)
__global__ void k_gemm_out(int b0, int b1){
  int col0 = blockIdx.x*128, row0 = blockIdx.y*128;
  int half = row0 >> 12;
  const uint4* W8 = g_ow8 + (size_t)(half ? b1 : b0)*16384;
  TC2_DECL();
#define LOADA(k0_) { raH = *(const uint4*)&g_yg[(size_t)(row0+s_r)*DIi + (k0_)+s_kb]; }
#define LOADB(k0_) { uint4 v = W8[(size_t)(((k0_)>>3)+(s_bq>>2))*256 + col0 + s_bn]; \
                     rb0 = v.x; rb1 = v.y; rb2 = v.z; rb3 = v.w; }
  TC2_BODY_H(DIi);
#undef LOADA
#undef LOADB
  #pragma unroll
  for (int mt=0;mt<2;mt++)
    #pragma unroll
    for (int j=0;j<8;j++){
      int r = row0 + wm*32 + mt*16 + (lane>>2);
      int c = col0 + wn*64 + j*8 + (lane&3)*2;
      float2 o0 = *(const float2*)&g_res[(size_t)r*DMm + c];
      float2 o1 = *(const float2*)&g_res[(size_t)(r+8)*DMm + c];
      *(float2*)&g_res[(size_t)r*DMm + c] =
          make_float2(acc[mt][j][0]+o0.x, acc[mt][j][1]+o0.y);
      *(float2*)&g_res[(size_t)(r+8)*DMm + c] =
          make_float2(acc[mt][j][2]+o1.x, acc[mt][j][3]+o1.y);
    }
}

// merge (TC core): concat(res0, res1_rev) @ merge_w -> out
__global__ void k_merge(float* __restrict__ out){
  int col0 = blockIdx.x*64, row0 = blockIdx.y*128;
  TC_DECL();
  int r_ = row0 + s_r;
  int b_ = r_ >> 11, s_ = r_ & (Ss-1);
  int rrev = MM + b_*Ss + (Ss-1-s_);
#define LOADA(k0_) {                                                               \
    int kk0 = (k0_)+s_kb, kk1 = (k0_)+s_kb+4;                                      \
    raA0 = *(const float4*)((kk0 < DMm) ? (g_res + (size_t)r_*DMm + kk0)           \
                                        : (g_res + (size_t)rrev*DMm + kk0-DMm));   \
    raA1 = *(const float4*)((kk1 < DMm) ? (g_res + (size_t)r_*DMm + kk1)           \
                                        : (g_res + (size_t)rrev*DMm + kk1-DMm)); }
#define LOADB(k0_) { uint2 v = g_mw4[(size_t)(((k0_)>>2)+s_bq)*256 + col0 + s_bn]; \
                     rbx = v.x; rby = v.y; }
  TC_BODY(2*DMm);
#undef LOADA
#undef LOADB
  #pragma unroll
  for (int mt=0;mt<2;mt++)
    #pragma unroll
    for (int nt=0;nt<4;nt++){
      int r = row0 + wm*32 + mt*16 + (lane>>2);
      int c = col0 + wn*32 + nt*8 + (lane&3)*2;
      *(float2*)&out[(size_t)r*DMm + c]     = make_float2(acc[mt][nt][0], acc[mt][nt][1]);
      *(float2*)&out[(size_t)(r+8)*DMm + c] = make_float2(acc[mt][nt][2], acc[mt][nt][3]);
    }
}

// ---------------- causal depthwise conv (K=4) + silu, 8 s-positions/thread ----
__global__ void k_conv(const float* __restrict__ cw0, const float* __restrict__ cb0,
                       const float* __restrict__ cw1, const float* __restrict__ cb1){
  int idx = blockIdx.x*256 + threadIdx.x;   // (M2/8)*128
  int d4 = idx & 127, g = idx >> 7;         // g in [0, M2/8)
  int b2 = g >> 8, sg = g & 255;            // seq 0..3, group within seq
  int half = b2 >> 1;
  const float* cw = half ? cw1 : cw0;
  const float* cb = half ? cb1 : cb0;
  int m0 = b2*Ss + sg*8;
  int d = d4*4;
  float4 w0 = *(const float4*)(cw + (d+0)*4);
  float4 w1 = *(const float4*)(cw + (d+1)*4);
  float4 w2 = *(const float4*)(cw + (d+2)*4);
  float4 w3 = *(const float4*)(cw + (d+3)*4);
  float4 bv = *(const float4*)(cb + d);
  float4 x0, x1, x2;
  if (sg > 0){
    x0 = h4load(&g_xs[(size_t)(m0-3)*DIi + d]);
    x1 = h4load(&g_xs[(size_t)(m0-2)*DIi + d]);
    x2 = h4load(&g_xs[(size_t)(m0-1)*DIi + d]);
  } else {
    x0 = x1 = x2 = make_float4(0.f,0.f,0.f,0.f);
  }
  #pragma unroll
  for (int s=0;s<8;s++){
    float4 x3 = h4load(&g_xs[(size_t)(m0+s)*DIi + d]);
    float4 a;
    a.x = bv.x + w0.x*x0.x + w0.y*x1.x + w0.z*x2.x + w0.w*x3.x;
    a.y = bv.y + w1.x*x0.y + w1.y*x1.y + w1.z*x2.y + w1.w*x3.y;
    a.z = bv.z + w2.x*x0.z + w2.y*x1.z + w2.z*x2.z + w2.w*x3.z;
    a.w = bv.w + w3.x*x0.w + w3.y*x1.w + w3.z*x2.w + w3.w*x3.w;
    a.x = siluf(a.x); a.y = siluf(a.y); a.z = siluf(a.z); a.w = siluf(a.w);
    h4store(&g_xc[(size_t)(m0+s)*DIi + d], a);
    x0 = x1; x1 = x2; x2 = x3;
  }
}

// dA helper: if A[n] == -(n+1) (the actual dataset), dA_n = r^(n+1) with
// r = exp(-delta): 1 MUFU + 15 FMUL instead of 16 MUFU.
__device__ __forceinline__ void dA_compute(float* dAv, const float* A,
                                           float dlt, bool fast){
  if (fast){
    float r = __expf(-dlt);
    dAv[0] = r; dAv[1] = r*r;
    #pragma unroll
    for (int n=2;n<NN;n++) dAv[n] = dAv[n>>1]*dAv[(n-1)>>1];
  } else {
    #pragma unroll
    for (int n=0;n<NN;n++) dAv[n] = __expf(dlt*A[n]);
  }
}

__device__ __forceinline__ bool a_fast(const float* A){
  bool f = true;
  #pragma unroll
  for (int n=0;n<NN;n++) f = f && (fabsf(A[n] + (float)(n+1)) < 1e-5f*(n+1));
  return f;
}

// ---------------- chunked scan phase 1 ----------------
__global__ void k_scan1(const float* __restrict__ Alog0, const float* __restrict__ Alog1){
  __shared__ float sB[CHUNK][NN];
  int blk = blockIdx.x;               // 2 * NSEQ*NCH = 512
  int bc_ = blk >> 1;                 // 0..255
  int seq = bc_ >> 6, c = bc_ & 63;
  int half = seq >> 1;
  const float* Alog = half ? Alog1 : Alog0;
  int d = (blk & 1)*256 + threadIdx.x;
  int m0 = seq*Ss + c*CHUNK;
  { int i0 = threadIdx.x, i1 = threadIdx.x + 256;
    sB[i0>>4][i0&15] = g_proj[(size_t)(m0+(i0>>4))*64 + 32 + (i0&15)];
    sB[i1>>4][i1&15] = g_proj[(size_t)(m0+(i1>>4))*64 + 32 + (i1&15)]; }
  float A[NN];
  #pragma unroll
  for (int n=0;n<NN;n++) A[n] = -__expf(Alog[d*NN + n]);
  bool fast = a_fast(A);
  __syncthreads();
  float h[NN];
  #pragma unroll
  for (int n=0;n<NN;n++) h[n] = 0.f;
  float sd = 0.f;
  float dlt = __half2float(g_delta[(size_t)m0*DIi + d]);
  float xcv = __half2float(g_xc[(size_t)m0*DIi + d]);
  #pragma unroll 2
  for (int s=0;s<CHUNK;s++){
    float dltn = 0.f, xcn = 0.f;
    if (s+1 < CHUNK){
      size_t mn = (size_t)(m0+s+1)*DIi + d;
      dltn = __half2float(g_delta[mn]);
      xcn  = __half2float(g_xc[mn]);
    }
    float dx = dlt * xcv;
    sd += dlt;
    float dAv[NN];
    dA_compute(dAv, A, dlt, fast);
    float4 b0 = *(const float4*)&sB[s][0];
    float4 b1 = *(const float4*)&sB[s][4];
    float4 b2 = *(const float4*)&sB[s][8];
    float4 b3 = *(const float4*)&sB[s][12];
    h[0]  = dAv[0] *h[0]  + dx*b0.x;  h[1]  = dAv[1] *h[1]  + dx*b0.y;
    h[2]  = dAv[2] *h[2]  + dx*b0.z;  h[3]  = dAv[3] *h[3]  + dx*b0.w;
    h[4]  = dAv[4] *h[4]  + dx*b1.x;  h[5]  = dAv[5] *h[5]  + dx*b1.y;
    h[6]  = dAv[6] *h[6]  + dx*b1.z;  h[7]  = dAv[7] *h[7]  + dx*b1.w;
    h[8]  = dAv[8] *h[8]  + dx*b2.x;  h[9]  = dAv[9] *h[9]  + dx*b2.y;
    h[10] = dAv[10]*h[10] + dx*b2.z;  h[11] = dAv[11]*h[11] + dx*b2.w;
    h[12] = dAv[12]*h[12] + dx*b3.x;  h[13] = dAv[13]*h[13] + dx*b3.y;
    h[14] = dAv[14]*h[14] + dx*b3.z;  h[15] = dAv[15]*h[15] + dx*b3.w;
    dlt = dltn; xcv = xcn;
  }
  size_t base = ((size_t)bc_*DIi + d)*NN;
  float Pv[NN];
  dA_compute(Pv, A, sd, fast);
  #pragma unroll
  for (int n=0;n<NN;n++){ g_Q[base+n]=h[n]; g_P[base+n]=Pv[n]; }
}

// ---------------- phase 2: combine across chunks ----------------
__global__ void k_comb(){
  int i = blockIdx.x*128 + threadIdx.x;     // NSEQ*DIi*NN = 32768
  int n = i & 15, d = (i >> 4) & (DIi-1), seq = i >> 13;
  float H = 0.f;
  size_t stride = (size_t)DIi*NN;
  size_t idx = ((size_t)(seq*NCH))*stride + (size_t)d*NN + n;
  #pragma unroll 2
  for (int c=0;c<NCH;c++){
    float p = g_P[idx], q = g_Q[idx];
    g_Hin[idx] = H;
    H = p*H + q;
    idx += stride;
  }
}

// ---------------- phase 3: replay + gated output ----------------
__global__ void k_scan2(const float* __restrict__ Alog0, const float* __restrict__ Alog1,
                        const float* __restrict__ Dp0, const float* __restrict__ Dp1){
  __shared__ float sB[CHUNK][NN];
  __shared__ float sC[CHUNK][NN];
  int blk = blockIdx.x;
  int bc_ = blk >> 1;
  int seq = bc_ >> 6, c = bc_ & 63;
  int half = seq >> 1;
  const float* Alog = half ? Alog1 : Alog0;
  const float* Dp   = half ? Dp1   : Dp0;
  int d = (blk & 1)*256 + threadIdx.x;
  int m0 = seq*Ss + c*CHUNK;
  { int i0 = threadIdx.x, i1 = threadIdx.x + 256;
    sB[i0>>4][i0&15] = g_proj[(size_t)(m0+(i0>>4))*64 + 32 + (i0&15)];
    sB[i1>>4][i1&15] = g_proj[(size_t)(m0+(i1>>4))*64 + 32 + (i1&15)];
    sC[i0>>4][i0&15] = g_proj[(size_t)(m0+(i0>>4))*64 + 48 + (i0&15)];
    sC[i1>>4][i1&15] = g_proj[(size_t)(m0+(i1>>4))*64 + 48 + (i1&15)]; }
  float A[NN];
  #pragma unroll
  for (int n=0;n<NN;n++) A[n] = -__expf(Alog[d*NN + n]);
  bool fast = a_fast(A);
  float h[NN];
  size_t base = ((size_t)bc_*DIi + d)*NN;
  #pragma unroll
  for (int n=0;n<NN;n++) h[n] = g_Hin[base+n];
  float Dv = Dp[d];
  __syncthreads();
  float dlt = __half2float(g_delta[(size_t)m0*DIi + d]);
  float xcv = __half2float(g_xc[(size_t)m0*DIi + d]);
  float zv  = __half2float(g_z[(size_t)m0*DIi + d]);
  #pragma unroll 2
  for (int s=0;s<CHUNK;s++){
    float dltn = 0.f, xcn = 0.f, zn = 0.f;
    if (s+1 < CHUNK){
      size_t mn = (size_t)(m0+s+1)*DIi + d;
      dltn = __half2float(g_delta[mn]);
      xcn  = __half2float(g_xc[mn]);
      zn   = __half2float(g_z[mn]);
    }
    float dx = dlt * xcv;
    float dAv[NN];
    dA_compute(dAv, A, dlt, fast);
    float4 b0 = *(const float4*)&sB[s][0];
    float4 b1 = *(const float4*)&sB[s][4];
    float4 b2 = *(const float4*)&sB[s][8];
    float4 b3 = *(const float4*)&sB[s][12];
    float4 c0 = *(const float4*)&sC[s][0];
    float4 c1 = *(const float4*)&sC[s][4];
    float4 c2 = *(const float4*)&sC[s][8];
    float4 c3 = *(const float4*)&sC[s][12];
    float y0, y1, y2, y3;
    h[0]  = dAv[0] *h[0]  + dx*b0.x;  y0  = h[0] *c0.x;
    h[1]  = dAv[1] *h[1]  + dx*b0.y;  y1  = h[1] *c0.y;
    h[2]  = dAv[2] *h[2]  + dx*b0.z;  y2  = h[2] *c0.z;
    h[3]  = dAv[3] *h[3]  + dx*b0.w;  y3  = h[3] *c0.w;
    h[4]  = dAv[4] *h[4]  + dx*b1.x;  y0 += h[4] *c1.x;
    h[5]  = dAv[5] *h[5]  + dx*b1.y;  y1 += h[5] *c1.y;
    h[6]  = dAv[6] *h[6]  + dx*b1.z;  y2 += h[6] *c1.z;
    h[7]  = dAv[7] *h[7]  + dx*b1.w;  y3 += h[7] *c1.w;
    h[8]  = dAv[8] *h[8]  + dx*b2.x;  y0 += h[8] *c2.x;
    h[9]  = dAv[9] *h[9]  + dx*b2.y;  y1 += h[9] *c2.y;
    h[10] = dAv[10]*h[10] + dx*b2.z;  y2 += h[10]*c2.z;
    h[11] = dAv[11]*h[11] + dx*b2.w;  y3 += h[11]*c2.w;
    h[12] = dAv[12]*h[12] + dx*b3.x;  y0 += h[12]*c3.x;
    h[13] = dAv[13]*h[13] + dx*b3.y;  y1 += h[13]*c3.y;
    h[14] = dAv[14]*h[14] + dx*b3.z;  y2 += h[14]*c3.z;
    h[15] = dAv[15]*h[15] + dx*b3.w;  y3 += h[15]*c3.w;
    float y = (y0 + y1) + (y2 + y3) + Dv*xcv;
    g_yg[(size_t)(m0+s)*DIi + d] = __float2half(y * siluf(zv));
    dlt = dltn; xcv = xcn; zv = zn;
  }
}

// ---------------- driver ----------------
extern "C" void kernel_launch(void* const* d_in, const int* in_sizes, int n_in,
                              void* d_out, int out_size){
  const float* x      = (const float*)d_in[0];
  const float* in_w   = (const float*)d_in[1];
  const float* conv_w = (const float*)d_in[2];
  const float* conv_b = (const float*)d_in[3];
  const float* A_log  = (const float*)d_in[4];
  const float* xd_w   = (const float*)d_in[5];
  const float* xB_w   = (const float*)d_in[6];
  const float* xC_w   = (const float*)d_in[7];
  const float* dtp_w  = (const float*)d_in[8];
  const float* dtp_b  = (const float*)d_in[9];
  const float* Dp     = (const float*)d_in[10];
  const float* out_w  = (const float*)d_in[11];
  const float* ln_g   = (const float*)d_in[12];
  const float* ln_b   = (const float*)d_in[13];
  const float* merge_w= (const float*)d_in[14];
  float* out = (float*)d_out;

  k_prep<<<3104, 256>>>(x, in_w, xd_w, xB_w, xC_w, dtp_w, out_w, merge_w);
  for (int bi=0; bi<2; bi++){
    int b0 = bi, b1 = 2 + bi;
    k_gemm_in <<<dim3(8,64), 256>>>(b0, b1,
                                    ln_g + b0*DMm, ln_b + b0*DMm,
                                    ln_g + b1*DMm, ln_b + b1*DMm);
    k_conv    <<<(M2/8)*128/256, 256>>>(conv_w + b0*DIi*4, conv_b + b0*DIi,
                                        conv_w + b1*DIi*4, conv_b + b1*DIi);
    k_gemm_x  <<<dim3(KS,64), 256>>>(b0, b1);
    k_xred    <<<M2*16/256, 256>>>();
    k_gemm_dt <<<dim3(4,64), 256>>>(b0, b1, dtp_b + b0*DIi, dtp_b + b1*DIi);
    k_scan1   <<<2*NSEQ*NCH, 256>>>(A_log + b0*DIi*NN, A_log + b1*DIi*NN);
    k_comb    <<<256, 128>>>();
    k_scan2   <<<2*NSEQ*NCH, 256>>>(A_log + b0*DIi*NN, A_log + b1*DIi*NN,
                                    Dp + b0*DIi, Dp + b1*DIi);
    k_gemm_out<<<dim3(2,64), 256>>>(b0, b1);
  }
  k_merge<<<dim3(4,32), 256>>>(out);
}

// round 17
// speedup vs baseline: 1.5353x; 1.0648x over previous
#include <cuda_runtime.h>
#include <cuda_fp16.h>

// ---------------- problem constants ----------------
#define Bb   2
#define Ss   2048
#define DMm  256
#define DIi  512
#define NN   16
#define RR   32
#define MM   (Bb*Ss)          // 4096 rows per chain
#define M2   (2*MM)           // 8192 rows: [fwd | reversed]
#define CHUNK 32
#define NCH  (Ss/CHUNK)       // 64 chunks per sequence
#define NSEQ 4                // 4 sequences total (2 fwd + 2 rev)
#define KS   4                // split-K for x-proj

// ---------------- device scratch ----------------
__device__ float  g_res [M2*DMm];
__device__ __half g_xn  [M2*DMm];         // LN(g_res) in half, per iteration
__device__ __half g_xs  [M2*DIi];
__device__ __half g_z   [M2*DIi];
__device__ __half g_xc  [M2*DIi];
__device__ float  g_proj[M2*64];          // [xd(32) | B(16) | C(16)] fp32
__device__ __half g_projh[M2*64];         // half mirror for gemm_dt A-path
__device__ float  g_projp[KS*M2*64];      // split-K partials (fp32)
__device__ __half g_delta[M2*DIi];
__device__ __half g_yg  [M2*DIi];
__device__ float  g_P   [NSEQ*NCH*DIi*NN];
__device__ float  g_Q   [NSEQ*NCH*DIi*NN];
__device__ float  g_Hin [NSEQ*NCH*DIi*NN];

// k-grouped packed half2 weight mirrors (n-fastest => coalesced)
__device__ uint4 g_win4[4*32*1024];   // in_w:   [blk][k8=32][n=1024]
__device__ uint2 g_xw4 [4*128*64];    // xd|xB|xC: [blk][k4=128][n=64]
__device__ uint4 g_dtw8[4*4*512];     // dtp_w:  [blk][k8=4][n=512]
__device__ uint4 g_ow8 [4*64*256];    // out_w:  [blk][k8=64][n=256]
__device__ uint2 g_mw4 [128*256];     // merge_w:[k4=128][n=256]

__device__ __forceinline__ float siluf(float x){ return x / (1.f + __expf(-x)); }
__device__ __forceinline__ float spf(float a){ return (a > 20.f) ? a : log1pf(__expf(a)); }

__device__ __forceinline__ unsigned h2pack(float a, float b){
  __half2 h = __floats2half2_rn(a, b);
  return *reinterpret_cast<unsigned*>(&h);
}
__device__ __forceinline__ float4 h4load(const __half* p){
  uint2 u = *(const uint2*)p;
  float2 fa = __half22float2(*(__half2*)&u.x);
  float2 fb = __half22float2(*(__half2*)&u.y);
  return make_float4(fa.x, fa.y, fb.x, fb.y);
}
__device__ __forceinline__ void h4store(__half* p, float4 v){
  uint2 u; u.x = h2pack(v.x, v.y); u.y = h2pack(v.z, v.w);
  *(uint2*)p = u;
}

#define MMA16(c, a, b)                                                       \
  asm volatile("mma.sync.aligned.m16n8k16.row.col.f32.f16.f16.f32 "          \
               "{%0,%1,%2,%3},{%4,%5,%6,%7},{%8,%9},{%0,%1,%2,%3};"          \
               : "+f"((c)[0]), "+f"((c)[1]), "+f"((c)[2]), "+f"((c)[3])      \
               : "r"((a)[0]), "r"((a)[1]), "r"((a)[2]), "r"((a)[3]),         \
                 "r"((b)[0]), "r"((b)[1]))

// ---------------- merged prep: weight pack + input init, one launch -------
__global__ void k_prep(const float* __restrict__ x,
                       const float* __restrict__ in_w,
                       const float* __restrict__ xd_w,
                       const float* __restrict__ xB_w,
                       const float* __restrict__ xC_w,
                       const float* __restrict__ dtp_w,
                       const float* __restrict__ out_w,
                       const float* __restrict__ merge_w){
  int i = blockIdx.x*256 + threadIdx.x;       // 794624 total
  if (i < 131072){                            // win4: [blk][k8=32][n=1024]
    int blk = i >> 15, r = i & 32767;
    int k8 = r >> 10, n = r & 1023;
    size_t b = (size_t)blk*262144 + (size_t)(8*k8)*1024 + n;
    g_win4[i] = make_uint4(h2pack(in_w[b], in_w[b+1024]),
                           h2pack(in_w[b+2048], in_w[b+3072]),
                           h2pack(in_w[b+4096], in_w[b+5120]),
                           h2pack(in_w[b+6144], in_w[b+7168]));
  } else if (i < 163840){                     // xw4: [blk][k4=128][n=64]
    int j = i - 131072;
    int blk = j >> 13, r = j & 8191;
    int k4 = r >> 6, n = r & 63;
    int k = 4*k4;
    float v0,v1,v2,v3;
    if (n < 32){
      size_t b = (size_t)blk*16384 + (size_t)k*32 + n;
      v0=xd_w[b]; v1=xd_w[b+32]; v2=xd_w[b+64]; v3=xd_w[b+96];
    } else if (n < 48){
      size_t b = (size_t)blk*8192 + (size_t)k*16 + (n-32);
      v0=xB_w[b]; v1=xB_w[b+16]; v2=xB_w[b+32]; v3=xB_w[b+48];
    } else {
      size_t b = (size_t)blk*8192 + (size_t)k*16 + (n-48);
      v0=xC_w[b]; v1=xC_w[b+16]; v2=xC_w[b+32]; v3=xC_w[b+48];
    }
    g_xw4[j] = make_uint2(h2pack(v0,v1), h2pack(v2,v3));
  } else if (i < 172032){                     // dtw8: [blk][k8=4][n=512]
    int j = i - 163840;
    int blk = j >> 11, r = j & 2047;
    int k8 = r >> 9, n = r & 511;
    size_t b = (size_t)blk*16384 + (size_t)(8*k8)*512 + n;
    g_dtw8[j] = make_uint4(h2pack(dtp_w[b], dtp_w[b+512]),
                           h2pack(dtp_w[b+1024], dtp_w[b+1536]),
                           h2pack(dtp_w[b+2048], dtp_w[b+2560]),
                           h2pack(dtp_w[b+3072], dtp_w[b+3584]));
  } else if (i < 237568){                     // ow8: [blk][k8=64][n=256]
    int j = i - 172032;
    int blk = j >> 14, r = j & 16383;
    int k8 = r >> 8, n = r & 255;
    size_t b = (size_t)blk*131072 + (size_t)(8*k8)*256 + n;
    g_ow8[j] = make_uint4(h2pack(out_w[b], out_w[b+256]),
                          h2pack(out_w[b+512], out_w[b+768]),
                          h2pack(out_w[b+1024], out_w[b+1280]),
                          h2pack(out_w[b+1536], out_w[b+1792]));
  } else if (i < 270336){                     // mw4: [k4=128][n=256]
    int j = i - 237568;
    int k4 = j >> 8, n = j & 255;
    size_t b = (size_t)(4*k4)*256 + n;
    g_mw4[j] = make_uint2(h2pack(merge_w[b], merge_w[b+256]),
                          h2pack(merge_w[b+512], merge_w[b+768]));
  } else {                                    // init: fwd + reversed copies
    int idx = i - 270336;                     // M2*64 = 524288 float4s
    int col = idx & 63;
    int m   = idx >> 6;
    int half = m >> 12;
    int b = (m >> 11) & 1, s = m & (Ss-1);
    int ms = b*Ss + (half ? (Ss-1-s) : s);
    reinterpret_cast<float4*>(g_res)[m*64+col] =
        reinterpret_cast<const float4*>(x)[ms*64+col];
  }
}

// ---------------- LayerNorm -> half (1 warp per row of 256) ---------------
__global__ void k_ln(const float* __restrict__ g0, const float* __restrict__ bt0,
                     const float* __restrict__ g1, const float* __restrict__ bt1){
  int row = (blockIdx.x*256 + threadIdx.x) >> 5;   // 0..8191
  int lane = threadIdx.x & 31;
  int half = row >> 12;
  const float* gm = half ? g1  : g0;
  const float* bb = half ? bt1 : bt0;
  const float* rp = g_res + (size_t)row*DMm;
  int c0 = lane*8;
  float4 v0 = *(const float4*)&rp[c0];
  float4 v1 = *(const float4*)&rp[c0+4];
  float s = v0.x+v0.y+v0.z+v0.w + v1.x+v1.y+v1.z+v1.w;
  float q = v0.x*v0.x+v0.y*v0.y+v0.z*v0.z+v0.w*v0.w
          + v1.x*v1.x+v1.y*v1.y+v1.z*v1.z+v1.w*v1.w;
  #pragma unroll
  for (int o=16;o;o>>=1){ s += __shfl_xor_sync(~0u,s,o); q += __shfl_xor_sync(~0u,q,o); }
  float mean = s*(1.f/DMm);
  float rstd = rsqrtf(q*(1.f/DMm) - mean*mean + 1e-5f);
  float4 g0v = *(const float4*)&gm[c0];
  float4 g1v = *(const float4*)&gm[c0+4];
  float4 b0v = *(const float4*)&bb[c0];
  float4 b1v = *(const float4*)&bb[c0+4];
  uint4 o;
  o.x = h2pack((v0.x-mean)*rstd*g0v.x+b0v.x, (v0.y-mean)*rstd*g0v.y+b0v.y);
  o.y = h2pack((v0.z-mean)*rstd*g0v.z+b0v.z, (v0.w-mean)*rstd*g0v.w+b0v.w);
  o.z = h2pack((v1.x-mean)*rstd*g1v.x+b1v.x, (v1.y-mean)*rstd*g1v.y+b1v.y);
  o.w = h2pack((v1.z-mean)*rstd*g1v.z+b1v.z, (v1.w-mean)*rstd*g1v.w+b1v.w);
  *(uint4*)&g_xn[(size_t)row*DMm + c0] = o;
}

// ======================================================================
// TC: 128x64 FP16 mma core. 256 thr = 8 warps (4Mx2N).
// ======================================================================
#define TC_DECL()                                                     \
  __shared__ __align__(16) unsigned Af[2][1024];                      \
  __shared__ __align__(16) unsigned Bf[2][512];                       \
  const int t = threadIdx.x;                                          \
  const int lane = t & 31, wid = t >> 5;                              \
  const int wm = wid >> 1, wn = wid & 1;                              \
  const int s_r  = t >> 1;                                            \
  const int s_kb = (t & 1) * 8;                                       \
  const int s_bq = t >> 6;                                            \
  const int s_bn = t & 63;                                            \
  float acc[2][4][4] = {};                                            \
  float4 raA0, raA1; uint4 raH; unsigned rbx, rby;                    \
  (void)raA0; (void)raA1; (void)raH;

#define TC_AB(buf) &Af[buf][(((s_r>>4)*32 + ((s_r&7)*4))*4) + ((s_r>>3)&1) + ((s_kb>>2)&2)]

#define TC_STAGE_B(buf) {                                             \
  int ln0 = (s_bn & 7)*4 + ((2*s_bq) & 3);                            \
  int rgB = s_bq >> 1;                                                \
  unsigned* bb = &Bf[buf][((s_bn >> 3)*32 + ln0)*2 + rgB];            \
  bb[0] = rbx;                                                        \
  bb[2] = rby; }

#define TC_STAGE_F(buf) {                                             \
  unsigned* ab = TC_AB(buf);                                          \
  ab[0]  = h2pack(raA0.x, raA0.y);                                    \
  ab[4]  = h2pack(raA0.z, raA0.w);                                    \
  ab[8]  = h2pack(raA1.x, raA1.y);                                    \
  ab[12] = h2pack(raA1.z, raA1.w);                                    \
  TC_STAGE_B(buf) }

#define TC_STAGE_H(buf) {                                             \
  unsigned* ab = TC_AB(buf);                                          \
  ab[0]  = raH.x;                                                     \
  ab[4]  = raH.y;                                                     \
  ab[8]  = raH.z;                                                     \
  ab[12] = raH.w;                                                     \
  TC_STAGE_B(buf) }

#define TC_COMP(buf) {                                                \
  unsigned a_[2][4]; unsigned b_[4][2];                               \
  _Pragma("unroll") for (int mt=0;mt<2;mt++)                          \
    *(uint4*)a_[mt] = *(const uint4*)&Af[buf][((wm*2+mt)*32 + lane)*4]; \
  _Pragma("unroll") for (int nt=0;nt<4;nt++)                          \
    *(uint2*)b_[nt] = *(const uint2*)&Bf[buf][((wn*4+nt)*32 + lane)*2]; \
  _Pragma("unroll") for (int mt=0;mt<2;mt++)                          \
    _Pragma("unroll") for (int nt=0;nt<4;nt++)                        \
      MMA16(acc[mt][nt], a_[mt], b_[nt]); }

#define TC_BODY_GEN(KT, STG, CMP)                                     \
  LOADA(0); LOADB(0);                                                 \
  STG(0);                                                             \
  if (16 < (KT)) { LOADA(16); LOADB(16); }                            \
  __syncthreads();                                                    \
  { int cur = 0;                                                      \
    _Pragma("unroll 1")                                               \
    for (int k0=0; k0<(KT); k0+=16){                                  \
      if (k0+16 < (KT)) STG(cur^1);                                   \
      if (k0+32 < (KT)) { LOADA(k0+32); LOADB(k0+32); }               \
      CMP(cur);                                                       \
      __syncthreads();                                                \
      cur ^= 1;                                                       \
    } }

#define TC_BODY(KT)   TC_BODY_GEN(KT, TC_STAGE_F, TC_COMP)
#define TC_BODY_H(KT) TC_BODY_GEN(KT, TC_STAGE_H, TC_COMP)

// ======================================================================
// TC2: 128x128 FP16 mma core. 256 threads, warp tile 32x64 (16 mma/chunk).
// ======================================================================
#define TC2_DECL()                                                    \
  __shared__ __align__(16) unsigned Af[2][1024];                      \
  __shared__ __align__(16) unsigned Bf[2][1024];                      \
  const int t = threadIdx.x;                                          \
  const int lane = t & 31, wid = t >> 5;                              \
  const int wm = wid >> 1, wn = wid & 1;                              \
  const int s_r  = t >> 1;                                            \
  const int s_kb = (t & 1) * 8;                                       \
  const int s_bn = t & 127;         /* B n 0..127        */           \
  const int s_bq = (t >> 7) * 4;    /* B k2 base 0 or 4  */           \
  const int b_base = (((s_bn>>3)*32 + (s_bn&7)*4))*2 + (s_bq>>2);     \
  float acc[2][8][4] = {};                                            \
  float4 raA0, raA1; uint4 raH;                                       \
  unsigned rb0, rb1, rb2, rb3;                                        \
  (void)raA0; (void)raA1; (void)raH;

#define TC2_STAGE_B(buf) {                                            \
  Bf[buf][b_base+0] = rb0;                                            \
  Bf[buf][b_base+2] = rb1;                                            \
  Bf[buf][b_base+4] = rb2;                                            \
  Bf[buf][b_base+6] = rb3; }

#define TC2_STAGE_H(buf) {                                            \
  unsigned* ab = TC_AB(buf);                                          \
  ab[0]  = raH.x;                                                     \
  ab[4]  = raH.y;                                                     \
  ab[8]  = raH.z;                                                     \
  ab[12] = raH.w;                                                     \
  TC2_STAGE_B(buf) }

#define TC2_COMP(buf) {                                               \
  unsigned a_[2][4];                                                  \
  _Pragma("unroll") for (int mt=0;mt<2;mt++)                          \
    *(uint4*)a_[mt] = *(const uint4*)&Af[buf][((wm*2+mt)*32 + lane)*4]; \
  _Pragma("unroll") for (int j=0;j<8;j++){                            \
    unsigned b_[2];                                                   \
    *(uint2*)b_ = *(const uint2*)&Bf[buf][((wn*8+j)*32 + lane)*2];    \
    MMA16(acc[0][j], a_[0], b_);                                      \
    MMA16(acc[1][j], a_[1], b_);                                      \
  } }

#define TC2_BODY_H(KT) TC_BODY_GEN(KT, TC2_STAGE_H, TC2_COMP)

// in_proj: xn(half)[8192,256] @ in_w[256,1024] -> xs | z (half), TC2, pure H
__global__ void k_gemm_in(int b0, int b1){
  int col0 = blockIdx.x*128, row0 = blockIdx.y*128;
  int half = row0 >> 12;
  const uint4* W4 = g_win4 + (size_t)(half ? b1 : b0)*32768;
  TC2_DECL();
#define LOADA(k0_) { raH = *(const uint4*)&g_xn[(size_t)(row0+s_r)*DMm + (k0_)+s_kb]; }
#define LOADB(k0_) { uint4 v = W4[(size_t)(((k0_)>>3)+(s_bq>>2))*1024 + col0 + s_bn]; \
                     rb0 = v.x; rb1 = v.y; rb2 = v.z; rb3 = v.w; }
  TC2_BODY_H(DMm);
#undef LOADA
#undef LOADB
  __half* dst = (col0 < DIi) ? g_xs : g_z;
  int cb = (col0 < DIi) ? col0 : col0 - DIi;
  #pragma unroll
  for (int mt=0;mt<2;mt++)
    #pragma unroll
    for (int j=0;j<8;j++){
      int r = row0 + wm*32 + mt*16 + (lane>>2);
      int c = cb + wn*64 + j*8 + (lane&3)*2;
      *(unsigned*)&dst[(size_t)r*DIi + c]     = h2pack(acc[mt][j][0], acc[mt][j][1]);
      *(unsigned*)&dst[(size_t)(r+8)*DIi + c] = h2pack(acc[mt][j][2], acc[mt][j][3]);
    }
}

// x-proj split-K (TC core): xc @ [xd|xB|xC] -> projp[kz]
__global__ void k_gemm_x(int b0, int b1){
  int kz = blockIdx.x, row0 = blockIdx.y*128;
  int half = row0 >> 12;
  int kbase = kz*(DIi/KS);
  const uint2* W4 = g_xw4 + (size_t)(half ? b1 : b0)*8192;
  TC_DECL();
#define LOADA(k0_) { raH = *(const uint4*)&g_xc[(size_t)(row0+s_r)*DIi + kbase+(k0_)+s_kb]; }
#define LOADB(k0_) { uint2 v = W4[(size_t)(((kbase+(k0_))>>2)+s_bq)*64 + s_bn];    \
                     rbx = v.x; rby = v.y; }
  TC_BODY_H(DIi/KS);
#undef LOADA
#undef LOADB
  float* dst = g_projp + (size_t)kz*M2*64;
  #pragma unroll
  for (int mt=0;mt<2;mt++)
    #pragma unroll
    for (int nt=0;nt<4;nt++){
      int r = row0 + wm*32 + mt*16 + (lane>>2);
      int c = wn*32 + nt*8 + (lane&3)*2;
      *(float2*)&dst[(size_t)r*64 + c]     = make_float2(acc[mt][nt][0], acc[mt][nt][1]);
      *(float2*)&dst[(size_t)(r+8)*64 + c] = make_float2(acc[mt][nt][2], acc[mt][nt][3]);
    }
}

__global__ void k_xred(){
  int i = blockIdx.x*256 + threadIdx.x;   // M2*16 float4s
  float4 a = reinterpret_cast<const float4*>(g_projp)[i];
  float4 b = reinterpret_cast<const float4*>(g_projp + (size_t)M2*64)[i];
  float4 c = reinterpret_cast<const float4*>(g_projp + (size_t)2*M2*64)[i];
  float4 d = reinterpret_cast<const float4*>(g_projp + (size_t)3*M2*64)[i];
  float4 s = make_float4(a.x+b.x+c.x+d.x, a.y+b.y+c.y+d.y,
                         a.z+b.z+c.z+d.z, a.w+b.w+c.w+d.w);
  reinterpret_cast<float4*>(g_proj)[i] = s;
  h4store(&g_projh[i*4], s);
}

// delta: softplus(projh[:, :32] @ dtp_w[32,512] + dtp_b), 128-wide N (TC2)
__global__ void k_gemm_dt(int b0, int b1,
                          const float* __restrict__ bd0, const float* __restrict__ bd1){
  int col0 = blockIdx.x*128, row0 = blockIdx.y*128;
  int half = row0 >> 12;
  const uint4* W8 = g_dtw8 + (size_t)(half ? b1 : b0)*2048;
  const float* bd = half ? bd1 : bd0;
  TC2_DECL();
#define LOADA(k0_) { raH = *(const uint4*)&g_projh[(size_t)(row0+s_r)*64 + (k0_)+s_kb]; }
#define LOADB(k0_) { uint4 v = W8[(size_t)(((k0_)>>3)+(s_bq>>2))*512 + col0 + s_bn]; \
                     rb0 = v.x; rb1 = v.y; rb2 = v.z; rb3 = v.w; }
  TC2_BODY_H(RR);
#undef LOADA
#undef LOADB
  #pragma unroll
  for (int mt=0;mt<2;mt++)
    #pragma unroll
    for (int j=0;j<8;j++){
      int r = row0 + wm*32 + mt*16 + (lane>>2);
      int c = col0 + wn*64 + j*8 + (lane&3)*2;
      float b0v = bd[c], b1v = bd[c+1];
      *(unsigned*)&g_delta[(size_t)r*DIi + c] =
          h2pack(spf(acc[mt][j][0]+b0v), spf(acc[mt][j][1]+b1v));
      *(unsigned*)&g_delta[(size_t)(r+8)*DIi + c] =
          h2pack(spf(acc[mt][j][2]+b0v), spf(acc[mt][j][3]+b1v));
    }
}

// out_proj, 128-wide N tiles (TC2): yg @ out_w + residual (in place on g_res)
__global__ void k_gemm_out(int b0, int b1){
  int col0 = blockIdx.x*128, row0 = blockIdx.y*128;
  int half = row0 >> 12;
  const uint4* W8 = g_ow8 + (size_t)(half ? b1 : b0)*16384;
  TC2_DECL();
#define LOADA(k0_) { raH = *(const uint4*)&g_yg[(size_t)(row0+s_r)*DIi + (k0_)+s_kb]; }
#define LOADB(k0_) { uint4 v = W8[(size_t)(((k0_)>>3)+(s_bq>>2))*256 + col0 + s_bn]; \
                     rb0 = v.x; rb1 = v.y; rb2 = v.z; rb3 = v.w; }
  TC2_BODY_H(DIi);
#undef LOADA
#undef LOADB
  #pragma unroll
  for (int mt=0;mt<2;mt++)
    #pragma unroll
    for (int j=0;j<8;j++){
      int r = row0 + wm*32 + mt*16 + (lane>>2);
      int c = col0 + wn*64 + j*8 + (lane&3)*2;
      float2 o0 = *(const float2*)&g_res[(size_t)r*DMm + c];
      float2 o1 = *(const float2*)&g_res[(size_t)(r+8)*DMm + c];
      *(float2*)&g_res[(size_t)r*DMm + c] =
          make_float2(acc[mt][j][0]+o0.x, acc[mt][j][1]+o0.y);
      *(float2*)&g_res[(size_t)(r+8)*DMm + c] =
          make_float2(acc[mt][j][2]+o1.x, acc[mt][j][3]+o1.y);
    }
}

// merge (TC core): concat(res0, res1_rev) @ merge_w -> out
__global__ void k_merge(float* __restrict__ out){
  int col0 = blockIdx.x*64, row0 = blockIdx.y*128;
  TC_DECL();
  int r_ = row0 + s_r;
  int b_ = r_ >> 11, s_ = r_ & (Ss-1);
  int rrev = MM + b_*Ss + (Ss-1-s_);
#define LOADA(k0_) {                                                               \
    int kk0 = (k0_)+s_kb, kk1 = (k0_)+s_kb+4;                                      \
    raA0 = *(const float4*)((kk0 < DMm) ? (g_res + (size_t)r_*DMm + kk0)           \
                                        : (g_res + (size_t)rrev*DMm + kk0-DMm));   \
    raA1 = *(const float4*)((kk1 < DMm) ? (g_res + (size_t)r_*DMm + kk1)           \
                                        : (g_res + (size_t)rrev*DMm + kk1-DMm)); }
#define LOADB(k0_) { uint2 v = g_mw4[(size_t)(((k0_)>>2)+s_bq)*256 + col0 + s_bn]; \
                     rbx = v.x; rby = v.y; }
  TC_BODY(2*DMm);
#undef LOADA
#undef LOADB
  #pragma unroll
  for (int mt=0;mt<2;mt++)
    #pragma unroll
    for (int nt=0;nt<4;nt++){
      int r = row0 + wm*32 + mt*16 + (lane>>2);
      int c = col0 + wn*32 + nt*8 + (lane&3)*2;
      *(float2*)&out[(size_t)r*DMm + c]     = make_float2(acc[mt][nt][0], acc[mt][nt][1]);
      *(float2*)&out[(size_t)(r+8)*DMm + c] = make_float2(acc[mt][nt][2], acc[mt][nt][3]);
    }
}

// ---------------- causal depthwise conv (K=4) + silu, 8 s-positions/thread ----
__global__ void k_conv(const float* __restrict__ cw0, const float* __restrict__ cb0,
                       const float* __restrict__ cw1, const float* __restrict__ cb1){
  int idx = blockIdx.x*256 + threadIdx.x;   // (M2/8)*128
  int d4 = idx & 127, g = idx >> 7;         // g in [0, M2/8)
  int b2 = g >> 8, sg = g & 255;            // seq 0..3, group within seq
  int half = b2 >> 1;
  const float* cw = half ? cw1 : cw0;
  const float* cb = half ? cb1 : cb0;
  int m0 = b2*Ss + sg*8;
  int d = d4*4;
  float4 w0 = *(const float4*)(cw + (d+0)*4);
  float4 w1 = *(const float4*)(cw + (d+1)*4);
  float4 w2 = *(const float4*)(cw + (d+2)*4);
  float4 w3 = *(const float4*)(cw + (d+3)*4);
  float4 bv = *(const float4*)(cb + d);
  float4 x0, x1, x2;
  if (sg > 0){
    x0 = h4load(&g_xs[(size_t)(m0-3)*DIi + d]);
    x1 = h4load(&g_xs[(size_t)(m0-2)*DIi + d]);
    x2 = h4load(&g_xs[(size_t)(m0-1)*DIi + d]);
  } else {
    x0 = x1 = x2 = make_float4(0.f,0.f,0.f,0.f);
  }
  #pragma unroll
  for (int s=0;s<8;s++){
    float4 x3 = h4load(&g_xs[(size_t)(m0+s)*DIi + d]);
    float4 a;
    a.x = bv.x + w0.x*x0.x + w0.y*x1.x + w0.z*x2.x + w0.w*x3.x;
    a.y = bv.y + w1.x*x0.y + w1.y*x1.y + w1.z*x2.y + w1.w*x3.y;
    a.z = bv.z + w2.x*x0.z + w2.y*x1.z + w2.z*x2.z + w2.w*x3.z;
    a.w = bv.w + w3.x*x0.w + w3.y*x1.w + w3.z*x2.w + w3.w*x3.w;
    a.x = siluf(a.x); a.y = siluf(a.y); a.z = siluf(a.z); a.w = siluf(a.w);
    h4store(&g_xc[(size_t)(m0+s)*DIi + d], a);
    x0 = x1; x1 = x2; x2 = x3;
  }
}

// dA helper: if A[n] == -(n+1) (the actual dataset), dA_n = r^(n+1) with
// r = exp(-delta): 1 MUFU + 15 FMUL instead of 16 MUFU.
__device__ __forceinline__ void dA_compute(float* dAv, const float* A,
                                           float dlt, bool fast){
  if (fast){
    float r = __expf(-dlt);
    dAv[0] = r; dAv[1] = r*r;
    #pragma unroll
    for (int n=2;n<NN;n++) dAv[n] = dAv[n>>1]*dAv[(n-1)>>1];
  } else {
    #pragma unroll
    for (int n=0;n<NN;n++) dAv[n] = __expf(dlt*A[n]);
  }
}

__device__ __forceinline__ bool a_fast(const float* A){
  bool f = true;
  #pragma unroll
  for (int n=0;n<NN;n++) f = f && (fabsf(A[n] + (float)(n+1)) < 1e-5f*(n+1));
  return f;
}

// ---------------- chunked scan phase 1 ----------------
__global__ void k_scan1(const float* __restrict__ Alog0, const float* __restrict__ Alog1){
  __shared__ float sB[CHUNK][NN];
  int blk = blockIdx.x;               // 2 * NSEQ*NCH = 512
  int bc_ = blk >> 1;                 // 0..255
  int seq = bc_ >> 6, c = bc_ & 63;
  int half = seq >> 1;
  const float* Alog = half ? Alog1 : Alog0;
  int d = (blk & 1)*256 + threadIdx.x;
  int m0 = seq*Ss + c*CHUNK;
  { int i0 = threadIdx.x, i1 = threadIdx.x + 256;
    sB[i0>>4][i0&15] = g_proj[(size_t)(m0+(i0>>4))*64 + 32 + (i0&15)];
    sB[i1>>4][i1&15] = g_proj[(size_t)(m0+(i1>>4))*64 + 32 + (i1&15)]; }
  float A[NN];
  #pragma unroll
  for (int n=0;n<NN;n++) A[n] = -__expf(Alog[d*NN + n]);
  bool fast = a_fast(A);
  __syncthreads();
  float h[NN];
  #pragma unroll
  for (int n=0;n<NN;n++) h[n] = 0.f;
  float sd = 0.f;
  float dlt = __half2float(g_delta[(size_t)m0*DIi + d]);
  float xcv = __half2float(g_xc[(size_t)m0*DIi + d]);
  #pragma unroll 2
  for (int s=0;s<CHUNK;s++){
    float dltn = 0.f, xcn = 0.f;
    if (s+1 < CHUNK){
      size_t mn = (size_t)(m0+s+1)*DIi + d;
      dltn = __half2float(g_delta[mn]);
      xcn  = __half2float(g_xc[mn]);
    }
    float dx = dlt * xcv;
    sd += dlt;
    float dAv[NN];
    dA_compute(dAv, A, dlt, fast);
    float4 b0 = *(const float4*)&sB[s][0];
    float4 b1 = *(const float4*)&sB[s][4];
    float4 b2 = *(const float4*)&sB[s][8];
    float4 b3 = *(const float4*)&sB[s][12];
    h[0]  = dAv[0] *h[0]  + dx*b0.x;  h[1]  = dAv[1] *h[1]  + dx*b0.y;
    h[2]  = dAv[2] *h[2]  + dx*b0.z;  h[3]  = dAv[3] *h[3]  + dx*b0.w;
    h[4]  = dAv[4] *h[4]  + dx*b1.x;  h[5]  = dAv[5] *h[5]  + dx*b1.y;
    h[6]  = dAv[6] *h[6]  + dx*b1.z;  h[7]  = dAv[7] *h[7]  + dx*b1.w;
    h[8]  = dAv[8] *h[8]  + dx*b2.x;  h[9]  = dAv[9] *h[9]  + dx*b2.y;
    h[10] = dAv[10]*h[10] + dx*b2.z;  h[11] = dAv[11]*h[11] + dx*b2.w;
    h[12] = dAv[12]*h[12] + dx*b3.x;  h[13] = dAv[13]*h[13] + dx*b3.y;
    h[14] = dAv[14]*h[14] + dx*b3.z;  h[15] = dAv[15]*h[15] + dx*b3.w;
    dlt = dltn; xcv = xcn;
  }
  size_t base = ((size_t)bc_*DIi + d)*NN;
  float Pv[NN];
  dA_compute(Pv, A, sd, fast);
  #pragma unroll
  for (int n=0;n<NN;n++){ g_Q[base+n]=h[n]; g_P[base+n]=Pv[n]; }
}

// ---------------- phase 2: combine across chunks ----------------
__global__ void k_comb(){
  int i = blockIdx.x*128 + threadIdx.x;     // NSEQ*DIi*NN = 32768
  int n = i & 15, d = (i >> 4) & (DIi-1), seq = i >> 13;
  float H = 0.f;
  size_t stride = (size_t)DIi*NN;
  size_t idx = ((size_t)(seq*NCH))*stride + (size_t)d*NN + n;
  #pragma unroll 2
  for (int c=0;c<NCH;c++){
    float p = g_P[idx], q = g_Q[idx];
    g_Hin[idx] = H;
    H = p*H + q;
    idx += stride;
  }
}

// ---------------- phase 3: replay + gated output ----------------
__global__ void k_scan2(const float* __restrict__ Alog0, const float* __restrict__ Alog1,
                        const float* __restrict__ Dp0, const float* __restrict__ Dp1){
  __shared__ float sB[CHUNK][NN];
  __shared__ float sC[CHUNK][NN];
  int blk = blockIdx.x;
  int bc_ = blk >> 1;
  int seq = bc_ >> 6, c = bc_ & 63;
  int half = seq >> 1;
  const float* Alog = half ? Alog1 : Alog0;
  const float* Dp   = half ? Dp1   : Dp0;
  int d = (blk & 1)*256 + threadIdx.x;
  int m0 = seq*Ss + c*CHUNK;
  { int i0 = threadIdx.x, i1 = threadIdx.x + 256;
    sB[i0>>4][i0&15] = g_proj[(size_t)(m0+(i0>>4))*64 + 32 + (i0&15)];
    sB[i1>>4][i1&15] = g_proj[(size_t)(m0+(i1>>4))*64 + 32 + (i1&15)];
    sC[i0>>4][i0&15] = g_proj[(size_t)(m0+(i0>>4))*64 + 48 + (i0&15)];
    sC[i1>>4][i1&15] = g_proj[(size_t)(m0+(i1>>4))*64 + 48 + (i1&15)]; }
  float A[NN];
  #pragma unroll
  for (int n=0;n<NN;n++) A[n] = -__expf(Alog[d*NN + n]);
  bool fast = a_fast(A);
  float h[NN];
  size_t base = ((size_t)bc_*DIi + d)*NN;
  #pragma unroll
  for (int n=0;n<NN;n++) h[n] = g_Hin[base+n];
  float Dv = Dp[d];
  __syncthreads();
  float dlt = __half2float(g_delta[(size_t)m0*DIi + d]);
  float xcv = __half2float(g_xc[(size_t)m0*DIi + d]);
  float zv  = __half2float(g_z[(size_t)m0*DIi + d]);
  #pragma unroll 2
  for (int s=0;s<CHUNK;s++){
    float dltn = 0.f, xcn = 0.f, zn = 0.f;
    if (s+1 < CHUNK){
      size_t mn = (size_t)(m0+s+1)*DIi + d;
      dltn = __half2float(g_delta[mn]);
      xcn  = __half2float(g_xc[mn]);
      zn   = __half2float(g_z[mn]);
    }
    float dx = dlt * xcv;
    float dAv[NN];
    dA_compute(dAv, A, dlt, fast);
    float4 b0 = *(const float4*)&sB[s][0];
    float4 b1 = *(const float4*)&sB[s][4];
    float4 b2 = *(const float4*)&sB[s][8];
    float4 b3 = *(const float4*)&sB[s][12];
    float4 c0 = *(const float4*)&sC[s][0];
    float4 c1 = *(const float4*)&sC[s][4];
    float4 c2 = *(const float4*)&sC[s][8];
    float4 c3 = *(const float4*)&sC[s][12];
    float y0, y1, y2, y3;
    h[0]  = dAv[0] *h[0]  + dx*b0.x;  y0  = h[0] *c0.x;
    h[1]  = dAv[1] *h[1]  + dx*b0.y;  y1  = h[1] *c0.y;
    h[2]  = dAv[2] *h[2]  + dx*b0.z;  y2  = h[2] *c0.z;
    h[3]  = dAv[3] *h[3]  + dx*b0.w;  y3  = h[3] *c0.w;
    h[4]  = dAv[4] *h[4]  + dx*b1.x;  y0 += h[4] *c1.x;
    h[5]  = dAv[5] *h[5]  + dx*b1.y;  y1 += h[5] *c1.y;
    h[6]  = dAv[6] *h[6]  + dx*b1.z;  y2 += h[6] *c1.z;
    h[7]  = dAv[7] *h[7]  + dx*b1.w;  y3 += h[7] *c1.w;
    h[8]  = dAv[8] *h[8]  + dx*b2.x;  y0 += h[8] *c2.x;
    h[9]  = dAv[9] *h[9]  + dx*b2.y;  y1 += h[9] *c2.y;
    h[10] = dAv[10]*h[10] + dx*b2.z;  y2 += h[10]*c2.z;
    h[11] = dAv[11]*h[11] + dx*b2.w;  y3 += h[11]*c2.w;
    h[12] = dAv[12]*h[12] + dx*b3.x;  y0 += h[12]*c3.x;
    h[13] = dAv[13]*h[13] + dx*b3.y;  y1 += h[13]*c3.y;
    h[14] = dAv[14]*h[14] + dx*b3.z;  y2 += h[14]*c3.z;
    h[15] = dAv[15]*h[15] + dx*b3.w;  y3 += h[15]*c3.w;
    float y = (y0 + y1) + (y2 + y3) + Dv*xcv;
    g_yg[(size_t)(m0+s)*DIi + d] = __float2half(y * siluf(zv));
    dlt = dltn; xcv = xcn; zv = zn;
  }
}

// ---------------- driver ----------------
extern "C" void kernel_launch(void* const* d_in, const int* in_sizes, int n_in,
                              void* d_out, int out_size){
  const float* x      = (const float*)d_in[0];
  const float* in_w   = (const float*)d_in[1];
  const float* conv_w = (const float*)d_in[2];
  const float* conv_b = (const float*)d_in[3];
  const float* A_log  = (const float*)d_in[4];
  const float* xd_w   = (const float*)d_in[5];
  const float* xB_w   = (const float*)d_in[6];
  const float* xC_w   = (const float*)d_in[7];
  const float* dtp_w  = (const float*)d_in[8];
  const float* dtp_b  = (const float*)d_in[9];
  const float* Dp     = (const float*)d_in[10];
  const float* out_w  = (const float*)d_in[11];
  const float* ln_g   = (const float*)d_in[12];
  const float* ln_b   = (const float*)d_in[13];
  const float* merge_w= (const float*)d_in[14];
  float* out = (float*)d_out;

  k_prep<<<3104, 256>>>(x, in_w, xd_w, xB_w, xC_w, dtp_w, out_w, merge_w);
  for (int bi=0; bi<2; bi++){
    int b0 = bi, b1 = 2 + bi;
    k_ln      <<<M2/8, 256>>>(ln_g + b0*DMm, ln_b + b0*DMm,
                              ln_g + b1*DMm, ln_b + b1*DMm);
    k_gemm_in <<<dim3(8,64), 256>>>(b0, b1);
    k_conv    <<<(M2/8)*128/256, 256>>>(conv_w + b0*DIi*4, conv_b + b0*DIi,
                                        conv_w + b1*DIi*4, conv_b + b1*DIi);
    k_gemm_x  <<<dim3(KS,64), 256>>>(b0, b1);
    k_xred    <<<M2*16/256, 256>>>();
    k_gemm_dt <<<dim3(4,64), 256>>>(b0, b1, dtp_b + b0*DIi, dtp_b + b1*DIi);
    k_scan1   <<<2*NSEQ*NCH, 256>>>(A_log + b0*DIi*NN, A_log + b1*DIi*NN);
    k_comb    <<<256, 128>>>();
    k_scan2   <<<2*NSEQ*NCH, 256>>>(A_log + b0*DIi*NN, A_log + b1*DIi*NN,
                                    Dp + b0*DIi, Dp + b1*DIi);
    k_gemm_out<<<dim3(2,64), 256>>>(b0, b1);
  }
  k_merge<<<dim3(4,32), 256>>>(out);
}